// round 1
// baseline (speedup 1.0000x reference)
#include <cuda_runtime.h>

// ---------------- problem constants ----------------
#define CIN   256
#define TT    64
#define HIN   32
#define WIN   32
#define C1    512
#define H1    16
#define W1    16
#define C2    512
#define AA    8
#define NANCH 512     // A * tlen = 8 * 64

// ---------------- scratch (static device globals; no cudaMalloc allowed) ---
__device__ float g_x1[(size_t)C1 * TT * H1 * W1];   // conv1 output, 33.5 MB
__device__ float g_feat[C2 * TT];                   // pooled features

// ---------------- f32x2 packed helpers (sm_103a FFMA2 path) ----------------
__device__ __forceinline__ unsigned long long pk2(float lo, float hi) {
    unsigned long long r;
    asm("mov.b64 %0, {%1, %2};" : "=l"(r) : "f"(lo), "f"(hi));
    return r;
}
__device__ __forceinline__ void upk2(unsigned long long v, float& lo, float& hi) {
    asm("mov.b64 {%0, %1}, %2;" : "=f"(lo), "=f"(hi) : "l"(v));
}
__device__ __forceinline__ unsigned long long ffma2(unsigned long long a,
                                                    unsigned long long b,
                                                    unsigned long long c) {
    unsigned long long d;
    asm("fma.rn.f32x2 %0, %1, %2, %3;" : "=l"(d) : "l"(a), "l"(b), "l"(c));
    return d;
}

// ============================================================================
// Conv1: in (256,64,32,32) * w (512,256,3,3,3), stride (1,2,2), pad 1
//        -> g_x1 (512,64,16,16)
// Grid: (64 t, 8 oc-tiles of 64). Block 256 threads.
// Thread tile: 8 oc x 8 positions (one half-row), f32x2 over position pairs.
// ============================================================================
__global__ void __launch_bounds__(256, 2)
conv1_kernel(const float* __restrict__ in, const float* __restrict__ w,
             const float* __restrict__ b) {
    __shared__ __align__(16) float in_s[3 * 33 * 33];   // halo: rows/cols -1..31
    __shared__ __align__(16) float w_s[64 * 27];

    const int t   = blockIdx.x;
    const int oc0 = blockIdx.y * 64;
    const int tid = threadIdx.x;
    const int p   = tid & 31;           // 32 position groups
    const int ocg = tid >> 5;           // 8 oc groups of 8
    const int h   = p >> 1;             // output row 0..15
    const int wb  = (p & 1) * 8;        // output col base 0 or 8

    unsigned long long acc[8][4];
#pragma unroll
    for (int i = 0; i < 8; i++)
#pragma unroll
        for (int jp = 0; jp < 4; jp++) acc[i][jp] = 0ull;

    for (int ic = 0; ic < CIN; ic++) {
        // stage input halo (3 time slices, 33x33 with top/left zero pad)
        for (int idx = tid; idx < 3 * 33 * 33; idx += 256) {
            int kd = idx / 1089;
            int r  = idx - kd * 1089;
            int hh = r / 33;
            int ww = r - hh * 33;
            int ti = t + kd - 1;
            float v = 0.f;
            if (ti >= 0 && ti < TT && hh >= 1 && ww >= 1)
                v = in[((size_t)(ic * TT + ti) * HIN + (hh - 1)) * WIN + (ww - 1)];
            in_s[idx] = v;
        }
        // stage weights for this ic: 64 oc x 27 taps
        for (int idx = tid; idx < 64 * 27; idx += 256) {
            int oci = idx / 27;
            int tap = idx - oci * 27;
            w_s[idx] = w[((size_t)(oc0 + oci) * CIN + ic) * 27 + tap];
        }
        __syncthreads();

#pragma unroll
        for (int kd = 0; kd < 3; kd++) {
#pragma unroll
            for (int kh = 0; kh < 3; kh++) {
                const float* rp = &in_s[kd * 1089 + (2 * h + kh) * 33];
#pragma unroll
                for (int kw = 0; kw < 3; kw++) {
                    float v[8];
#pragma unroll
                    for (int j = 0; j < 8; j++) v[j] = rp[2 * (wb + j) + kw];
                    unsigned long long vp[4];
#pragma unroll
                    for (int jp = 0; jp < 4; jp++) vp[jp] = pk2(v[2 * jp], v[2 * jp + 1]);
                    const int tap = kd * 9 + kh * 3 + kw;
#pragma unroll
                    for (int i = 0; i < 8; i++) {
                        float wv = w_s[(ocg * 8 + i) * 27 + tap];
                        unsigned long long wp = pk2(wv, wv);
#pragma unroll
                        for (int jp = 0; jp < 4; jp++)
                            acc[i][jp] = ffma2(vp[jp], wp, acc[i][jp]);
                    }
                }
            }
        }
        __syncthreads();
    }

#pragma unroll
    for (int i = 0; i < 8; i++) {
        int oc = oc0 + ocg * 8 + i;
        float bias = b[oc];
        float o0, o1, o2, o3, o4, o5, o6, o7;
        upk2(acc[i][0], o0, o1);
        upk2(acc[i][1], o2, o3);
        upk2(acc[i][2], o4, o5);
        upk2(acc[i][3], o6, o7);
        float4 f0 = make_float4(o0 + bias, o1 + bias, o2 + bias, o3 + bias);
        float4 f1 = make_float4(o4 + bias, o5 + bias, o6 + bias, o7 + bias);
        float* op = &g_x1[((size_t)(oc * TT + t) * H1 + h) * W1 + wb];
        *(float4*)(op)     = f0;
        *(float4*)(op + 4) = f1;
    }
}

// ============================================================================
// Conv2 + max-pool(8x8): g_x1 (512,64,16,16) * w (512,512,3,3,3),
// stride (1,2,2), pad 1 -> feat (512,64)
// Grid: (64 t, 8 oc-tiles of 64). Block 256 threads = 64 pos x 4 oc-groups.
// Thread tile: 16 oc (f32x2 over oc pairs) x 1 position.
// ============================================================================
#define W2STR 66   // padded tap-major weight stride (even -> 8B aligned pairs)

__global__ void __launch_bounds__(256, 2)
conv2_kernel(const float* __restrict__ w, const float* __restrict__ b) {
    __shared__ __align__(16) float in_s[3 * 17 * 17];
    __shared__ __align__(16) float w_s[27 * W2STR];
    __shared__ float red[64 * 65];

    const int t   = blockIdx.x;
    const int oc0 = blockIdx.y * 64;
    const int tid = threadIdx.x;
    const int pos = tid & 63;
    const int ocg = tid >> 6;           // 0..3, 16 oc each
    const int h   = pos >> 3;
    const int wq  = pos & 7;

    unsigned long long acc[8];
#pragma unroll
    for (int k = 0; k < 8; k++) acc[k] = 0ull;

    for (int ic = 0; ic < C1; ic++) {
        for (int idx = tid; idx < 3 * 17 * 17; idx += 256) {
            int kd = idx / 289;
            int r  = idx - kd * 289;
            int hh = r / 17;
            int ww = r - hh * 17;
            int ti = t + kd - 1;
            float v = 0.f;
            if (ti >= 0 && ti < TT && hh >= 1 && ww >= 1)
                v = g_x1[((size_t)(ic * TT + ti) * H1 + (hh - 1)) * W1 + (ww - 1)];
            in_s[idx] = v;
        }
        for (int idx = tid; idx < 64 * 27; idx += 256) {
            int oci = idx / 27;
            int tap = idx - oci * 27;
            w_s[tap * W2STR + oci] = w[((size_t)(oc0 + oci) * C1 + ic) * 27 + tap];
        }
        __syncthreads();

#pragma unroll
        for (int kd = 0; kd < 3; kd++) {
#pragma unroll
            for (int kh = 0; kh < 3; kh++) {
                const float* rp = &in_s[kd * 289 + (2 * h + kh) * 17];
#pragma unroll
                for (int kw = 0; kw < 3; kw++) {
                    float v = rp[2 * wq + kw];
                    unsigned long long vp = pk2(v, v);
                    const unsigned long long* wpp = (const unsigned long long*)
                        &w_s[(kd * 9 + kh * 3 + kw) * W2STR + ocg * 16];
#pragma unroll
                    for (int k = 0; k < 8; k++)
                        acc[k] = ffma2(vp, wpp[k], acc[k]);
                }
            }
        }
        __syncthreads();
    }

    // spill per-thread results, reduce max over 64 spatial positions
#pragma unroll
    for (int k = 0; k < 8; k++) {
        float a0, a1;
        upk2(acc[k], a0, a1);
        red[pos * 65 + ocg * 16 + 2 * k]     = a0;
        red[pos * 65 + ocg * 16 + 2 * k + 1] = a1;
    }
    __syncthreads();
    if (tid < 64) {
        float m = -3.4e38f;
        for (int p2 = 0; p2 < 64; p2++) m = fmaxf(m, red[p2 * 65 + tid]);
        g_feat[(oc0 + tid) * TT + t] = m + b[oc0 + tid];
    }
}

// ============================================================================
// Head: logits GEMM, softmax, box decode, NMS(100), labels, losses.
// Single block, 512 threads (one per anchor).
// out layout: [0..199] prop_coord, [200..299] prop_score, [300] cls, [301] reg
// ============================================================================
__device__ __forceinline__ float iou1d(float s1, float e1, float s2, float e2) {
    float inter = fmaxf(fminf(e1, e2) - fmaxf(s1, s2), 0.f);
    float uni   = (e1 - s1) + (e2 - s2) - inter;
    return inter / fmaxf(uni, 1e-6f);
}

__global__ void __launch_bounds__(512, 1)
head_kernel(const float* __restrict__ sw, const float* __restrict__ sb,
            const float* __restrict__ dw, const float* __restrict__ db,
            const float* __restrict__ gt, const int* __restrict__ vlen,
            float* __restrict__ out) {
    __shared__ float s_sl[16 * 64], s_dl[16 * 64];
    __shared__ float s_bs[NANCH], s_be[NANCH], s_sc[NANCH];
    __shared__ float s_as[NANCH], s_ae[NANCH];
    __shared__ float s_lp0[NANCH], s_lp1[NANCH], s_dc[NANCH], s_dt[NANCH];
    __shared__ float s_gt[16];
    __shared__ int   s_best[8];
    __shared__ float r0[512], r1[512], r2[512], r3[512];

    const int tid  = threadIdx.x;
    const int wid  = tid >> 5;
    const int lane = tid & 31;
    if (tid < 16) s_gt[tid] = gt[tid];

    // ---- phase A: logits (16x64 each for score & delta) -------------------
    const int o = tid >> 6;          // 0..7
    const int t = tid & 63;
    {
        float a0 = sb[o], a1 = sb[o + 8], d0 = db[o], d1 = db[o + 8];
        for (int c = 0; c < C2; c++) {
            float f = g_feat[c * 64 + t];
            a0 = fmaf(sw[o * 512 + c],       f, a0);
            a1 = fmaf(sw[(o + 8) * 512 + c], f, a1);
            d0 = fmaf(dw[o * 512 + c],       f, d0);
            d1 = fmaf(dw[(o + 8) * 512 + c], f, d1);
        }
        s_sl[o * 64 + t] = a0;  s_sl[(o + 8) * 64 + t] = a1;
        s_dl[o * 64 + t] = d0;  s_dl[(o + 8) * 64 + t] = d1;
    }
    __syncthreads();

    // ---- phase B: per-anchor decode (n = tid = a*64 + t) -------------------
    {
        const int a = o;  // anchor scale index
        float l0 = s_sl[a * 64 + t], l1 = s_sl[(a + 8) * 64 + t];
        float mx = fmaxf(l0, l1);
        float lse = mx + logf(expf(l0 - mx) + expf(l1 - mx));
        float p1  = expf(l1 - lse);
        float dc  = s_dl[a * 64 + t], dl = s_dl[(a + 8) * 64 + t];
        float alen = (float)(8 << a);
        float ctr  = (t + 0.5f) * 8.f;
        float pc = ctr + dc * alen;
        float pl = alen * expf(fminf(fmaxf(dl, -10.f), 10.f));
        float ps = fminf(fmaxf(pc - 0.5f * pl, 0.f), 512.f);
        float pe = fminf(fmaxf(pc + 0.5f * pl, 0.f), 512.f);
        s_bs[tid] = ps;  s_be[tid] = pe;
        s_sc[tid] = (pe - ps >= 4.f) ? p1 : -1.0e9f;
        s_as[tid] = ctr - 0.5f * alen;
        s_ae[tid] = ctr + 0.5f * alen;
        s_lp0[tid] = l0 - lse;  s_lp1[tid] = l1 - lse;
        s_dc[tid] = dc;  s_dt[tid] = dl;
    }
    __syncthreads();

    // ---- phase C: best anchor per gt (first-max argmax over 512) ----------
    if (wid < 8) {
        float gs = s_gt[wid * 2], ge = s_gt[wid * 2 + 1];
        float bv = -3.4e38f; int bi = 0x7fffffff;
        for (int k = 0; k < 16; k++) {
            int n = lane + 32 * k;
            float v = iou1d(s_as[n], s_ae[n], gs, ge);
            if (v > bv) { bv = v; bi = n; }
        }
        for (int off = 16; off; off >>= 1) {
            float ov = __shfl_xor_sync(0xffffffffu, bv, off);
            int   oi = __shfl_xor_sync(0xffffffffu, bi, off);
            if (ov > bv || (ov == bv && oi < bi)) { bv = ov; bi = oi; }
        }
        if (lane == 0) s_best[wid] = bi;
    }
    __syncthreads();

    // ---- phase D: labels + losses ------------------------------------------
    {
        float myas = s_as[tid], myae = s_ae[tid];
        float miou = -1.f; int ag = 0;
#pragma unroll
        for (int g = 0; g < 8; g++) {
            float v = iou1d(myas, myae, s_gt[2 * g], s_gt[2 * g + 1]);
            if (v > miou) { miou = v; ag = g; }
        }
        int lab = (miou < 0.3f) ? 0 : -1;
        if (miou >= 0.7f) lab = 1;
#pragma unroll
        for (int g = 0; g < 8; g++)
            if (s_best[g] == tid) lab = 1;
        float vl = (float)vlen[0];
        if (!(myas >= 0.f && myae <= vl)) lab = -1;

        float gs = s_gt[2 * ag], ge = s_gt[2 * ag + 1];
        float gc = 0.5f * (gs + ge);
        float gl = fmaxf(ge - gs, 1e-6f);
        float ac = 0.5f * (myas + myae);
        float al = myae - myas;
        float rl0 = (gc - ac) / al;
        float rl1 = logf(gl / al);
        float d0 = s_dc[tid] - rl0, d1 = s_dt[tid] - rl1;
        float sl1 = (fabsf(d0) < 1.f ? 0.5f * d0 * d0 : fabsf(d0) - 0.5f)
                  + (fabsf(d1) < 1.f ? 0.5f * d1 * d1 : fabsf(d1) - 0.5f);
        float maskv = (lab >= 0) ? 1.f : 0.f;
        float posv  = (lab == 1) ? 1.f : 0.f;
        float nll   = -((lab == 1) ? s_lp1[tid] : s_lp0[tid]);
        r0[tid] = nll * maskv;  r1[tid] = maskv;
        r2[tid] = sl1 * posv;   r3[tid] = posv;
    }
    __syncthreads();
    for (int s = 256; s > 0; s >>= 1) {
        if (tid < s) {
            r0[tid] += r0[tid + s];  r1[tid] += r1[tid + s];
            r2[tid] += r2[tid + s];  r3[tid] += r3[tid + s];
        }
        __syncthreads();
    }
    if (tid == 0) {
        out[300] = r0[0] / fmaxf(r1[0], 1.f);
        out[301] = r2[0] / fmaxf(r3[0], 1.f);
    }
    __syncthreads();

    // ---- phase E: NMS (warp 0 only; no block barriers afterwards) ---------
    if (wid == 0) {
        for (int it = 0; it < 100; it++) {
            float bv = -3.4e38f; int bi = 0x7fffffff;
#pragma unroll
            for (int k = 0; k < 16; k++) {
                int n = lane + 32 * k;
                float v = s_sc[n];
                if (v > bv) { bv = v; bi = n; }
            }
            for (int off = 16; off; off >>= 1) {
                float ov = __shfl_xor_sync(0xffffffffu, bv, off);
                int   oi = __shfl_xor_sync(0xffffffffu, bi, off);
                if (ov > bv || (ov == bv && oi < bi)) { bv = ov; bi = oi; }
            }
            float kb0 = s_bs[bi], kb1 = s_be[bi];
            bool keep = bv > -5.0e8f;
            if (lane == 0) {
                out[2 * it]     = keep ? kb0 : 0.f;
                out[2 * it + 1] = keep ? kb1 : 0.f;
                out[200 + it]   = keep ? bv  : 0.f;
            }
#pragma unroll
            for (int k = 0; k < 16; k++) {
                int n = lane + 32 * k;
                float v = iou1d(kb0, kb1, s_bs[n], s_be[n]);
                if (v > 0.7f || n == bi) s_sc[n] = -1.0e9f;
            }
            __syncwarp();
        }
    }
}

// ============================================================================
extern "C" void kernel_launch(void* const* d_in, const int* in_sizes, int n_in,
                              void* d_out, int out_size) {
    const float* base = (const float*)d_in[0];
    const float* gt   = (const float*)d_in[1];
    const int*   vl   = (const int*)d_in[2];
    const float* c1w  = (const float*)d_in[3];
    const float* c1b  = (const float*)d_in[4];
    const float* c2w  = (const float*)d_in[5];
    const float* c2b  = (const float*)d_in[6];
    const float* sw   = (const float*)d_in[7];
    const float* sb   = (const float*)d_in[8];
    const float* dw   = (const float*)d_in[9];
    const float* db   = (const float*)d_in[10];
    float* out = (float*)d_out;

    dim3 g(64, 8);
    conv1_kernel<<<g, 256>>>(base, c1w, c1b);
    conv2_kernel<<<g, 256>>>(c2w, c2b);
    head_kernel<<<1, 512>>>(sw, sb, dw, db, gt, vl, out);
}

// round 2
// speedup vs baseline: 1.4269x; 1.4269x over previous
#include <cuda_runtime.h>

typedef unsigned long long ull;

// ---------------- problem constants ----------------
#define CIN   256
#define TT    64
#define HIN   32
#define WIN   32
#define C1    512
#define H1    16
#define W1    16
#define C2    512
#define NANCH 512

// ---------------- scratch ----------------
__device__ float g_x1[(size_t)C1 * TT * H1 * W1];
__device__ float g_feat[C2 * TT];

// ---------------- f32x2 helpers ----------------
__device__ __forceinline__ ull ffma2(ull a, ull b, ull c) {
    ull d;
    asm("fma.rn.f32x2 %0, %1, %2, %3;" : "=l"(d) : "l"(a), "l"(b), "l"(c));
    return d;
}
__device__ __forceinline__ void upk2(ull v, float& lo, float& hi) {
    asm("mov.b64 {%0, %1}, %2;" : "=f"(lo), "=f"(hi) : "l"(v));
}

// ============================================================================
// Conv1: in (256,64,32,32) * w (512,256,3x3x3), stride (1,2,2), pad 1
//        -> g_x1 (512,64,16,16)
// Grid (64 t, 8 oc-tiles of 64). Block 256.
// Thread: 8 oc (4 f32x2 pairs) x 8 cols of one output row.
// Inputs stored DUPLICATED in smem (LDS.64 splat, zero MOVs).
// Weights tap-major oc-contiguous (LDS.64 natural pairs).
// Row stride 66 floats: h-lane stride 528B = 16 mod 128 -> conflict-free.
// ============================================================================
#define ROW1   66
#define SLICE1 (33 * ROW1)

__global__ void __launch_bounds__(256, 2)
conv1_kernel(const float* __restrict__ in, const float* __restrict__ w,
             const float* __restrict__ b) {
    __shared__ __align__(16) float in_s[3 * SLICE1];   // 26.1 KB
    __shared__ __align__(16) float w_s[27 * 64];       //  6.9 KB

    const int t    = blockIdx.x;
    const int oc0  = blockIdx.y * 64;
    const int tid  = threadIdx.x;
    const int warp = tid >> 5;
    const int lane = tid & 31;
    // warp bits: {ocg_hi, h_hi, half}; lane bits: {ocg_lo[1:0], h_lo[2:0]}
    const int ocg  = ((warp >> 2) << 2) | (lane >> 3);   // 0..7 (8 oc each)
    const int h    = (((warp >> 1) & 1) << 3) | (lane & 7);
    const int wb   = (warp & 1) * 8;

    ull acc[4][8];
#pragma unroll
    for (int k = 0; k < 4; k++)
#pragma unroll
        for (int j = 0; j < 8; j++) acc[k][j] = 0ull;

    for (int ic = 0; ic < CIN; ic++) {
        // stage input halo, duplicated
        const float* inb = in + (size_t)ic * (TT * HIN * WIN);
        for (int idx = tid; idx < 3 * 33 * 33; idx += 256) {
            int kd = idx / 1089;
            int r  = idx - kd * 1089;
            int hh = r / 33;
            int ww = r - hh * 33;
            int ti = t + kd - 1;
            float v = 0.f;
            if (ti >= 0 && ti < TT && hh >= 1 && ww >= 1)
                v = inb[((size_t)ti * HIN + (hh - 1)) * WIN + (ww - 1)];
            *(float2*)&in_s[(kd * 33 + hh) * ROW1 + 2 * ww] = make_float2(v, v);
        }
        // stage weights tap-major
        for (int idx = tid; idx < 64 * 27; idx += 256) {
            int oci = idx / 27;
            int tap = idx - oci * 27;
            w_s[tap * 64 + oci] = w[((size_t)(oc0 + oci) * CIN + ic) * 27 + tap];
        }
        __syncthreads();

#pragma unroll
        for (int kd = 0; kd < 3; kd++) {
#pragma unroll
            for (int kh = 0; kh < 3; kh++) {
                const ull* up = (const ull*)&in_s[(kd * 33 + 2 * h + kh) * ROW1]
                                + 2 * wb;
                const int tap0 = kd * 9 + kh * 3;
                ull e[9];
#pragma unroll
                for (int j = 0; j < 9; j++) e[j] = up[2 * j];
                {   // kw = 0
                    const ull* wp = (const ull*)&w_s[tap0 * 64 + ocg * 8];
                    ull wv[4];
#pragma unroll
                    for (int k = 0; k < 4; k++) wv[k] = wp[k];
#pragma unroll
                    for (int k = 0; k < 4; k++)
#pragma unroll
                        for (int j = 0; j < 8; j++)
                            acc[k][j] = ffma2(e[j], wv[k], acc[k][j]);
                }
                {   // kw = 2 (reuses e, shifted)
                    const ull* wp = (const ull*)&w_s[(tap0 + 2) * 64 + ocg * 8];
                    ull wv[4];
#pragma unroll
                    for (int k = 0; k < 4; k++) wv[k] = wp[k];
#pragma unroll
                    for (int k = 0; k < 4; k++)
#pragma unroll
                        for (int j = 0; j < 8; j++)
                            acc[k][j] = ffma2(e[j + 1], wv[k], acc[k][j]);
                }
                {   // kw = 1 (odd columns)
                    ull o[8];
#pragma unroll
                    for (int j = 0; j < 8; j++) o[j] = up[2 * j + 1];
                    const ull* wp = (const ull*)&w_s[(tap0 + 1) * 64 + ocg * 8];
                    ull wv[4];
#pragma unroll
                    for (int k = 0; k < 4; k++) wv[k] = wp[k];
#pragma unroll
                    for (int k = 0; k < 4; k++)
#pragma unroll
                        for (int j = 0; j < 8; j++)
                            acc[k][j] = ffma2(o[j], wv[k], acc[k][j]);
                }
            }
        }
        __syncthreads();
    }

    // epilogue: unpack, add bias, store 8 oc x 8 cols
#pragma unroll
    for (int k = 0; k < 4; k++) {
        float lo[8], hi[8];
#pragma unroll
        for (int j = 0; j < 8; j++) upk2(acc[k][j], lo[j], hi[j]);
        int oca = oc0 + ocg * 8 + 2 * k;
        float ba = b[oca], bb = b[oca + 1];
        float* pa = &g_x1[((size_t)(oca * TT + t) * H1 + h) * W1 + wb];
        float* pb = &g_x1[((size_t)((oca + 1) * TT + t) * H1 + h) * W1 + wb];
        *(float4*)pa       = make_float4(lo[0] + ba, lo[1] + ba, lo[2] + ba, lo[3] + ba);
        *(float4*)(pa + 4) = make_float4(lo[4] + ba, lo[5] + ba, lo[6] + ba, lo[7] + ba);
        *(float4*)pb       = make_float4(hi[0] + bb, hi[1] + bb, hi[2] + bb, hi[3] + bb);
        *(float4*)(pb + 4) = make_float4(hi[4] + bb, hi[5] + bb, hi[6] + bb, hi[7] + bb);
    }
}

// ============================================================================
// Conv2 + maxpool: g_x1 (512,64,16,16) * w (512,512,3x3x3), stride (1,2,2)
//                  -> feat (512,64)
// Grid (64 t, 4 oc-tiles of 128). Block 256.
// Thread: 8 oc (4 pairs) x 4 cols of one output row.
// warp bits {ocg_hi[1:0], wq}; lane bits {ocg_lo[1:0], h[2:0]}.
// Row stride 34 floats: h-lane stride 272B = 16 mod 128 -> conflict-free.
// ============================================================================
#define ROW2   34
#define SLICE2 (17 * ROW2)

__global__ void __launch_bounds__(256, 2)
conv2_kernel(const float* __restrict__ w, const float* __restrict__ b) {
    __shared__ __align__(16) float in_s[3 * SLICE2];   //  6.9 KB
    __shared__ __align__(16) float w_s[27 * 128];      // 13.8 KB
    __shared__ float red[128 * 17];                    //  8.7 KB

    const int t    = blockIdx.x;
    const int oc0  = blockIdx.y * 128;
    const int tid  = threadIdx.x;
    const int warp = tid >> 5;
    const int lane = tid & 31;
    const int ocg  = ((warp >> 1) << 2) | (lane >> 3);  // 0..15 (8 oc each)
    const int wq   = warp & 1;
    const int h    = lane & 7;
    const int wbase = wq * 4;

    ull acc[4][4];
#pragma unroll
    for (int k = 0; k < 4; k++)
#pragma unroll
        for (int m = 0; m < 4; m++) acc[k][m] = 0ull;

    for (int ic = 0; ic < C1; ic++) {
        const float* inb = g_x1 + (size_t)ic * (TT * H1 * W1);
        for (int idx = tid; idx < 3 * 17 * 17; idx += 256) {
            int kd = idx / 289;
            int r  = idx - kd * 289;
            int hh = r / 17;
            int ww = r - hh * 17;
            int ti = t + kd - 1;
            float v = 0.f;
            if (ti >= 0 && ti < TT && hh >= 1 && ww >= 1)
                v = inb[((size_t)ti * H1 + (hh - 1)) * W1 + (ww - 1)];
            *(float2*)&in_s[(kd * 17 + hh) * ROW2 + 2 * ww] = make_float2(v, v);
        }
        for (int idx = tid; idx < 128 * 27; idx += 256) {
            int oci = idx / 27;
            int tap = idx - oci * 27;
            w_s[tap * 128 + oci] = w[((size_t)(oc0 + oci) * C1 + ic) * 27 + tap];
        }
        __syncthreads();

#pragma unroll
        for (int kd = 0; kd < 3; kd++) {
#pragma unroll
            for (int kh = 0; kh < 3; kh++) {
                const ull* up = (const ull*)&in_s[(kd * 17 + 2 * h + kh) * ROW2]
                                + 2 * wbase;
                const int tap0 = kd * 9 + kh * 3;
                ull e[5], o[4];
#pragma unroll
                for (int m = 0; m < 5; m++) e[m] = up[2 * m];
#pragma unroll
                for (int m = 0; m < 4; m++) o[m] = up[2 * m + 1];
                const ull* wp0 = (const ull*)&w_s[tap0 * 128 + ocg * 8];
                const ull* wp1 = (const ull*)&w_s[(tap0 + 1) * 128 + ocg * 8];
                const ull* wp2 = (const ull*)&w_s[(tap0 + 2) * 128 + ocg * 8];
#pragma unroll
                for (int k = 0; k < 4; k++) {
                    ull w0 = wp0[k], w1 = wp1[k], w2 = wp2[k];
#pragma unroll
                    for (int m = 0; m < 4; m++) {
                        acc[k][m] = ffma2(e[m],     w0, acc[k][m]);
                        acc[k][m] = ffma2(o[m],     w1, acc[k][m]);
                        acc[k][m] = ffma2(e[m + 1], w2, acc[k][m]);
                    }
                }
            }
        }
        __syncthreads();
    }

    // maxpool epilogue: reduce own 4 cols, spill, reduce across 16 pos-groups
    const int pg = wq * 8 + h;   // 0..15
#pragma unroll
    for (int k = 0; k < 4; k++) {
        float mlo = -3.4e38f, mhi = -3.4e38f;
#pragma unroll
        for (int m = 0; m < 4; m++) {
            float lo, hi;
            upk2(acc[k][m], lo, hi);
            mlo = fmaxf(mlo, lo);
            mhi = fmaxf(mhi, hi);
        }
        red[(ocg * 8 + 2 * k) * 17 + pg]     = mlo;
        red[(ocg * 8 + 2 * k + 1) * 17 + pg] = mhi;
    }
    __syncthreads();
    if (tid < 128) {
        float m = -3.4e38f;
#pragma unroll
        for (int p = 0; p < 16; p++) m = fmaxf(m, red[tid * 17 + p]);
        g_feat[(oc0 + tid) * TT + t] = m + b[oc0 + tid];
    }
}

// ============================================================================
// Head (unchanged from passing R1 kernel)
// ============================================================================
__device__ __forceinline__ float iou1d(float s1, float e1, float s2, float e2) {
    float inter = fmaxf(fminf(e1, e2) - fmaxf(s1, s2), 0.f);
    float uni   = (e1 - s1) + (e2 - s2) - inter;
    return inter / fmaxf(uni, 1e-6f);
}

__global__ void __launch_bounds__(512, 1)
head_kernel(const float* __restrict__ sw, const float* __restrict__ sb,
            const float* __restrict__ dw, const float* __restrict__ db,
            const float* __restrict__ gt, const int* __restrict__ vlen,
            float* __restrict__ out) {
    __shared__ float s_sl[16 * 64], s_dl[16 * 64];
    __shared__ float s_bs[NANCH], s_be[NANCH], s_sc[NANCH];
    __shared__ float s_as[NANCH], s_ae[NANCH];
    __shared__ float s_lp0[NANCH], s_lp1[NANCH], s_dc[NANCH], s_dt[NANCH];
    __shared__ float s_gt[16];
    __shared__ int   s_best[8];
    __shared__ float r0[512], r1[512], r2[512], r3[512];

    const int tid  = threadIdx.x;
    const int wid  = tid >> 5;
    const int lane = tid & 31;
    if (tid < 16) s_gt[tid] = gt[tid];

    const int o = tid >> 6;
    const int t = tid & 63;
    {
        float a0 = sb[o], a1 = sb[o + 8], d0 = db[o], d1 = db[o + 8];
        for (int c = 0; c < C2; c++) {
            float f = g_feat[c * 64 + t];
            a0 = fmaf(sw[o * 512 + c],       f, a0);
            a1 = fmaf(sw[(o + 8) * 512 + c], f, a1);
            d0 = fmaf(dw[o * 512 + c],       f, d0);
            d1 = fmaf(dw[(o + 8) * 512 + c], f, d1);
        }
        s_sl[o * 64 + t] = a0;  s_sl[(o + 8) * 64 + t] = a1;
        s_dl[o * 64 + t] = d0;  s_dl[(o + 8) * 64 + t] = d1;
    }
    __syncthreads();

    {
        const int a = o;
        float l0 = s_sl[a * 64 + t], l1 = s_sl[(a + 8) * 64 + t];
        float mx = fmaxf(l0, l1);
        float lse = mx + logf(expf(l0 - mx) + expf(l1 - mx));
        float p1  = expf(l1 - lse);
        float dc  = s_dl[a * 64 + t], dl = s_dl[(a + 8) * 64 + t];
        float alen = (float)(8 << a);
        float ctr  = (t + 0.5f) * 8.f;
        float pc = ctr + dc * alen;
        float pl = alen * expf(fminf(fmaxf(dl, -10.f), 10.f));
        float ps = fminf(fmaxf(pc - 0.5f * pl, 0.f), 512.f);
        float pe = fminf(fmaxf(pc + 0.5f * pl, 0.f), 512.f);
        s_bs[tid] = ps;  s_be[tid] = pe;
        s_sc[tid] = (pe - ps >= 4.f) ? p1 : -1.0e9f;
        s_as[tid] = ctr - 0.5f * alen;
        s_ae[tid] = ctr + 0.5f * alen;
        s_lp0[tid] = l0 - lse;  s_lp1[tid] = l1 - lse;
        s_dc[tid] = dc;  s_dt[tid] = dl;
    }
    __syncthreads();

    if (wid < 8) {
        float gs = s_gt[wid * 2], ge = s_gt[wid * 2 + 1];
        float bv = -3.4e38f; int bi = 0x7fffffff;
        for (int k = 0; k < 16; k++) {
            int n = lane + 32 * k;
            float v = iou1d(s_as[n], s_ae[n], gs, ge);
            if (v > bv) { bv = v; bi = n; }
        }
        for (int off = 16; off; off >>= 1) {
            float ov = __shfl_xor_sync(0xffffffffu, bv, off);
            int   oi = __shfl_xor_sync(0xffffffffu, bi, off);
            if (ov > bv || (ov == bv && oi < bi)) { bv = ov; bi = oi; }
        }
        if (lane == 0) s_best[wid] = bi;
    }
    __syncthreads();

    {
        float myas = s_as[tid], myae = s_ae[tid];
        float miou = -1.f; int ag = 0;
#pragma unroll
        for (int g = 0; g < 8; g++) {
            float v = iou1d(myas, myae, s_gt[2 * g], s_gt[2 * g + 1]);
            if (v > miou) { miou = v; ag = g; }
        }
        int lab = (miou < 0.3f) ? 0 : -1;
        if (miou >= 0.7f) lab = 1;
#pragma unroll
        for (int g = 0; g < 8; g++)
            if (s_best[g] == tid) lab = 1;
        float vl = (float)vlen[0];
        if (!(myas >= 0.f && myae <= vl)) lab = -1;

        float gs = s_gt[2 * ag], ge = s_gt[2 * ag + 1];
        float gc = 0.5f * (gs + ge);
        float gl = fmaxf(ge - gs, 1e-6f);
        float ac = 0.5f * (myas + myae);
        float al = myae - myas;
        float rl0 = (gc - ac) / al;
        float rl1 = logf(gl / al);
        float d0 = s_dc[tid] - rl0, d1 = s_dt[tid] - rl1;
        float sl1 = (fabsf(d0) < 1.f ? 0.5f * d0 * d0 : fabsf(d0) - 0.5f)
                  + (fabsf(d1) < 1.f ? 0.5f * d1 * d1 : fabsf(d1) - 0.5f);
        float maskv = (lab >= 0) ? 1.f : 0.f;
        float posv  = (lab == 1) ? 1.f : 0.f;
        float nll   = -((lab == 1) ? s_lp1[tid] : s_lp0[tid]);
        r0[tid] = nll * maskv;  r1[tid] = maskv;
        r2[tid] = sl1 * posv;   r3[tid] = posv;
    }
    __syncthreads();
    for (int s = 256; s > 0; s >>= 1) {
        if (tid < s) {
            r0[tid] += r0[tid + s];  r1[tid] += r1[tid + s];
            r2[tid] += r2[tid + s];  r3[tid] += r3[tid + s];
        }
        __syncthreads();
    }
    if (tid == 0) {
        out[300] = r0[0] / fmaxf(r1[0], 1.f);
        out[301] = r2[0] / fmaxf(r3[0], 1.f);
    }
    __syncthreads();

    if (wid == 0) {
        for (int it = 0; it < 100; it++) {
            float bv = -3.4e38f; int bi = 0x7fffffff;
#pragma unroll
            for (int k = 0; k < 16; k++) {
                int n = lane + 32 * k;
                float v = s_sc[n];
                if (v > bv) { bv = v; bi = n; }
            }
            for (int off = 16; off; off >>= 1) {
                float ov = __shfl_xor_sync(0xffffffffu, bv, off);
                int   oi = __shfl_xor_sync(0xffffffffu, bi, off);
                if (ov > bv || (ov == bv && oi < bi)) { bv = ov; bi = oi; }
            }
            float kb0 = s_bs[bi], kb1 = s_be[bi];
            bool keep = bv > -5.0e8f;
            if (lane == 0) {
                out[2 * it]     = keep ? kb0 : 0.f;
                out[2 * it + 1] = keep ? kb1 : 0.f;
                out[200 + it]   = keep ? bv  : 0.f;
            }
#pragma unroll
            for (int k = 0; k < 16; k++) {
                int n = lane + 32 * k;
                float v = iou1d(kb0, kb1, s_bs[n], s_be[n]);
                if (v > 0.7f || n == bi) s_sc[n] = -1.0e9f;
            }
            __syncwarp();
        }
    }
}

// ============================================================================
extern "C" void kernel_launch(void* const* d_in, const int* in_sizes, int n_in,
                              void* d_out, int out_size) {
    const float* base = (const float*)d_in[0];
    const float* gt   = (const float*)d_in[1];
    const int*   vl   = (const int*)d_in[2];
    const float* c1w  = (const float*)d_in[3];
    const float* c1b  = (const float*)d_in[4];
    const float* c2w  = (const float*)d_in[5];
    const float* c2b  = (const float*)d_in[6];
    const float* sw   = (const float*)d_in[7];
    const float* sb   = (const float*)d_in[8];
    const float* dw   = (const float*)d_in[9];
    const float* db   = (const float*)d_in[10];
    float* out = (float*)d_out;

    conv1_kernel<<<dim3(64, 8), 256>>>(base, c1w, c1b);
    conv2_kernel<<<dim3(64, 4), 256>>>(c2w, c2b);
    head_kernel<<<1, 512>>>(sw, sb, dw, db, gt, vl, out);
}

// round 3
// speedup vs baseline: 2.2128x; 1.5508x over previous
#include <cuda_runtime.h>

typedef unsigned long long ull;

// ---------------- problem constants ----------------
#define CIN   256
#define TT    64
#define HIN   32
#define WIN   32
#define C1    512
#define C2    512
#define NANCH 512

// conv1 padded-dup input layout: [ic][66 slices][33 rows x 66 floats] (+pad)
#define C1ROW   66
#define C1SLICE 2180            // 33*66 = 2178, padded to 2180 (8720B, 16B mult)
#define C1STAGE (3 * C1SLICE)   // 6540 floats
#define C1W     (27 * 64)       // 1728 floats

// conv2 padded-dup input layout: [ic][66 slices][17 rows x 34 floats] (+pad)
#define C2ROW   34
#define C2SLICE 580             // 17*34 = 578, padded to 580 (2320B, 16B mult)
#define C2STAGE (3 * C2SLICE)   // 1740 floats
#define C2W     (27 * 128)      // 3456 floats

// ---------------- device scratch ----------------
__device__ float g_p1[(size_t)CIN * 66 * C1SLICE];   // 147 MB
__device__ float g_p2[(size_t)C1  * 66 * C2SLICE];   //  78 MB
__device__ float g_w1[(size_t)CIN * 27 * 512];       //  14 MB  [ic][tap][oc]
__device__ float g_w2[(size_t)C1  * 27 * 512];       //  28 MB  [ic][tap][oc]
__device__ float g_feat[C2 * TT];

// ---------------- helpers ----------------
__device__ __forceinline__ ull ffma2(ull a, ull b, ull c) {
    ull d;
    asm("fma.rn.f32x2 %0, %1, %2, %3;" : "=l"(d) : "l"(a), "l"(b), "l"(c));
    return d;
}
__device__ __forceinline__ void upk2(ull v, float& lo, float& hi) {
    asm("mov.b64 {%0, %1}, %2;" : "=f"(lo), "=f"(hi) : "l"(v));
}
__device__ __forceinline__ void cp16(float* dst, const float* src) {
    unsigned d = (unsigned)__cvta_generic_to_shared(dst);
    asm volatile("cp.async.cg.shared.global [%0], [%1], 16;" :: "r"(d), "l"(src));
}

// ============================================================================
// Pre-layout kernels
// ============================================================================
__global__ void prepad_in(const float* __restrict__ in) {
    int sl = blockIdx.x;            // 0..65
    int ic = blockIdx.y;            // 0..255
    float* dst = g_p1 + ((size_t)ic * 66 + sl) * C1SLICE;
    int ti = sl - 1;
    for (int idx = threadIdx.x; idx < 33 * 33; idx += 256) {
        int hh = idx / 33, ww = idx - hh * 33;
        float v = 0.f;
        if (ti >= 0 && ti < TT && hh >= 1 && ww >= 1)
            v = in[((size_t)ic * TT + ti) * (HIN * WIN) + (hh - 1) * WIN + (ww - 1)];
        *(float2*)&dst[hh * C1ROW + 2 * ww] = make_float2(v, v);
    }
    if (threadIdx.x == 0) { dst[2178] = 0.f; dst[2179] = 0.f; }
}

__global__ void transpose_w(const float* __restrict__ w, float* __restrict__ dst,
                            int nic) {
    int ic = blockIdx.x;
    for (int i = threadIdx.x; i < 27 * 512; i += blockDim.x) {
        int oc = i & 511, tap = i >> 9;
        dst[((size_t)ic * 27 + tap) * 512 + oc] =
            w[((size_t)oc * nic + ic) * 27 + tap];
    }
}

__global__ void zero_halo2() {
    int oc = blockIdx.x;
    float* base = g_p2 + (size_t)oc * 66 * C2SLICE;
    for (int i = threadIdx.x; i < C2SLICE; i += 256) {
        base[i] = 0.f;
        base[(size_t)65 * C2SLICE + i] = 0.f;
    }
    for (int i = threadIdx.x; i < 64 * C2ROW; i += 256) {      // row 0 of slices 1..64
        int s = 1 + i / C2ROW, c = i - (i / C2ROW) * C2ROW;
        base[(size_t)s * C2SLICE + c] = 0.f;
    }
    for (int i = threadIdx.x; i < 64 * 16; i += 256) {         // left col pair
        int s = 1 + (i >> 4), r = 1 + (i & 15);
        base[(size_t)s * C2SLICE + r * C2ROW]     = 0.f;
        base[(size_t)s * C2SLICE + r * C2ROW + 1] = 0.f;
    }
    for (int i = threadIdx.x; i < 64; i += 256) {              // slice tail pad
        base[(size_t)(1 + i) * C2SLICE + 578] = 0.f;
        base[(size_t)(1 + i) * C2SLICE + 579] = 0.f;
    }
}

// ============================================================================
// Conv1: g_p1 * w -> g_p2 (padded, duplicated, bias added)
// Grid (64 t, 8 oc-tiles of 64). Block 256. Thread: 8 oc x 8 cols of one row.
// cp.async double-buffered staging, 1 block copy per ic.
// ============================================================================
__global__ void __launch_bounds__(256, 2)
conv1_kernel(const float* __restrict__ b) {
    extern __shared__ __align__(16) float smem[];
    float* inb[2] = { smem, smem + C1STAGE };
    float* wb_[2] = { smem + 2 * C1STAGE, smem + 2 * C1STAGE + C1W };

    const int t    = blockIdx.x;
    const int oc0  = blockIdx.y * 64;
    const int tid  = threadIdx.x;
    const int warp = tid >> 5;
    const int lane = tid & 31;
    const int ocg  = ((warp >> 2) << 2) | (lane >> 3);
    const int h    = (((warp >> 1) & 1) << 3) | (lane & 7);
    const int wbase= (warp & 1) * 8;

    ull acc[4][8];
#pragma unroll
    for (int k = 0; k < 4; k++)
#pragma unroll
        for (int j = 0; j < 8; j++) acc[k][j] = 0ull;

    // ---- staging macro: input 1635 chunks, weights 432 chunks --------------
#define C1_STAGE(ICN, IBUF, WBUF)                                              \
    {                                                                          \
        const float* src = g_p1 + ((size_t)(ICN) * 66 + t) * C1SLICE;          \
        _Pragma("unroll")                                                      \
        for (int j = 0; j < 7; j++) {                                          \
            int idx = tid + j * 256;                                           \
            if (idx < 1635) cp16((IBUF) + idx * 4, src + idx * 4);             \
        }                                                                      \
        const float* wsrc = g_w1 + (size_t)(ICN) * 27 * 512 + oc0;             \
        _Pragma("unroll")                                                      \
        for (int j = 0; j < 2; j++) {                                          \
            int idx = tid + j * 256;                                           \
            if (idx < 432) {                                                   \
                int tap = idx >> 4, part = idx & 15;                           \
                cp16((WBUF) + tap * 64 + part * 4, wsrc + tap * 512 + part * 4); \
            }                                                                  \
        }                                                                      \
    }

    C1_STAGE(0, inb[0], wb_[0]);
    asm volatile("cp.async.commit_group;");

    for (int ic = 0; ic < CIN; ic++) {
        const float* ibuf = inb[ic & 1];
        const float* wbuf = wb_[ic & 1];
        if (ic + 1 < CIN) {
            C1_STAGE(ic + 1, inb[(ic + 1) & 1], wb_[(ic + 1) & 1]);
            asm volatile("cp.async.commit_group;");
            asm volatile("cp.async.wait_group 1;");
        } else {
            asm volatile("cp.async.wait_group 0;");
        }
        __syncthreads();

#pragma unroll
        for (int kd = 0; kd < 3; kd++) {
#pragma unroll
            for (int kh = 0; kh < 3; kh++) {
                const ull* up = (const ull*)(ibuf + kd * C1SLICE
                                             + (2 * h + kh) * C1ROW) + 2 * wbase;
                const int tap0 = kd * 9 + kh * 3;
                ull e[9];
#pragma unroll
                for (int j = 0; j < 9; j++) e[j] = up[2 * j];
                {
                    const ull* wp = (const ull*)(wbuf + tap0 * 64 + ocg * 8);
                    ull wv[4];
#pragma unroll
                    for (int k = 0; k < 4; k++) wv[k] = wp[k];
#pragma unroll
                    for (int k = 0; k < 4; k++)
#pragma unroll
                        for (int j = 0; j < 8; j++)
                            acc[k][j] = ffma2(e[j], wv[k], acc[k][j]);
                }
                {
                    const ull* wp = (const ull*)(wbuf + (tap0 + 2) * 64 + ocg * 8);
                    ull wv[4];
#pragma unroll
                    for (int k = 0; k < 4; k++) wv[k] = wp[k];
#pragma unroll
                    for (int k = 0; k < 4; k++)
#pragma unroll
                        for (int j = 0; j < 8; j++)
                            acc[k][j] = ffma2(e[j + 1], wv[k], acc[k][j]);
                }
                {
                    ull o[8];
#pragma unroll
                    for (int j = 0; j < 8; j++) o[j] = up[2 * j + 1];
                    const ull* wp = (const ull*)(wbuf + (tap0 + 1) * 64 + ocg * 8);
                    ull wv[4];
#pragma unroll
                    for (int k = 0; k < 4; k++) wv[k] = wp[k];
#pragma unroll
                    for (int k = 0; k < 4; k++)
#pragma unroll
                        for (int j = 0; j < 8; j++)
                            acc[k][j] = ffma2(o[j], wv[k], acc[k][j]);
                }
            }
        }
        __syncthreads();
    }
#undef C1_STAGE

    // epilogue: bias + write duplicated into g_p2 padded layout
#pragma unroll
    for (int k = 0; k < 4; k++) {
        float lo[8], hi[8];
#pragma unroll
        for (int j = 0; j < 8; j++) upk2(acc[k][j], lo[j], hi[j]);
        int oca = oc0 + ocg * 8 + 2 * k;
        float ba = b[oca], bb = b[oca + 1];
        float* pa = g_p2 + ((size_t)oca * 66 + (t + 1)) * C2SLICE
                    + (h + 1) * C2ROW + 2 * (1 + wbase);
        float* pb = pa + (size_t)66 * C2SLICE;
#pragma unroll
        for (int j = 0; j < 8; j++) {
            *(float2*)(pa + 2 * j) = make_float2(lo[j] + ba, lo[j] + ba);
            *(float2*)(pb + 2 * j) = make_float2(hi[j] + bb, hi[j] + bb);
        }
    }
}

// ============================================================================
// Conv2 + maxpool: g_p2 * w -> g_feat (512, 64)
// Grid (64 t, 4 oc-tiles of 128). Block 128 = 16 ocg x 8 h. 4 CTAs/SM.
// Thread: 8 oc x 8 cols of one row; fused max over cols then rows.
// ============================================================================
__global__ void __launch_bounds__(128, 4)
conv2_kernel(const float* __restrict__ b) {
    __shared__ __align__(16) float in_s[2][C2STAGE];
    __shared__ __align__(16) float w_s[2][C2W];
    __shared__ float red[128 * 9];

    const int t    = blockIdx.x;
    const int oc0  = blockIdx.y * 128;
    const int tid  = threadIdx.x;
    const int warp = tid >> 5;
    const int lane = tid & 31;
    const int ocg  = (warp << 2) | (lane >> 3);   // 0..15
    const int h    = lane & 7;

    ull acc[4][8];
#pragma unroll
    for (int k = 0; k < 4; k++)
#pragma unroll
        for (int j = 0; j < 8; j++) acc[k][j] = 0ull;

#define C2_STAGE(ICN, IBUF, WBUF)                                              \
    {                                                                          \
        const float* src = g_p2 + ((size_t)(ICN) * 66 + t) * C2SLICE;          \
        _Pragma("unroll")                                                      \
        for (int j = 0; j < 4; j++) {                                          \
            int idx = tid + j * 128;                                           \
            if (idx < 435) cp16((IBUF) + idx * 4, src + idx * 4);              \
        }                                                                      \
        const float* wsrc = g_w2 + (size_t)(ICN) * 27 * 512 + oc0;             \
        _Pragma("unroll")                                                      \
        for (int j = 0; j < 7; j++) {                                          \
            int idx = tid + j * 128;                                           \
            if (idx < 864) {                                                   \
                int tap = idx >> 5, part = idx & 31;                           \
                cp16((WBUF) + tap * 128 + part * 4, wsrc + tap * 512 + part * 4); \
            }                                                                  \
        }                                                                      \
    }

    C2_STAGE(0, in_s[0], w_s[0]);
    asm volatile("cp.async.commit_group;");

    for (int ic = 0; ic < C1; ic++) {
        const float* ibuf = in_s[ic & 1];
        const float* wbuf = w_s[ic & 1];
        if (ic + 1 < C1) {
            C2_STAGE(ic + 1, in_s[(ic + 1) & 1], w_s[(ic + 1) & 1]);
            asm volatile("cp.async.commit_group;");
            asm volatile("cp.async.wait_group 1;");
        } else {
            asm volatile("cp.async.wait_group 0;");
        }
        __syncthreads();

#pragma unroll
        for (int kd = 0; kd < 3; kd++) {
#pragma unroll
            for (int kh = 0; kh < 3; kh++) {
                const ull* up = (const ull*)(ibuf + kd * C2SLICE
                                             + (2 * h + kh) * C2ROW);
                const int tap0 = kd * 9 + kh * 3;
                ull e[9];
#pragma unroll
                for (int j = 0; j < 9; j++) e[j] = up[2 * j];
                {
                    const ull* wp = (const ull*)(wbuf + tap0 * 128 + ocg * 8);
                    ull wv[4];
#pragma unroll
                    for (int k = 0; k < 4; k++) wv[k] = wp[k];
#pragma unroll
                    for (int k = 0; k < 4; k++)
#pragma unroll
                        for (int j = 0; j < 8; j++)
                            acc[k][j] = ffma2(e[j], wv[k], acc[k][j]);
                }
                {
                    const ull* wp = (const ull*)(wbuf + (tap0 + 2) * 128 + ocg * 8);
                    ull wv[4];
#pragma unroll
                    for (int k = 0; k < 4; k++) wv[k] = wp[k];
#pragma unroll
                    for (int k = 0; k < 4; k++)
#pragma unroll
                        for (int j = 0; j < 8; j++)
                            acc[k][j] = ffma2(e[j + 1], wv[k], acc[k][j]);
                }
                {
                    ull o[8];
#pragma unroll
                    for (int j = 0; j < 8; j++) o[j] = up[2 * j + 1];
                    const ull* wp = (const ull*)(wbuf + (tap0 + 1) * 128 + ocg * 8);
                    ull wv[4];
#pragma unroll
                    for (int k = 0; k < 4; k++) wv[k] = wp[k];
#pragma unroll
                    for (int k = 0; k < 4; k++)
#pragma unroll
                        for (int j = 0; j < 8; j++)
                            acc[k][j] = ffma2(o[j], wv[k], acc[k][j]);
                }
            }
        }
        __syncthreads();
    }
#undef C2_STAGE

    // maxpool over this thread's 8 cols -> red[oc][h], then over h
#pragma unroll
    for (int k = 0; k < 4; k++) {
        float mlo = -3.4e38f, mhi = -3.4e38f;
#pragma unroll
        for (int j = 0; j < 8; j++) {
            float lo, hi;
            upk2(acc[k][j], lo, hi);
            mlo = fmaxf(mlo, lo);
            mhi = fmaxf(mhi, hi);
        }
        red[(ocg * 8 + 2 * k) * 9 + h]     = mlo;
        red[(ocg * 8 + 2 * k + 1) * 9 + h] = mhi;
    }
    __syncthreads();
    {
        float m = -3.4e38f;
#pragma unroll
        for (int p = 0; p < 8; p++) m = fmaxf(m, red[tid * 9 + p]);
        g_feat[(oc0 + tid) * TT + t] = m + b[oc0 + tid];
    }
}

// ============================================================================
// Head (unchanged, passing since R1)
// ============================================================================
__device__ __forceinline__ float iou1d(float s1, float e1, float s2, float e2) {
    float inter = fmaxf(fminf(e1, e2) - fmaxf(s1, s2), 0.f);
    float uni   = (e1 - s1) + (e2 - s2) - inter;
    return inter / fmaxf(uni, 1e-6f);
}

__global__ void __launch_bounds__(512, 1)
head_kernel(const float* __restrict__ sw, const float* __restrict__ sb,
            const float* __restrict__ dw, const float* __restrict__ db,
            const float* __restrict__ gt, const int* __restrict__ vlen,
            float* __restrict__ out) {
    __shared__ float s_sl[16 * 64], s_dl[16 * 64];
    __shared__ float s_bs[NANCH], s_be[NANCH], s_sc[NANCH];
    __shared__ float s_as[NANCH], s_ae[NANCH];
    __shared__ float s_lp0[NANCH], s_lp1[NANCH], s_dc[NANCH], s_dt[NANCH];
    __shared__ float s_gt[16];
    __shared__ int   s_best[8];
    __shared__ float r0[512], r1[512], r2[512], r3[512];

    const int tid  = threadIdx.x;
    const int wid  = tid >> 5;
    const int lane = tid & 31;
    if (tid < 16) s_gt[tid] = gt[tid];

    const int o = tid >> 6;
    const int t = tid & 63;
    {
        float a0 = sb[o], a1 = sb[o + 8], d0 = db[o], d1 = db[o + 8];
        for (int c = 0; c < C2; c++) {
            float f = g_feat[c * 64 + t];
            a0 = fmaf(sw[o * 512 + c],       f, a0);
            a1 = fmaf(sw[(o + 8) * 512 + c], f, a1);
            d0 = fmaf(dw[o * 512 + c],       f, d0);
            d1 = fmaf(dw[(o + 8) * 512 + c], f, d1);
        }
        s_sl[o * 64 + t] = a0;  s_sl[(o + 8) * 64 + t] = a1;
        s_dl[o * 64 + t] = d0;  s_dl[(o + 8) * 64 + t] = d1;
    }
    __syncthreads();

    {
        const int a = o;
        float l0 = s_sl[a * 64 + t], l1 = s_sl[(a + 8) * 64 + t];
        float mx = fmaxf(l0, l1);
        float lse = mx + logf(expf(l0 - mx) + expf(l1 - mx));
        float p1  = expf(l1 - lse);
        float dc  = s_dl[a * 64 + t], dl = s_dl[(a + 8) * 64 + t];
        float alen = (float)(8 << a);
        float ctr  = (t + 0.5f) * 8.f;
        float pc = ctr + dc * alen;
        float pl = alen * expf(fminf(fmaxf(dl, -10.f), 10.f));
        float ps = fminf(fmaxf(pc - 0.5f * pl, 0.f), 512.f);
        float pe = fminf(fmaxf(pc + 0.5f * pl, 0.f), 512.f);
        s_bs[tid] = ps;  s_be[tid] = pe;
        s_sc[tid] = (pe - ps >= 4.f) ? p1 : -1.0e9f;
        s_as[tid] = ctr - 0.5f * alen;
        s_ae[tid] = ctr + 0.5f * alen;
        s_lp0[tid] = l0 - lse;  s_lp1[tid] = l1 - lse;
        s_dc[tid] = dc;  s_dt[tid] = dl;
    }
    __syncthreads();

    if (wid < 8) {
        float gs = s_gt[wid * 2], ge = s_gt[wid * 2 + 1];
        float bv = -3.4e38f; int bi = 0x7fffffff;
        for (int k = 0; k < 16; k++) {
            int n = lane + 32 * k;
            float v = iou1d(s_as[n], s_ae[n], gs, ge);
            if (v > bv) { bv = v; bi = n; }
        }
        for (int off = 16; off; off >>= 1) {
            float ov = __shfl_xor_sync(0xffffffffu, bv, off);
            int   oi = __shfl_xor_sync(0xffffffffu, bi, off);
            if (ov > bv || (ov == bv && oi < bi)) { bv = ov; bi = oi; }
        }
        if (lane == 0) s_best[wid] = bi;
    }
    __syncthreads();

    {
        float myas = s_as[tid], myae = s_ae[tid];
        float miou = -1.f; int ag = 0;
#pragma unroll
        for (int g = 0; g < 8; g++) {
            float v = iou1d(myas, myae, s_gt[2 * g], s_gt[2 * g + 1]);
            if (v > miou) { miou = v; ag = g; }
        }
        int lab = (miou < 0.3f) ? 0 : -1;
        if (miou >= 0.7f) lab = 1;
#pragma unroll
        for (int g = 0; g < 8; g++)
            if (s_best[g] == tid) lab = 1;
        float vl = (float)vlen[0];
        if (!(myas >= 0.f && myae <= vl)) lab = -1;

        float gs = s_gt[2 * ag], ge = s_gt[2 * ag + 1];
        float gc = 0.5f * (gs + ge);
        float gl = fmaxf(ge - gs, 1e-6f);
        float ac = 0.5f * (myas + myae);
        float al = myae - myas;
        float rl0 = (gc - ac) / al;
        float rl1 = logf(gl / al);
        float d0 = s_dc[tid] - rl0, d1 = s_dt[tid] - rl1;
        float sl1 = (fabsf(d0) < 1.f ? 0.5f * d0 * d0 : fabsf(d0) - 0.5f)
                  + (fabsf(d1) < 1.f ? 0.5f * d1 * d1 : fabsf(d1) - 0.5f);
        float maskv = (lab >= 0) ? 1.f : 0.f;
        float posv  = (lab == 1) ? 1.f : 0.f;
        float nll   = -((lab == 1) ? s_lp1[tid] : s_lp0[tid]);
        r0[tid] = nll * maskv;  r1[tid] = maskv;
        r2[tid] = sl1 * posv;   r3[tid] = posv;
    }
    __syncthreads();
    for (int s = 256; s > 0; s >>= 1) {
        if (tid < s) {
            r0[tid] += r0[tid + s];  r1[tid] += r1[tid + s];
            r2[tid] += r2[tid + s];  r3[tid] += r3[tid + s];
        }
        __syncthreads();
    }
    if (tid == 0) {
        out[300] = r0[0] / fmaxf(r1[0], 1.f);
        out[301] = r2[0] / fmaxf(r3[0], 1.f);
    }
    __syncthreads();

    if (wid == 0) {
        for (int it = 0; it < 100; it++) {
            float bv = -3.4e38f; int bi = 0x7fffffff;
#pragma unroll
            for (int k = 0; k < 16; k++) {
                int n = lane + 32 * k;
                float v = s_sc[n];
                if (v > bv) { bv = v; bi = n; }
            }
            for (int off = 16; off; off >>= 1) {
                float ov = __shfl_xor_sync(0xffffffffu, bv, off);
                int   oi = __shfl_xor_sync(0xffffffffu, bi, off);
                if (ov > bv || (ov == bv && oi < bi)) { bv = ov; bi = oi; }
            }
            float kb0 = s_bs[bi], kb1 = s_be[bi];
            bool keep = bv > -5.0e8f;
            if (lane == 0) {
                out[2 * it]     = keep ? kb0 : 0.f;
                out[2 * it + 1] = keep ? kb1 : 0.f;
                out[200 + it]   = keep ? bv  : 0.f;
            }
#pragma unroll
            for (int k = 0; k < 16; k++) {
                int n = lane + 32 * k;
                float v = iou1d(kb0, kb1, s_bs[n], s_be[n]);
                if (v > 0.7f || n == bi) s_sc[n] = -1.0e9f;
            }
            __syncwarp();
        }
    }
}

// ============================================================================
extern "C" void kernel_launch(void* const* d_in, const int* in_sizes, int n_in,
                              void* d_out, int out_size) {
    const float* base = (const float*)d_in[0];
    const float* gt   = (const float*)d_in[1];
    const int*   vl   = (const int*)d_in[2];
    const float* c1w  = (const float*)d_in[3];
    const float* c1b  = (const float*)d_in[4];
    const float* c2w  = (const float*)d_in[5];
    const float* c2b  = (const float*)d_in[6];
    const float* sw   = (const float*)d_in[7];
    const float* sb   = (const float*)d_in[8];
    const float* dw   = (const float*)d_in[9];
    const float* db   = (const float*)d_in[10];
    float* out = (float*)d_out;

    static int smem_set = 0;
    const int c1_smem = (2 * C1STAGE + 2 * C1W) * 4;   // 66144 B
    if (!smem_set) {
        cudaFuncSetAttribute(conv1_kernel,
                             cudaFuncAttributeMaxDynamicSharedMemorySize, c1_smem);
        smem_set = 1;
    }

    float* w1d; cudaGetSymbolAddress((void**)&w1d, g_w1);
    float* w2d; cudaGetSymbolAddress((void**)&w2d, g_w2);

    prepad_in<<<dim3(66, 256), 256>>>(base);
    transpose_w<<<256, 256>>>(c1w, w1d, CIN);
    transpose_w<<<512, 256>>>(c2w, w2d, C1);
    zero_halo2<<<512, 256>>>();
    conv1_kernel<<<dim3(64, 8), 256, c1_smem>>>(c1b);
    conv2_kernel<<<dim3(64, 4), 128>>>(c2b);
    head_kernel<<<1, 512>>>(sw, sb, dw, db, gt, vl, out);
}

// round 6
// speedup vs baseline: 3.5581x; 1.6080x over previous
#include <cuda_runtime.h>
#include <cuda_bf16.h>
#include <cstdint>

typedef unsigned long long ull;

// ---------------- problem constants ----------------
#define CIN   256
#define TT    64
#define HIN   32
#define WIN   32
#define C1    512
#define C2    512
#define NANCH 512

#define K1      6912          // 256 ic * 27 taps
#define NCHUNK  324           // 3 segments * 108 chunks of 64
#define CHUNKK  64

// conv2 padded-dup input layout
#define C2ROW   34
#define C2SLICE 580
#define C2STAGE (3 * C2SLICE)
#define C2W     (27 * 128)

// conv1 mma staging
#define STAGE_BYTES 49152      // A 16KB + B 32KB
#define C1MMA_SMEM  (2 * STAGE_BYTES)

// ---------------- device scratch ----------------
__device__ __align__(16) __nv_bfloat16 g_a1h[(size_t)64 * 256 * K1];  // 226 MB
__device__ __align__(16) __nv_bfloat16 g_a1l[(size_t)64 * 256 * K1];  // 226 MB
__device__ __align__(16) __nv_bfloat16 g_b1h[(size_t)C1 * K1];        //   7 MB
__device__ __align__(16) __nv_bfloat16 g_b1l[(size_t)C1 * K1];        //   7 MB
__device__ float g_p2[(size_t)C1 * 66 * C2SLICE];                      //  78 MB
__device__ float g_w2[(size_t)C1 * 27 * 512];                          //  28 MB
__device__ float g_feat[C2 * TT];

// ---------------- scalar helpers ----------------
__device__ __forceinline__ ull ffma2(ull a, ull b, ull c) {
    ull d;
    asm("fma.rn.f32x2 %0, %1, %2, %3;" : "=l"(d) : "l"(a), "l"(b), "l"(c));
    return d;
}
__device__ __forceinline__ void upk2(ull v, float& lo, float& hi) {
    asm("mov.b64 {%0, %1}, %2;" : "=f"(lo), "=f"(hi) : "l"(v));
}
__device__ __forceinline__ void cp16(float* dst, const float* src) {
    unsigned d = (unsigned)__cvta_generic_to_shared(dst);
    asm volatile("cp.async.cg.shared.global [%0], [%1], 16;" :: "r"(d), "l"(src));
}
__device__ __forceinline__ void cp16u(unsigned dst, const void* src) {
    asm volatile("cp.async.cg.shared.global [%0], [%1], 16;" :: "r"(dst), "l"(src));
}
__device__ __forceinline__ uint32_t smem_u32(const void* p) {
    return (uint32_t)__cvta_generic_to_shared(p);
}

// ============================================================================
// Prepass: split conv1 weights into bf16 hi/lo   (k = ic*27+tap natural order)
// ============================================================================
__global__ void split_w1(const float* __restrict__ w) {
    int oc = blockIdx.x;
    const float* src = w + (size_t)oc * K1;
    __nv_bfloat16* dh = g_b1h + (size_t)oc * K1;
    __nv_bfloat16* dl = g_b1l + (size_t)oc * K1;
    for (int k = threadIdx.x; k < K1; k += 256) {
        float v = src[k];
        __nv_bfloat16 hi = __float2bfloat16(v);
        dh[k] = hi;
        dl[k] = __float2bfloat16(v - __bfloat162float(hi));
    }
}

// ============================================================================
// Prepass: im2col + split of input -> A1 [t][m(256)][k(6912)] hi/lo bf16
// ============================================================================
__global__ void im2col1(const float* __restrict__ in) {
    const int t = blockIdx.x;
    const int m = blockIdx.y;
    const int h = m >> 4, w = m & 15;
    __nv_bfloat16* dh = g_a1h + ((size_t)t * 256 + m) * K1;
    __nv_bfloat16* dl = g_a1l + ((size_t)t * 256 + m) * K1;
#pragma unroll
    for (int j = 0; j < 27; j++) {
        int k   = threadIdx.x + j * 256;
        int ic  = k / 27;
        int tap = k - ic * 27;
        int kd = tap / 9, r = tap - kd * 9, kh = r / 3, kw = r - kh * 3;
        int ti = t + kd - 1, hh = 2 * h + kh - 1, ww = 2 * w + kw - 1;
        float v = 0.f;
        if (ti >= 0 && ti < TT && hh >= 0 && hh < HIN && ww >= 0 && ww < WIN)
            v = in[((size_t)(ic * TT + ti) * HIN + hh) * WIN + ww];
        __nv_bfloat16 hi = __float2bfloat16(v);
        dh[k] = hi;
        dl[k] = __float2bfloat16(v - __bfloat162float(hi));
    }
}

// ============================================================================
// Prepass: transpose conv2 weights [oc][ic][tap] -> [ic][tap][oc]
// ============================================================================
__global__ void transpose_w(const float* __restrict__ w, float* __restrict__ dst,
                            int nic) {
    int ic = blockIdx.x;
    for (int i = threadIdx.x; i < 27 * 512; i += blockDim.x) {
        int oc = i & 511, tap = i >> 9;
        dst[((size_t)ic * 27 + tap) * 512 + oc] =
            w[((size_t)oc * nic + ic) * 27 + tap];
    }
}

// ============================================================================
// Prepass: zero conv2 input halo regions in g_p2
// ============================================================================
__global__ void zero_halo2() {
    int oc = blockIdx.x;
    float* base = g_p2 + (size_t)oc * 66 * C2SLICE;
    for (int i = threadIdx.x; i < C2SLICE; i += 256) {
        base[i] = 0.f;
        base[(size_t)65 * C2SLICE + i] = 0.f;
    }
    for (int i = threadIdx.x; i < 64 * C2ROW; i += 256) {
        int s = 1 + i / C2ROW, c = i - (i / C2ROW) * C2ROW;
        base[(size_t)s * C2SLICE + c] = 0.f;
    }
    for (int i = threadIdx.x; i < 64 * 16; i += 256) {
        int s = 1 + (i >> 4), r = 1 + (i & 15);
        base[(size_t)s * C2SLICE + r * C2ROW]     = 0.f;
        base[(size_t)s * C2SLICE + r * C2ROW + 1] = 0.f;
    }
    for (int i = threadIdx.x; i < 64; i += 256) {
        base[(size_t)(1 + i) * C2SLICE + 578] = 0.f;
        base[(size_t)(1 + i) * C2SLICE + 579] = 0.f;
    }
}

// ============================================================================
// Conv1 via mma.sync bf16x3 GEMM (legacy HMMA path — sm_103 baseline PTX).
// Grid (t=64, mh=2, nq=2). 256 thr = 8 warps (2 m x 4 n), warp tile 64x64.
// CTA: M=128, N=256, K=3*6912 in 324 chunks of 64.
// B stored [n][k] in SMEM; ldmatrix (NON-trans) delivers the col-major B
// fragment directly: lane l gets stored[l>>2][2*(l%4)+j] = B[k][n].  (R5 bug
// was a spurious .trans here.)
// ============================================================================
__global__ void __launch_bounds__(256)
conv1_mma(const float* __restrict__ bias) {
    extern __shared__ __align__(128) char dsmem[];

    const int t    = blockIdx.x;
    const int mh   = blockIdx.y;
    const int nq   = blockIdx.z;
    const int tid  = threadIdx.x;
    const int warp = tid >> 5;
    const int lane = tid & 31;
    const int wm   = warp >> 2;          // 0/1 -> M offset
    const int wn   = warp & 3;           // 0..3 -> N offset

    const uint32_t abase = smem_u32(dsmem);

    // per-lane ldmatrix row bases (constant swizzle selector per lane)
    const int aRow = wm * 64 + ((lane >> 3) & 1) * 8 + (lane & 7);
    const int kA   = lane >> 4;                 // k-half select
    const int sA   = aRow & 7;
    const int bRow = wn * 64 + ((lane >> 4) << 3) + (lane & 7);
    const int kB   = (lane >> 3) & 1;
    const int sB   = bRow & 7;

    float acc[4][8][4];
#pragma unroll
    for (int mi = 0; mi < 4; mi++)
#pragma unroll
        for (int ni = 0; ni < 8; ni++)
#pragma unroll
            for (int r = 0; r < 4; r++) acc[mi][ni][r] = 0.f;

    const size_t arow0 = ((size_t)t * 256 + mh * 128) * K1;
    const size_t boff  = (size_t)(nq * 256) * K1;

#define STAGE_LOAD(CH, S)                                                      \
    {                                                                          \
        int seg = (CH) / 108;                                                  \
        int kin = ((CH) - seg * 108) * CHUNKK;                                 \
        const __nv_bfloat16* asrc = (seg == 1) ? g_a1l : g_a1h;                \
        const __nv_bfloat16* bsrc = (seg == 2) ? g_b1l : g_b1h;                \
        uint32_t ab = abase + (S) * STAGE_BYTES;                               \
        uint32_t bb = ab + 16384;                                              \
        _Pragma("unroll")                                                      \
        for (int j = 0; j < 4; j++) {                                          \
            int idx = tid + j * 256;                                           \
            int m = idx >> 3, kp = idx & 7;                                    \
            cp16u(ab + m * 128 + ((kp ^ (m & 7)) << 4),                        \
                  asrc + arow0 + (size_t)m * K1 + kin + kp * 8);               \
        }                                                                      \
        _Pragma("unroll")                                                      \
        for (int j = 0; j < 8; j++) {                                          \
            int idx = tid + j * 256;                                           \
            int oc = idx >> 3, kp = idx & 7;                                   \
            cp16u(bb + oc * 128 + ((kp ^ (oc & 7)) << 4),                      \
                  bsrc + boff + (size_t)oc * K1 + kin + kp * 8);               \
        }                                                                      \
    }

    STAGE_LOAD(0, 0);
    asm volatile("cp.async.commit_group;");

    for (int c = 0; c < NCHUNK; c++) {
        const int b = c & 1;
        asm volatile("cp.async.wait_group 0;");
        __syncthreads();
        if (c + 1 < NCHUNK) {
            STAGE_LOAD(c + 1, (c + 1) & 1);
            asm volatile("cp.async.commit_group;");
        }

        const uint32_t abuf = abase + b * STAGE_BYTES;
        const uint32_t aB = abuf + aRow * 128;
        const uint32_t bB = abuf + 16384 + bRow * 128;

#pragma unroll
        for (int ks = 0; ks < 4; ks++) {
            uint32_t a[4][4];
#pragma unroll
            for (int mi = 0; mi < 4; mi++) {
                uint32_t ad = aB + mi * 2048 + (((2 * ks + kA) ^ sA) << 4);
                asm volatile(
                    "ldmatrix.sync.aligned.m8n8.x4.shared.b16 {%0,%1,%2,%3}, [%4];"
                    : "=r"(a[mi][0]), "=r"(a[mi][1]), "=r"(a[mi][2]), "=r"(a[mi][3])
                    : "r"(ad));
            }
            uint32_t bg[8][2];
#pragma unroll
            for (int p = 0; p < 4; p++) {
                uint32_t bd = bB + p * 2048 + (((2 * ks + kB) ^ sB) << 4);
                asm volatile(
                    "ldmatrix.sync.aligned.m8n8.x4.shared.b16 {%0,%1,%2,%3}, [%4];"
                    : "=r"(bg[2 * p][0]), "=r"(bg[2 * p][1]),
                      "=r"(bg[2 * p + 1][0]), "=r"(bg[2 * p + 1][1])
                    : "r"(bd));
            }
#pragma unroll
            for (int mi = 0; mi < 4; mi++)
#pragma unroll
                for (int ni = 0; ni < 8; ni++)
                    asm volatile(
                        "mma.sync.aligned.m16n8k16.row.col.f32.bf16.bf16.f32 "
                        "{%0,%1,%2,%3}, {%4,%5,%6,%7}, {%8,%9}, {%0,%1,%2,%3};"
                        : "+f"(acc[mi][ni][0]), "+f"(acc[mi][ni][1]),
                          "+f"(acc[mi][ni][2]), "+f"(acc[mi][ni][3])
                        : "r"(a[mi][0]), "r"(a[mi][1]), "r"(a[mi][2]), "r"(a[mi][3]),
                          "r"(bg[ni][0]), "r"(bg[ni][1]));
        }
        __syncthreads();
    }
#undef STAGE_LOAD

    // epilogue: bias + write duplicated fp32 into g_p2 padded layout
    const int mrow = mh * 128 + wm * 64 + (lane >> 2);
    const int ncb  = nq * 256 + wn * 64 + 2 * (lane & 3);
#pragma unroll
    for (int ni = 0; ni < 8; ni++) {
        int n0 = ncb + ni * 8;
        float b0 = bias[n0], b1 = bias[n0 + 1];
        float* base0 = g_p2 + ((size_t)n0 * 66 + t + 1) * C2SLICE;
        float* base1 = g_p2 + ((size_t)(n0 + 1) * 66 + t + 1) * C2SLICE;
#pragma unroll
        for (int mi = 0; mi < 4; mi++) {
            int m0 = mrow + mi * 16;
            int m1 = m0 + 8;
            int o0 = ((m0 >> 4) + 1) * C2ROW + 2 * ((m0 & 15) + 1);
            int o1 = ((m1 >> 4) + 1) * C2ROW + 2 * ((m1 & 15) + 1);
            float v00 = acc[mi][ni][0] + b0;
            float v01 = acc[mi][ni][1] + b1;
            float v10 = acc[mi][ni][2] + b0;
            float v11 = acc[mi][ni][3] + b1;
            *(float2*)(base0 + o0) = make_float2(v00, v00);
            *(float2*)(base1 + o0) = make_float2(v01, v01);
            *(float2*)(base0 + o1) = make_float2(v10, v10);
            *(float2*)(base1 + o1) = make_float2(v11, v11);
        }
    }
}

// ============================================================================
// Conv2 + maxpool (FFMA2 path, unchanged from R3)
// ============================================================================
__global__ void __launch_bounds__(128, 4)
conv2_kernel(const float* __restrict__ b) {
    __shared__ __align__(16) float in_s[2][C2STAGE];
    __shared__ __align__(16) float w_s[2][C2W];
    __shared__ float red[128 * 9];

    const int t    = blockIdx.x;
    const int oc0  = blockIdx.y * 128;
    const int tid  = threadIdx.x;
    const int warp = tid >> 5;
    const int lane = tid & 31;
    const int ocg  = (warp << 2) | (lane >> 3);
    const int h    = lane & 7;

    ull acc[4][8];
#pragma unroll
    for (int k = 0; k < 4; k++)
#pragma unroll
        for (int j = 0; j < 8; j++) acc[k][j] = 0ull;

#define C2_STAGE(ICN, IBUF, WBUF)                                              \
    {                                                                          \
        const float* src = g_p2 + ((size_t)(ICN) * 66 + t) * C2SLICE;          \
        _Pragma("unroll")                                                      \
        for (int j = 0; j < 4; j++) {                                          \
            int idx = tid + j * 128;                                           \
            if (idx < 435) cp16((IBUF) + idx * 4, src + idx * 4);              \
        }                                                                      \
        const float* wsrc = g_w2 + (size_t)(ICN) * 27 * 512 + oc0;             \
        _Pragma("unroll")                                                      \
        for (int j = 0; j < 7; j++) {                                          \
            int idx = tid + j * 128;                                           \
            if (idx < 864) {                                                   \
                int tap = idx >> 5, part = idx & 31;                           \
                cp16((WBUF) + tap * 128 + part * 4, wsrc + tap * 512 + part * 4); \
            }                                                                  \
        }                                                                      \
    }

    C2_STAGE(0, in_s[0], w_s[0]);
    asm volatile("cp.async.commit_group;");

    for (int ic = 0; ic < C1; ic++) {
        const float* ibuf = in_s[ic & 1];
        const float* wbuf = w_s[ic & 1];
        if (ic + 1 < C1) {
            C2_STAGE(ic + 1, in_s[(ic + 1) & 1], w_s[(ic + 1) & 1]);
            asm volatile("cp.async.commit_group;");
            asm volatile("cp.async.wait_group 1;");
        } else {
            asm volatile("cp.async.wait_group 0;");
        }
        __syncthreads();

#pragma unroll
        for (int kd = 0; kd < 3; kd++) {
#pragma unroll
            for (int kh = 0; kh < 3; kh++) {
                const ull* up = (const ull*)(ibuf + kd * C2SLICE
                                             + (2 * h + kh) * C2ROW);
                const int tap0 = kd * 9 + kh * 3;
                ull e[9];
#pragma unroll
                for (int j = 0; j < 9; j++) e[j] = up[2 * j];
                {
                    const ull* wp = (const ull*)(wbuf + tap0 * 128 + ocg * 8);
                    ull wv[4];
#pragma unroll
                    for (int k = 0; k < 4; k++) wv[k] = wp[k];
#pragma unroll
                    for (int k = 0; k < 4; k++)
#pragma unroll
                        for (int j = 0; j < 8; j++)
                            acc[k][j] = ffma2(e[j], wv[k], acc[k][j]);
                }
                {
                    const ull* wp = (const ull*)(wbuf + (tap0 + 2) * 128 + ocg * 8);
                    ull wv[4];
#pragma unroll
                    for (int k = 0; k < 4; k++) wv[k] = wp[k];
#pragma unroll
                    for (int k = 0; k < 4; k++)
#pragma unroll
                        for (int j = 0; j < 8; j++)
                            acc[k][j] = ffma2(e[j + 1], wv[k], acc[k][j]);
                }
                {
                    ull o[8];
#pragma unroll
                    for (int j = 0; j < 8; j++) o[j] = up[2 * j + 1];
                    const ull* wp = (const ull*)(wbuf + (tap0 + 1) * 128 + ocg * 8);
                    ull wv[4];
#pragma unroll
                    for (int k = 0; k < 4; k++) wv[k] = wp[k];
#pragma unroll
                    for (int k = 0; k < 4; k++)
#pragma unroll
                        for (int j = 0; j < 8; j++)
                            acc[k][j] = ffma2(o[j], wv[k], acc[k][j]);
                }
            }
        }
        __syncthreads();
    }
#undef C2_STAGE

#pragma unroll
    for (int k = 0; k < 4; k++) {
        float mlo = -3.4e38f, mhi = -3.4e38f;
#pragma unroll
        for (int j = 0; j < 8; j++) {
            float lo, hi;
            upk2(acc[k][j], lo, hi);
            mlo = fmaxf(mlo, lo);
            mhi = fmaxf(mhi, hi);
        }
        red[(ocg * 8 + 2 * k) * 9 + h]     = mlo;
        red[(ocg * 8 + 2 * k + 1) * 9 + h] = mhi;
    }
    __syncthreads();
    {
        float m = -3.4e38f;
#pragma unroll
        for (int p = 0; p < 8; p++) m = fmaxf(m, red[tid * 9 + p]);
        g_feat[(oc0 + tid) * TT + t] = m + b[oc0 + tid];
    }
}

// ============================================================================
// Head (unchanged, passing since R1)
// ============================================================================
__device__ __forceinline__ float iou1d(float s1, float e1, float s2, float e2) {
    float inter = fmaxf(fminf(e1, e2) - fmaxf(s1, s2), 0.f);
    float uni   = (e1 - s1) + (e2 - s2) - inter;
    return inter / fmaxf(uni, 1e-6f);
}

__global__ void __launch_bounds__(512, 1)
head_kernel(const float* __restrict__ sw, const float* __restrict__ sb,
            const float* __restrict__ dw, const float* __restrict__ db,
            const float* __restrict__ gt, const int* __restrict__ vlen,
            float* __restrict__ out) {
    __shared__ float s_sl[16 * 64], s_dl[16 * 64];
    __shared__ float s_bs[NANCH], s_be[NANCH], s_sc[NANCH];
    __shared__ float s_as[NANCH], s_ae[NANCH];
    __shared__ float s_lp0[NANCH], s_lp1[NANCH], s_dc[NANCH], s_dt[NANCH];
    __shared__ float s_gt[16];
    __shared__ int   s_best[8];
    __shared__ float r0[512], r1[512], r2[512], r3[512];

    const int tid  = threadIdx.x;
    const int wid  = tid >> 5;
    const int lane = tid & 31;
    if (tid < 16) s_gt[tid] = gt[tid];

    const int o = tid >> 6;
    const int t = tid & 63;
    {
        float a0 = sb[o], a1 = sb[o + 8], d0 = db[o], d1 = db[o + 8];
        for (int c = 0; c < C2; c++) {
            float f = g_feat[c * 64 + t];
            a0 = fmaf(sw[o * 512 + c],       f, a0);
            a1 = fmaf(sw[(o + 8) * 512 + c], f, a1);
            d0 = fmaf(dw[o * 512 + c],       f, d0);
            d1 = fmaf(dw[(o + 8) * 512 + c], f, d1);
        }
        s_sl[o * 64 + t] = a0;  s_sl[(o + 8) * 64 + t] = a1;
        s_dl[o * 64 + t] = d0;  s_dl[(o + 8) * 64 + t] = d1;
    }
    __syncthreads();

    {
        const int a = o;
        float l0 = s_sl[a * 64 + t], l1 = s_sl[(a + 8) * 64 + t];
        float mx = fmaxf(l0, l1);
        float lse = mx + logf(expf(l0 - mx) + expf(l1 - mx));
        float p1  = expf(l1 - lse);
        float dc  = s_dl[a * 64 + t], dl = s_dl[(a + 8) * 64 + t];
        float alen = (float)(8 << a);
        float ctr  = (t + 0.5f) * 8.f;
        float pc = ctr + dc * alen;
        float pl = alen * expf(fminf(fmaxf(dl, -10.f), 10.f));
        float ps = fminf(fmaxf(pc - 0.5f * pl, 0.f), 512.f);
        float pe = fminf(fmaxf(pc + 0.5f * pl, 0.f), 512.f);
        s_bs[tid] = ps;  s_be[tid] = pe;
        s_sc[tid] = (pe - ps >= 4.f) ? p1 : -1.0e9f;
        s_as[tid] = ctr - 0.5f * alen;
        s_ae[tid] = ctr + 0.5f * alen;
        s_lp0[tid] = l0 - lse;  s_lp1[tid] = l1 - lse;
        s_dc[tid] = dc;  s_dt[tid] = dl;
    }
    __syncthreads();

    if (wid < 8) {
        float gs = s_gt[wid * 2], ge = s_gt[wid * 2 + 1];
        float bv = -3.4e38f; int bi = 0x7fffffff;
        for (int k = 0; k < 16; k++) {
            int n = lane + 32 * k;
            float v = iou1d(s_as[n], s_ae[n], gs, ge);
            if (v > bv) { bv = v; bi = n; }
        }
        for (int off = 16; off; off >>= 1) {
            float ov = __shfl_xor_sync(0xffffffffu, bv, off);
            int   oi = __shfl_xor_sync(0xffffffffu, bi, off);
            if (ov > bv || (ov == bv && oi < bi)) { bv = ov; bi = oi; }
        }
        if (lane == 0) s_best[wid] = bi;
    }
    __syncthreads();

    {
        float myas = s_as[tid], myae = s_ae[tid];
        float miou = -1.f; int ag = 0;
#pragma unroll
        for (int g = 0; g < 8; g++) {
            float v = iou1d(myas, myae, s_gt[2 * g], s_gt[2 * g + 1]);
            if (v > miou) { miou = v; ag = g; }
        }
        int lab = (miou < 0.3f) ? 0 : -1;
        if (miou >= 0.7f) lab = 1;
#pragma unroll
        for (int g = 0; g < 8; g++)
            if (s_best[g] == tid) lab = 1;
        float vl = (float)vlen[0];
        if (!(myas >= 0.f && myae <= vl)) lab = -1;

        float gs = s_gt[2 * ag], ge = s_gt[2 * ag + 1];
        float gc = 0.5f * (gs + ge);
        float gl = fmaxf(ge - gs, 1e-6f);
        float ac = 0.5f * (myas + myae);
        float al = myae - myas;
        float rl0 = (gc - ac) / al;
        float rl1 = logf(gl / al);
        float d0 = s_dc[tid] - rl0, d1 = s_dt[tid] - rl1;
        float sl1 = (fabsf(d0) < 1.f ? 0.5f * d0 * d0 : fabsf(d0) - 0.5f)
                  + (fabsf(d1) < 1.f ? 0.5f * d1 * d1 : fabsf(d1) - 0.5f);
        float maskv = (lab >= 0) ? 1.f : 0.f;
        float posv  = (lab == 1) ? 1.f : 0.f;
        float nll   = -((lab == 1) ? s_lp1[tid] : s_lp0[tid]);
        r0[tid] = nll * maskv;  r1[tid] = maskv;
        r2[tid] = sl1 * posv;   r3[tid] = posv;
    }
    __syncthreads();
    for (int s = 256; s > 0; s >>= 1) {
        if (tid < s) {
            r0[tid] += r0[tid + s];  r1[tid] += r1[tid + s];
            r2[tid] += r2[tid + s];  r3[tid] += r3[tid + s];
        }
        __syncthreads();
    }
    if (tid == 0) {
        out[300] = r0[0] / fmaxf(r1[0], 1.f);
        out[301] = r2[0] / fmaxf(r3[0], 1.f);
    }
    __syncthreads();

    if (wid == 0) {
        for (int it = 0; it < 100; it++) {
            float bv = -3.4e38f; int bi = 0x7fffffff;
#pragma unroll
            for (int k = 0; k < 16; k++) {
                int n = lane + 32 * k;
                float v = s_sc[n];
                if (v > bv) { bv = v; bi = n; }
            }
            for (int off = 16; off; off >>= 1) {
                float ov = __shfl_xor_sync(0xffffffffu, bv, off);
                int   oi = __shfl_xor_sync(0xffffffffu, bi, off);
                if (ov > bv || (ov == bv && oi < bi)) { bv = ov; bi = oi; }
            }
            float kb0 = s_bs[bi], kb1 = s_be[bi];
            bool keep = bv > -5.0e8f;
            if (lane == 0) {
                out[2 * it]     = keep ? kb0 : 0.f;
                out[2 * it + 1] = keep ? kb1 : 0.f;
                out[200 + it]   = keep ? bv  : 0.f;
            }
#pragma unroll
            for (int k = 0; k < 16; k++) {
                int n = lane + 32 * k;
                float v = iou1d(kb0, kb1, s_bs[n], s_be[n]);
                if (v > 0.7f || n == bi) s_sc[n] = -1.0e9f;
            }
            __syncwarp();
        }
    }
}

// ============================================================================
extern "C" void kernel_launch(void* const* d_in, const int* in_sizes, int n_in,
                              void* d_out, int out_size) {
    const float* base = (const float*)d_in[0];
    const float* gt   = (const float*)d_in[1];
    const int*   vl   = (const int*)d_in[2];
    const float* c1w  = (const float*)d_in[3];
    const float* c1b  = (const float*)d_in[4];
    const float* c2w  = (const float*)d_in[5];
    const float* c2b  = (const float*)d_in[6];
    const float* sw   = (const float*)d_in[7];
    const float* sb   = (const float*)d_in[8];
    const float* dw   = (const float*)d_in[9];
    const float* db   = (const float*)d_in[10];
    float* out = (float*)d_out;

    static int attr_set = 0;
    if (!attr_set) {
        cudaFuncSetAttribute(conv1_mma,
                             cudaFuncAttributeMaxDynamicSharedMemorySize, C1MMA_SMEM);
        attr_set = 1;
    }

    float* w2d; cudaGetSymbolAddress((void**)&w2d, g_w2);

    split_w1<<<512, 256>>>(c1w);
    im2col1<<<dim3(64, 256), 256>>>(base);
    zero_halo2<<<512, 256>>>();
    transpose_w<<<512, 256>>>(c2w, w2d, C1);
    conv1_mma<<<dim3(64, 2, 2), 256, C1MMA_SMEM>>>(c1b);
    conv2_kernel<<<dim3(64, 4), 128>>>(c2b);
    head_kernel<<<1, 512>>>(sw, sb, dw, db, gt, vl, out);
}

// round 7
// speedup vs baseline: 4.5177x; 1.2697x over previous
#include <cuda_runtime.h>
#include <cuda_bf16.h>
#include <cstdint>

typedef unsigned long long ull;

// ---------------- problem constants ----------------
#define CIN   256
#define TT    64
#define HIN   32
#define WIN   32
#define C1    512
#define C2    512
#define NANCH 512

// conv1 GEMM: K1 = 256 ic * 27 taps
#define K1      6912
#define NCHUNK1 324            // 3 segments * 108 chunks of 64
#define STAGE1_BYTES 49152     // A 16KB + B 32KB
#define C1MMA_SMEM  (2 * STAGE1_BYTES)

// conv2 GEMM: K2 = 512 ic * 32 padded taps (27 real + 5 zero)
#define K2      16384
#define NCHUNK2 768            // 3 segments * 256 chunks of 64
#define STAGE2_BYTES 40960     // A 8KB + B 32KB
#define C2MMA_SMEM  (2 * STAGE2_BYTES)

// ---------------- device scratch ----------------
__device__ __align__(16) __nv_bfloat16 g_a1h[(size_t)64 * 256 * K1];  // 226 MB
__device__ __align__(16) __nv_bfloat16 g_a1l[(size_t)64 * 256 * K1];  // 226 MB
__device__ __align__(16) __nv_bfloat16 g_b1h[(size_t)C1 * K1];        //   7 MB
__device__ __align__(16) __nv_bfloat16 g_b1l[(size_t)C1 * K1];        //   7 MB
__device__ float g_x1[(size_t)C1 * TT * 256];                          //  33 MB
__device__ __align__(16) __nv_bfloat16 g_a2h[(size_t)64 * 64 * K2];   // 134 MB
__device__ __align__(16) __nv_bfloat16 g_a2l[(size_t)64 * 64 * K2];   // 134 MB
__device__ __align__(16) __nv_bfloat16 g_b2h[(size_t)C2 * K2];        //  17 MB
__device__ __align__(16) __nv_bfloat16 g_b2l[(size_t)C2 * K2];        //  17 MB
__device__ float g_feat[C2 * TT];

// ---------------- helpers ----------------
__device__ __forceinline__ void cp16u(unsigned dst, const void* src) {
    asm volatile("cp.async.cg.shared.global [%0], [%1], 16;" :: "r"(dst), "l"(src));
}
__device__ __forceinline__ uint32_t smem_u32(const void* p) {
    return (uint32_t)__cvta_generic_to_shared(p);
}
__device__ __forceinline__ unsigned pack_bf2(float a, float b) {
    __nv_bfloat162 p = __floats2bfloat162_rn(a, b);
    return *reinterpret_cast<unsigned*>(&p);
}

// ============================================================================
// Prepass: split conv1 weights into bf16 hi/lo  (k = ic*27+tap natural order)
// ============================================================================
__global__ void split_w1(const float* __restrict__ w) {
    int oc = blockIdx.x;
    const float* src = w + (size_t)oc * K1;
    __nv_bfloat16* dh = g_b1h + (size_t)oc * K1;
    __nv_bfloat16* dl = g_b1l + (size_t)oc * K1;
    for (int k = threadIdx.x; k < K1; k += 256) {
        float v = src[k];
        __nv_bfloat16 hi = __float2bfloat16(v);
        dh[k] = hi;
        dl[k] = __float2bfloat16(v - __bfloat162float(hi));
    }
}

// ============================================================================
// Prepass: split conv2 weights -> [oc][ic*32+tap] padded order, hi/lo
// ============================================================================
__global__ void split_w2(const float* __restrict__ w) {
    int oc = blockIdx.x;
    const float* src = w + (size_t)oc * (512 * 27);
    __nv_bfloat16* dh = g_b2h + (size_t)oc * K2;
    __nv_bfloat16* dl = g_b2l + (size_t)oc * K2;
#pragma unroll 4
    for (int j = 0; j < 64; j++) {
        int k = threadIdx.x + j * 256;
        int ic = k >> 5, tap = k & 31;
        float v = (tap < 27) ? src[ic * 27 + tap] : 0.f;
        __nv_bfloat16 hi = __float2bfloat16(v);
        dh[k] = hi;
        dl[k] = __float2bfloat16(v - __bfloat162float(hi));
    }
}

// ============================================================================
// Prepass: im2col + split of input -> A1 [t][m(256)][k(6912)] hi/lo bf16
// ============================================================================
__global__ void im2col1(const float* __restrict__ in) {
    const int t = blockIdx.x;
    const int m = blockIdx.y;
    const int h = m >> 4, w = m & 15;
    __nv_bfloat16* dh = g_a1h + ((size_t)t * 256 + m) * K1;
    __nv_bfloat16* dl = g_a1l + ((size_t)t * 256 + m) * K1;
#pragma unroll
    for (int j = 0; j < 27; j++) {
        int k   = threadIdx.x + j * 256;
        int ic  = k / 27;
        int tap = k - ic * 27;
        int kd = tap / 9, r = tap - kd * 9, kh = r / 3, kw = r - kh * 3;
        int ti = t + kd - 1, hh = 2 * h + kh - 1, ww = 2 * w + kw - 1;
        float v = 0.f;
        if (ti >= 0 && ti < TT && hh >= 0 && hh < HIN && ww >= 0 && ww < WIN)
            v = in[((size_t)(ic * TT + ti) * HIN + hh) * WIN + ww];
        __nv_bfloat16 hi = __float2bfloat16(v);
        dh[k] = hi;
        dl[k] = __float2bfloat16(v - __bfloat162float(hi));
    }
}

// ============================================================================
// im2col2: g_x1 fp32 -> A2 [t*64+m][ic*32+tap] hi/lo bf16 (padded taps zero)
// Grid (64 t, 8 icg): each block handles 64 ics in 16 iters of 4.
// ============================================================================
__global__ void __launch_bounds__(256)
im2col2() {
    __shared__ float sm[4][3][256];
    const int t   = blockIdx.x;
    const int ic0 = blockIdx.y * 64;
    const int tid = threadIdx.x;
    const int icq = tid >> 6;
    const int m   = tid & 63;
    const int h   = m >> 3, w = m & 7;

    for (int it = 0; it < 16; it++) {
        const int icb = ic0 + it * 4;
        __syncthreads();
#pragma unroll
        for (int icq2 = 0; icq2 < 4; icq2++)
#pragma unroll
            for (int kd = 0; kd < 3; kd++) {
                int ti = t + kd - 1;
                sm[icq2][kd][tid & 255] = 0.f;
                if (ti >= 0 && ti < TT && tid < 256)
                    sm[icq2][kd][tid] =
                        g_x1[((size_t)(icb + icq2) * TT + ti) * 256 + tid];
            }
        __syncthreads();

        float v[32];
#pragma unroll
        for (int tap = 0; tap < 27; tap++) {
            const int kd = tap / 9, rr = tap - kd * 9;
            const int kh = rr / 3, kw = rr - kh * 3;
            int hh = 2 * h + kh - 1, ww = 2 * w + kw - 1;
            v[tap] = (hh >= 0 && ww >= 0) ? sm[icq][kd][hh * 16 + ww] : 0.f;
        }
#pragma unroll
        for (int tap = 27; tap < 32; tap++) v[tap] = 0.f;

        unsigned uh[16], ul[16];
#pragma unroll
        for (int p = 0; p < 16; p++) {
            float a = v[2 * p], b = v[2 * p + 1];
            uh[p] = pack_bf2(a, b);
            float ah = __bfloat162float(__float2bfloat16(a));
            float bh = __bfloat162float(__float2bfloat16(b));
            ul[p] = pack_bf2(a - ah, b - bh);
        }
        const size_t row = ((size_t)t * 64 + m) * K2 + (size_t)(icb + icq) * 32;
        uint4* dh = (uint4*)(g_a2h + row);
        uint4* dl = (uint4*)(g_a2l + row);
        dh[0] = make_uint4(uh[0], uh[1], uh[2], uh[3]);
        dh[1] = make_uint4(uh[4], uh[5], uh[6], uh[7]);
        dh[2] = make_uint4(uh[8], uh[9], uh[10], uh[11]);
        dh[3] = make_uint4(uh[12], uh[13], uh[14], uh[15]);
        dl[0] = make_uint4(ul[0], ul[1], ul[2], ul[3]);
        dl[1] = make_uint4(ul[4], ul[5], ul[6], ul[7]);
        dl[2] = make_uint4(ul[8], ul[9], ul[10], ul[11]);
        dl[3] = make_uint4(ul[12], ul[13], ul[14], ul[15]);
    }
}

// ============================================================================
// Conv1 via mma.sync bf16x3 GEMM.
// Grid (t=64, mh=2, nq=2). 256 thr = 8 warps (2m x 4n), warp tile 64x64.
// Epilogue: bias + plain fp32 store to g_x1[oc][t][m].
// ============================================================================
__global__ void __launch_bounds__(256)
conv1_mma(const float* __restrict__ bias) {
    extern __shared__ __align__(128) char dsmem[];

    const int t    = blockIdx.x;
    const int mh   = blockIdx.y;
    const int nq   = blockIdx.z;
    const int tid  = threadIdx.x;
    const int warp = tid >> 5;
    const int lane = tid & 31;
    const int wm   = warp >> 2;
    const int wn   = warp & 3;

    const uint32_t abase = smem_u32(dsmem);

    const int aRow = wm * 64 + ((lane >> 3) & 1) * 8 + (lane & 7);
    const int kA   = lane >> 4;
    const int sA   = aRow & 7;
    const int bRow = wn * 64 + ((lane >> 4) << 3) + (lane & 7);
    const int kB   = (lane >> 3) & 1;
    const int sB   = bRow & 7;

    float acc[4][8][4];
#pragma unroll
    for (int mi = 0; mi < 4; mi++)
#pragma unroll
        for (int ni = 0; ni < 8; ni++)
#pragma unroll
            for (int r = 0; r < 4; r++) acc[mi][ni][r] = 0.f;

    const size_t arow0 = ((size_t)t * 256 + mh * 128) * K1;
    const size_t boff  = (size_t)(nq * 256) * K1;

#define STAGE_LOAD1(CH, S)                                                     \
    {                                                                          \
        int seg = (CH) / 108;                                                  \
        int kin = ((CH) - seg * 108) * 64;                                     \
        const __nv_bfloat16* asrc = (seg == 1) ? g_a1l : g_a1h;                \
        const __nv_bfloat16* bsrc = (seg == 2) ? g_b1l : g_b1h;                \
        uint32_t ab = abase + (S) * STAGE1_BYTES;                              \
        uint32_t bb = ab + 16384;                                              \
        _Pragma("unroll")                                                      \
        for (int j = 0; j < 4; j++) {                                          \
            int idx = tid + j * 256;                                           \
            int m = idx >> 3, kp = idx & 7;                                    \
            cp16u(ab + m * 128 + ((kp ^ (m & 7)) << 4),                        \
                  asrc + arow0 + (size_t)m * K1 + kin + kp * 8);               \
        }                                                                      \
        _Pragma("unroll")                                                      \
        for (int j = 0; j < 8; j++) {                                          \
            int idx = tid + j * 256;                                           \
            int oc = idx >> 3, kp = idx & 7;                                   \
            cp16u(bb + oc * 128 + ((kp ^ (oc & 7)) << 4),                      \
                  bsrc + boff + (size_t)oc * K1 + kin + kp * 8);               \
        }                                                                      \
    }

    STAGE_LOAD1(0, 0);
    asm volatile("cp.async.commit_group;");

    for (int c = 0; c < NCHUNK1; c++) {
        const int b = c & 1;
        asm volatile("cp.async.wait_group 0;");
        __syncthreads();
        if (c + 1 < NCHUNK1) {
            STAGE_LOAD1(c + 1, (c + 1) & 1);
            asm volatile("cp.async.commit_group;");
        }

        const uint32_t abuf = abase + b * STAGE1_BYTES;
        const uint32_t aB = abuf + aRow * 128;
        const uint32_t bB = abuf + 16384 + bRow * 128;

#pragma unroll
        for (int ks = 0; ks < 4; ks++) {
            uint32_t a[4][4];
#pragma unroll
            for (int mi = 0; mi < 4; mi++) {
                uint32_t ad = aB + mi * 2048 + (((2 * ks + kA) ^ sA) << 4);
                asm volatile(
                    "ldmatrix.sync.aligned.m8n8.x4.shared.b16 {%0,%1,%2,%3}, [%4];"
                    : "=r"(a[mi][0]), "=r"(a[mi][1]), "=r"(a[mi][2]), "=r"(a[mi][3])
                    : "r"(ad));
            }
            uint32_t bg[8][2];
#pragma unroll
            for (int p = 0; p < 4; p++) {
                uint32_t bd = bB + p * 2048 + (((2 * ks + kB) ^ sB) << 4);
                asm volatile(
                    "ldmatrix.sync.aligned.m8n8.x4.shared.b16 {%0,%1,%2,%3}, [%4];"
                    : "=r"(bg[2 * p][0]), "=r"(bg[2 * p][1]),
                      "=r"(bg[2 * p + 1][0]), "=r"(bg[2 * p + 1][1])
                    : "r"(bd));
            }
#pragma unroll
            for (int mi = 0; mi < 4; mi++)
#pragma unroll
                for (int ni = 0; ni < 8; ni++)
                    asm volatile(
                        "mma.sync.aligned.m16n8k16.row.col.f32.bf16.bf16.f32 "
                        "{%0,%1,%2,%3}, {%4,%5,%6,%7}, {%8,%9}, {%0,%1,%2,%3};"
                        : "+f"(acc[mi][ni][0]), "+f"(acc[mi][ni][1]),
                          "+f"(acc[mi][ni][2]), "+f"(acc[mi][ni][3])
                        : "r"(a[mi][0]), "r"(a[mi][1]), "r"(a[mi][2]), "r"(a[mi][3]),
                          "r"(bg[ni][0]), "r"(bg[ni][1]));
        }
        __syncthreads();
    }
#undef STAGE_LOAD1

    // epilogue: bias + plain fp32 store into g_x1[oc][t][m]
    const int mrow = mh * 128 + wm * 64 + (lane >> 2);
    const int ncb  = nq * 256 + wn * 64 + 2 * (lane & 3);
#pragma unroll
    for (int ni = 0; ni < 8; ni++) {
        int n0 = ncb + ni * 8;
        float b0 = bias[n0], b1 = bias[n0 + 1];
        float* p0 = g_x1 + ((size_t)n0 * TT + t) * 256;
        float* p1 = g_x1 + ((size_t)(n0 + 1) * TT + t) * 256;
#pragma unroll
        for (int mi = 0; mi < 4; mi++) {
            int m0 = mrow + mi * 16;
            int m1 = m0 + 8;
            p0[m0] = acc[mi][ni][0] + b0;
            p1[m0] = acc[mi][ni][1] + b1;
            p0[m1] = acc[mi][ni][2] + b0;
            p1[m1] = acc[mi][ni][3] + b1;
        }
    }
}

// ============================================================================
// Conv2 via mma.sync bf16x3 GEMM + fused maxpool epilogue.
// Grid (t=64, nq=2). 256 thr = 8 warps (1m x 8n), warp tile 64x32.
// CTA: M=64, N=256, K=3*16384 in 768 chunks of 64.
// Epilogue: warp spans all 64 positions -> max via 3 shfl_xor, + bias -> feat.
// ============================================================================
__global__ void __launch_bounds__(256)
conv2_mma(const float* __restrict__ bias) {
    extern __shared__ __align__(128) char dsmem[];

    const int t    = blockIdx.x;
    const int nq   = blockIdx.y;
    const int tid  = threadIdx.x;
    const int warp = tid >> 5;
    const int lane = tid & 31;
    const int wn   = warp;

    const uint32_t abase = smem_u32(dsmem);

    const int aRow = ((lane >> 3) & 1) * 8 + (lane & 7);
    const int kA   = lane >> 4;
    const int sA   = aRow & 7;
    const int bRow = wn * 32 + ((lane >> 4) << 3) + (lane & 7);
    const int kB   = (lane >> 3) & 1;
    const int sB   = bRow & 7;

    float acc[4][4][4];
#pragma unroll
    for (int mi = 0; mi < 4; mi++)
#pragma unroll
        for (int ni = 0; ni < 4; ni++)
#pragma unroll
            for (int r = 0; r < 4; r++) acc[mi][ni][r] = 0.f;

    const size_t arow0 = (size_t)t * 64 * K2;
    const size_t boff  = (size_t)(nq * 256) * K2;

#define STAGE_LOAD2(CH, S)                                                     \
    {                                                                          \
        int seg = (CH) >> 8;                                                   \
        int kin = ((CH) & 255) * 64;                                           \
        const __nv_bfloat16* asrc = (seg == 1) ? g_a2l : g_a2h;                \
        const __nv_bfloat16* bsrc = (seg == 2) ? g_b2l : g_b2h;                \
        uint32_t ab = abase + (S) * STAGE2_BYTES;                              \
        uint32_t bb = ab + 8192;                                               \
        _Pragma("unroll")                                                      \
        for (int j = 0; j < 2; j++) {                                          \
            int idx = tid + j * 256;                                           \
            int m = idx >> 3, kp = idx & 7;                                    \
            cp16u(ab + m * 128 + ((kp ^ (m & 7)) << 4),                        \
                  asrc + arow0 + (size_t)m * K2 + kin + kp * 8);               \
        }                                                                      \
        _Pragma("unroll")                                                      \
        for (int j = 0; j < 8; j++) {                                          \
            int idx = tid + j * 256;                                           \
            int oc = idx >> 3, kp = idx & 7;                                   \
            cp16u(bb + oc * 128 + ((kp ^ (oc & 7)) << 4),                      \
                  bsrc + boff + (size_t)oc * K2 + kin + kp * 8);               \
        }                                                                      \
    }

    STAGE_LOAD2(0, 0);
    asm volatile("cp.async.commit_group;");

    for (int c = 0; c < NCHUNK2; c++) {
        const int b = c & 1;
        asm volatile("cp.async.wait_group 0;");
        __syncthreads();
        if (c + 1 < NCHUNK2) {
            STAGE_LOAD2(c + 1, (c + 1) & 1);
            asm volatile("cp.async.commit_group;");
        }

        const uint32_t abuf = abase + b * STAGE2_BYTES;
        const uint32_t aB = abuf + aRow * 128;
        const uint32_t bB = abuf + 8192 + bRow * 128;

#pragma unroll
        for (int ks = 0; ks < 4; ks++) {
            uint32_t a[4][4];
#pragma unroll
            for (int mi = 0; mi < 4; mi++) {
                uint32_t ad = aB + mi * 2048 + (((2 * ks + kA) ^ sA) << 4);
                asm volatile(
                    "ldmatrix.sync.aligned.m8n8.x4.shared.b16 {%0,%1,%2,%3}, [%4];"
                    : "=r"(a[mi][0]), "=r"(a[mi][1]), "=r"(a[mi][2]), "=r"(a[mi][3])
                    : "r"(ad));
            }
            uint32_t bg[4][2];
#pragma unroll
            for (int p = 0; p < 2; p++) {
                uint32_t bd = bB + p * 2048 + (((2 * ks + kB) ^ sB) << 4);
                asm volatile(
                    "ldmatrix.sync.aligned.m8n8.x4.shared.b16 {%0,%1,%2,%3}, [%4];"
                    : "=r"(bg[2 * p][0]), "=r"(bg[2 * p][1]),
                      "=r"(bg[2 * p + 1][0]), "=r"(bg[2 * p + 1][1])
                    : "r"(bd));
            }
#pragma unroll
            for (int mi = 0; mi < 4; mi++)
#pragma unroll
                for (int ni = 0; ni < 4; ni++)
                    asm volatile(
                        "mma.sync.aligned.m16n8k16.row.col.f32.bf16.bf16.f32 "
                        "{%0,%1,%2,%3}, {%4,%5,%6,%7}, {%8,%9}, {%0,%1,%2,%3};"
                        : "+f"(acc[mi][ni][0]), "+f"(acc[mi][ni][1]),
                          "+f"(acc[mi][ni][2]), "+f"(acc[mi][ni][3])
                        : "r"(a[mi][0]), "r"(a[mi][1]), "r"(a[mi][2]), "r"(a[mi][3]),
                          "r"(bg[ni][0]), "r"(bg[ni][1]));
        }
        __syncthreads();
    }
#undef STAGE_LOAD2

    // fused maxpool epilogue: max over all 64 positions, + bias -> g_feat
#pragma unroll
    for (int ni = 0; ni < 4; ni++) {
        float me = -3.4e38f, mo = -3.4e38f;
#pragma unroll
        for (int mi = 0; mi < 4; mi++) {
            me = fmaxf(me, fmaxf(acc[mi][ni][0], acc[mi][ni][2]));
            mo = fmaxf(mo, fmaxf(acc[mi][ni][1], acc[mi][ni][3]));
        }
#pragma unroll
        for (int off = 4; off < 32; off <<= 1) {
            me = fmaxf(me, __shfl_xor_sync(0xffffffffu, me, off));
            mo = fmaxf(mo, __shfl_xor_sync(0xffffffffu, mo, off));
        }
        if (lane < 4) {
            int oc = nq * 256 + wn * 32 + ni * 8 + 2 * lane;
            g_feat[oc * TT + t]       = me + bias[oc];
            g_feat[(oc + 1) * TT + t] = mo + bias[oc + 1];
        }
    }
}

// ============================================================================
// Head (unchanged, passing since R1)
// ============================================================================
__device__ __forceinline__ float iou1d(float s1, float e1, float s2, float e2) {
    float inter = fmaxf(fminf(e1, e2) - fmaxf(s1, s2), 0.f);
    float uni   = (e1 - s1) + (e2 - s2) - inter;
    return inter / fmaxf(uni, 1e-6f);
}

__global__ void __launch_bounds__(512, 1)
head_kernel(const float* __restrict__ sw, const float* __restrict__ sb,
            const float* __restrict__ dw, const float* __restrict__ db,
            const float* __restrict__ gt, const int* __restrict__ vlen,
            float* __restrict__ out) {
    __shared__ float s_sl[16 * 64], s_dl[16 * 64];
    __shared__ float s_bs[NANCH], s_be[NANCH], s_sc[NANCH];
    __shared__ float s_as[NANCH], s_ae[NANCH];
    __shared__ float s_lp0[NANCH], s_lp1[NANCH], s_dc[NANCH], s_dt[NANCH];
    __shared__ float s_gt[16];
    __shared__ int   s_best[8];
    __shared__ float r0[512], r1[512], r2[512], r3[512];

    const int tid  = threadIdx.x;
    const int wid  = tid >> 5;
    const int lane = tid & 31;
    if (tid < 16) s_gt[tid] = gt[tid];

    const int o = tid >> 6;
    const int t = tid & 63;
    {
        float a0 = sb[o], a1 = sb[o + 8], d0 = db[o], d1 = db[o + 8];
        for (int c = 0; c < C2; c++) {
            float f = g_feat[c * 64 + t];
            a0 = fmaf(sw[o * 512 + c],       f, a0);
            a1 = fmaf(sw[(o + 8) * 512 + c], f, a1);
            d0 = fmaf(dw[o * 512 + c],       f, d0);
            d1 = fmaf(dw[(o + 8) * 512 + c], f, d1);
        }
        s_sl[o * 64 + t] = a0;  s_sl[(o + 8) * 64 + t] = a1;
        s_dl[o * 64 + t] = d0;  s_dl[(o + 8) * 64 + t] = d1;
    }
    __syncthreads();

    {
        const int a = o;
        float l0 = s_sl[a * 64 + t], l1 = s_sl[(a + 8) * 64 + t];
        float mx = fmaxf(l0, l1);
        float lse = mx + logf(expf(l0 - mx) + expf(l1 - mx));
        float p1  = expf(l1 - lse);
        float dc  = s_dl[a * 64 + t], dl = s_dl[(a + 8) * 64 + t];
        float alen = (float)(8 << a);
        float ctr  = (t + 0.5f) * 8.f;
        float pc = ctr + dc * alen;
        float pl = alen * expf(fminf(fmaxf(dl, -10.f), 10.f));
        float ps = fminf(fmaxf(pc - 0.5f * pl, 0.f), 512.f);
        float pe = fminf(fmaxf(pc + 0.5f * pl, 0.f), 512.f);
        s_bs[tid] = ps;  s_be[tid] = pe;
        s_sc[tid] = (pe - ps >= 4.f) ? p1 : -1.0e9f;
        s_as[tid] = ctr - 0.5f * alen;
        s_ae[tid] = ctr + 0.5f * alen;
        s_lp0[tid] = l0 - lse;  s_lp1[tid] = l1 - lse;
        s_dc[tid] = dc;  s_dt[tid] = dl;
    }
    __syncthreads();

    if (wid < 8) {
        float gs = s_gt[wid * 2], ge = s_gt[wid * 2 + 1];
        float bv = -3.4e38f; int bi = 0x7fffffff;
        for (int k = 0; k < 16; k++) {
            int n = lane + 32 * k;
            float v = iou1d(s_as[n], s_ae[n], gs, ge);
            if (v > bv) { bv = v; bi = n; }
        }
        for (int off = 16; off; off >>= 1) {
            float ov = __shfl_xor_sync(0xffffffffu, bv, off);
            int   oi = __shfl_xor_sync(0xffffffffu, bi, off);
            if (ov > bv || (ov == bv && oi < bi)) { bv = ov; bi = oi; }
        }
        if (lane == 0) s_best[wid] = bi;
    }
    __syncthreads();

    {
        float myas = s_as[tid], myae = s_ae[tid];
        float miou = -1.f; int ag = 0;
#pragma unroll
        for (int g = 0; g < 8; g++) {
            float v = iou1d(myas, myae, s_gt[2 * g], s_gt[2 * g + 1]);
            if (v > miou) { miou = v; ag = g; }
        }
        int lab = (miou < 0.3f) ? 0 : -1;
        if (miou >= 0.7f) lab = 1;
#pragma unroll
        for (int g = 0; g < 8; g++)
            if (s_best[g] == tid) lab = 1;
        float vl = (float)vlen[0];
        if (!(myas >= 0.f && myae <= vl)) lab = -1;

        float gs = s_gt[2 * ag], ge = s_gt[2 * ag + 1];
        float gc = 0.5f * (gs + ge);
        float gl = fmaxf(ge - gs, 1e-6f);
        float ac = 0.5f * (myas + myae);
        float al = myae - myas;
        float rl0 = (gc - ac) / al;
        float rl1 = logf(gl / al);
        float d0 = s_dc[tid] - rl0, d1 = s_dt[tid] - rl1;
        float sl1 = (fabsf(d0) < 1.f ? 0.5f * d0 * d0 : fabsf(d0) - 0.5f)
                  + (fabsf(d1) < 1.f ? 0.5f * d1 * d1 : fabsf(d1) - 0.5f);
        float maskv = (lab >= 0) ? 1.f : 0.f;
        float posv  = (lab == 1) ? 1.f : 0.f;
        float nll   = -((lab == 1) ? s_lp1[tid] : s_lp0[tid]);
        r0[tid] = nll * maskv;  r1[tid] = maskv;
        r2[tid] = sl1 * posv;   r3[tid] = posv;
    }
    __syncthreads();
    for (int s = 256; s > 0; s >>= 1) {
        if (tid < s) {
            r0[tid] += r0[tid + s];  r1[tid] += r1[tid + s];
            r2[tid] += r2[tid + s];  r3[tid] += r3[tid + s];
        }
        __syncthreads();
    }
    if (tid == 0) {
        out[300] = r0[0] / fmaxf(r1[0], 1.f);
        out[301] = r2[0] / fmaxf(r3[0], 1.f);
    }
    __syncthreads();

    if (wid == 0) {
        for (int it = 0; it < 100; it++) {
            float bv = -3.4e38f; int bi = 0x7fffffff;
#pragma unroll
            for (int k = 0; k < 16; k++) {
                int n = lane + 32 * k;
                float v = s_sc[n];
                if (v > bv) { bv = v; bi = n; }
            }
            for (int off = 16; off; off >>= 1) {
                float ov = __shfl_xor_sync(0xffffffffu, bv, off);
                int   oi = __shfl_xor_sync(0xffffffffu, bi, off);
                if (ov > bv || (ov == bv && oi < bi)) { bv = ov; bi = oi; }
            }
            float kb0 = s_bs[bi], kb1 = s_be[bi];
            bool keep = bv > -5.0e8f;
            if (lane == 0) {
                out[2 * it]     = keep ? kb0 : 0.f;
                out[2 * it + 1] = keep ? kb1 : 0.f;
                out[200 + it]   = keep ? bv  : 0.f;
            }
#pragma unroll
            for (int k = 0; k < 16; k++) {
                int n = lane + 32 * k;
                float v = iou1d(kb0, kb1, s_bs[n], s_be[n]);
                if (v > 0.7f || n == bi) s_sc[n] = -1.0e9f;
            }
            __syncwarp();
        }
    }
}

// ============================================================================
extern "C" void kernel_launch(void* const* d_in, const int* in_sizes, int n_in,
                              void* d_out, int out_size) {
    const float* base = (const float*)d_in[0];
    const float* gt   = (const float*)d_in[1];
    const int*   vl   = (const int*)d_in[2];
    const float* c1w  = (const float*)d_in[3];
    const float* c1b  = (const float*)d_in[4];
    const float* c2w  = (const float*)d_in[5];
    const float* c2b  = (const float*)d_in[6];
    const float* sw   = (const float*)d_in[7];
    const float* sb   = (const float*)d_in[8];
    const float* dw   = (const float*)d_in[9];
    const float* db   = (const float*)d_in[10];
    float* out = (float*)d_out;

    static int attr_set = 0;
    if (!attr_set) {
        cudaFuncSetAttribute(conv1_mma,
                             cudaFuncAttributeMaxDynamicSharedMemorySize, C1MMA_SMEM);
        cudaFuncSetAttribute(conv2_mma,
                             cudaFuncAttributeMaxDynamicSharedMemorySize, C2MMA_SMEM);
        attr_set = 1;
    }

    split_w1<<<512, 256>>>(c1w);
    split_w2<<<512, 256>>>(c2w);
    im2col1<<<dim3(64, 256), 256>>>(base);
    conv1_mma<<<dim3(64, 2, 2), 256, C1MMA_SMEM>>>(c1b);
    im2col2<<<dim3(64, 8), 256>>>();
    conv2_mma<<<dim3(64, 2), 256, C2MMA_SMEM>>>(c2b);
    head_kernel<<<1, 512>>>(sw, sb, dw, db, gt, vl, out);
}

// round 8
// speedup vs baseline: 4.5438x; 1.0058x over previous
#include <cuda_runtime.h>
#include <cuda_bf16.h>
#include <cstdint>

typedef unsigned long long ull;

// ---------------- problem constants ----------------
#define CIN   256
#define TT    64
#define HIN   32
#define WIN   32
#define C1    512
#define C2    512
#define NANCH 512

// conv1 GEMM: K1 = 256 ic * 27 taps
#define K1      6912
#define NCHUNK1 324            // 3 segments * 108 chunks of 64
#define STAGE1_BYTES 49152     // A 16KB + B 32KB
#define C1MMA_SMEM  (3 * STAGE1_BYTES)

// conv2 GEMM: K2 = 512 ic * 32 padded taps (27 real + 5 zero)
#define K2      16384
#define NCHUNK2 768            // 3 segments * 256 chunks of 64
#define STAGE2_BYTES 40960     // A 8KB + B 32KB
#define C2MMA_SMEM  (3 * STAGE2_BYTES)

// ---------------- device scratch ----------------
__device__ __align__(16) __nv_bfloat16 g_a1h[(size_t)64 * 256 * K1];  // 226 MB
__device__ __align__(16) __nv_bfloat16 g_a1l[(size_t)64 * 256 * K1];  // 226 MB
__device__ __align__(16) __nv_bfloat16 g_b1h[(size_t)C1 * K1];        //   7 MB
__device__ __align__(16) __nv_bfloat16 g_b1l[(size_t)C1 * K1];        //   7 MB
__device__ float g_x1[(size_t)C1 * TT * 256];                          //  33 MB
__device__ __align__(16) __nv_bfloat16 g_a2h[(size_t)64 * 64 * K2];   // 134 MB
__device__ __align__(16) __nv_bfloat16 g_a2l[(size_t)64 * 64 * K2];   // 134 MB
__device__ __align__(16) __nv_bfloat16 g_b2h[(size_t)C2 * K2];        //  17 MB
__device__ __align__(16) __nv_bfloat16 g_b2l[(size_t)C2 * K2];        //  17 MB
__device__ float g_feat[C2 * TT];

// ---------------- helpers ----------------
__device__ __forceinline__ void cp16u(unsigned dst, const void* src) {
    asm volatile("cp.async.cg.shared.global [%0], [%1], 16;" :: "r"(dst), "l"(src));
}
__device__ __forceinline__ uint32_t smem_u32(const void* p) {
    return (uint32_t)__cvta_generic_to_shared(p);
}
__device__ __forceinline__ unsigned pack_bf2(float a, float b) {
    __nv_bfloat162 p = __floats2bfloat162_rn(a, b);
    return *reinterpret_cast<unsigned*>(&p);
}

// ============================================================================
// Prepass: split conv1 weights into bf16 hi/lo  (k = ic*27+tap natural order)
// ============================================================================
__global__ void split_w1(const float* __restrict__ w) {
    int oc = blockIdx.x;
    const float* src = w + (size_t)oc * K1;
    __nv_bfloat16* dh = g_b1h + (size_t)oc * K1;
    __nv_bfloat16* dl = g_b1l + (size_t)oc * K1;
    for (int k = threadIdx.x; k < K1; k += 256) {
        float v = src[k];
        __nv_bfloat16 hi = __float2bfloat16(v);
        dh[k] = hi;
        dl[k] = __float2bfloat16(v - __bfloat162float(hi));
    }
}

// ============================================================================
// Prepass: split conv2 weights -> [oc][ic*32+tap] padded order, hi/lo
// ============================================================================
__global__ void split_w2(const float* __restrict__ w) {
    int oc = blockIdx.x;
    const float* src = w + (size_t)oc * (512 * 27);
    __nv_bfloat16* dh = g_b2h + (size_t)oc * K2;
    __nv_bfloat16* dl = g_b2l + (size_t)oc * K2;
#pragma unroll 4
    for (int j = 0; j < 64; j++) {
        int k = threadIdx.x + j * 256;
        int ic = k >> 5, tap = k & 31;
        float v = (tap < 27) ? src[ic * 27 + tap] : 0.f;
        __nv_bfloat16 hi = __float2bfloat16(v);
        dh[k] = hi;
        dl[k] = __float2bfloat16(v - __bfloat162float(hi));
    }
}

// ============================================================================
// Prepass: im2col + split of input -> A1 [t][m(256)][k(6912)] hi/lo bf16
// ============================================================================
__global__ void im2col1(const float* __restrict__ in) {
    const int t = blockIdx.x;
    const int m = blockIdx.y;
    const int h = m >> 4, w = m & 15;
    __nv_bfloat16* dh = g_a1h + ((size_t)t * 256 + m) * K1;
    __nv_bfloat16* dl = g_a1l + ((size_t)t * 256 + m) * K1;
#pragma unroll
    for (int j = 0; j < 27; j++) {
        int k   = threadIdx.x + j * 256;
        int ic  = k / 27;
        int tap = k - ic * 27;
        int kd = tap / 9, r = tap - kd * 9, kh = r / 3, kw = r - kh * 3;
        int ti = t + kd - 1, hh = 2 * h + kh - 1, ww = 2 * w + kw - 1;
        float v = 0.f;
        if (ti >= 0 && ti < TT && hh >= 0 && hh < HIN && ww >= 0 && ww < WIN)
            v = in[((size_t)(ic * TT + ti) * HIN + hh) * WIN + ww];
        __nv_bfloat16 hi = __float2bfloat16(v);
        dh[k] = hi;
        dl[k] = __float2bfloat16(v - __bfloat162float(hi));
    }
}

// ============================================================================
// im2col2: g_x1 fp32 -> A2 [t*64+m][ic*32+tap] hi/lo bf16 (padded taps zero)
// ============================================================================
__global__ void __launch_bounds__(256)
im2col2() {
    __shared__ float sm[4][3][256];
    const int t   = blockIdx.x;
    const int ic0 = blockIdx.y * 64;
    const int tid = threadIdx.x;
    const int icq = tid >> 6;
    const int m   = tid & 63;
    const int h   = m >> 3, w = m & 7;

    for (int it = 0; it < 16; it++) {
        const int icb = ic0 + it * 4;
        __syncthreads();
#pragma unroll
        for (int icq2 = 0; icq2 < 4; icq2++)
#pragma unroll
            for (int kd = 0; kd < 3; kd++) {
                int ti = t + kd - 1;
                sm[icq2][kd][tid & 255] = 0.f;
                if (ti >= 0 && ti < TT && tid < 256)
                    sm[icq2][kd][tid] =
                        g_x1[((size_t)(icb + icq2) * TT + ti) * 256 + tid];
            }
        __syncthreads();

        float v[32];
#pragma unroll
        for (int tap = 0; tap < 27; tap++) {
            const int kd = tap / 9, rr = tap - kd * 9;
            const int kh = rr / 3, kw = rr - kh * 3;
            int hh = 2 * h + kh - 1, ww = 2 * w + kw - 1;
            v[tap] = (hh >= 0 && ww >= 0) ? sm[icq][kd][hh * 16 + ww] : 0.f;
        }
#pragma unroll
        for (int tap = 27; tap < 32; tap++) v[tap] = 0.f;

        unsigned uh[16], ul[16];
#pragma unroll
        for (int p = 0; p < 16; p++) {
            float a = v[2 * p], b = v[2 * p + 1];
            uh[p] = pack_bf2(a, b);
            float ah = __bfloat162float(__float2bfloat16(a));
            float bh = __bfloat162float(__float2bfloat16(b));
            ul[p] = pack_bf2(a - ah, b - bh);
        }
        const size_t row = ((size_t)t * 64 + m) * K2 + (size_t)(icb + icq) * 32;
        uint4* dh = (uint4*)(g_a2h + row);
        uint4* dl = (uint4*)(g_a2l + row);
        dh[0] = make_uint4(uh[0], uh[1], uh[2], uh[3]);
        dh[1] = make_uint4(uh[4], uh[5], uh[6], uh[7]);
        dh[2] = make_uint4(uh[8], uh[9], uh[10], uh[11]);
        dh[3] = make_uint4(uh[12], uh[13], uh[14], uh[15]);
        dl[0] = make_uint4(ul[0], ul[1], ul[2], ul[3]);
        dl[1] = make_uint4(ul[4], ul[5], ul[6], ul[7]);
        dl[2] = make_uint4(ul[8], ul[9], ul[10], ul[11]);
        dl[3] = make_uint4(ul[12], ul[13], ul[14], ul[15]);
    }
}

// ============================================================================
// Conv1 via mma.sync bf16x3 GEMM, 3-stage cp.async pipeline.
// Grid (t=64, mh=2, nq=2). 256 thr = 8 warps (2m x 4n), warp tile 64x64.
// ============================================================================
__global__ void __launch_bounds__(256)
conv1_mma(const float* __restrict__ bias) {
    extern __shared__ __align__(128) char dsmem[];

    const int t    = blockIdx.x;
    const int mh   = blockIdx.y;
    const int nq   = blockIdx.z;
    const int tid  = threadIdx.x;
    const int warp = tid >> 5;
    const int lane = tid & 31;
    const int wm   = warp >> 2;
    const int wn   = warp & 3;

    const uint32_t abase = smem_u32(dsmem);

    const int aRow = wm * 64 + ((lane >> 3) & 1) * 8 + (lane & 7);
    const int kA   = lane >> 4;
    const int sA   = aRow & 7;
    const int bRow = wn * 64 + ((lane >> 4) << 3) + (lane & 7);
    const int kB   = (lane >> 3) & 1;
    const int sB   = bRow & 7;

    float acc[4][8][4];
#pragma unroll
    for (int mi = 0; mi < 4; mi++)
#pragma unroll
        for (int ni = 0; ni < 8; ni++)
#pragma unroll
            for (int r = 0; r < 4; r++) acc[mi][ni][r] = 0.f;

    const size_t arow0 = ((size_t)t * 256 + mh * 128) * K1;
    const size_t boff  = (size_t)(nq * 256) * K1;

#define STAGE_LOAD1(CH, S)                                                     \
    {                                                                          \
        int seg = (CH) / 108;                                                  \
        int kin = ((CH) - seg * 108) * 64;                                     \
        const __nv_bfloat16* asrc = (seg == 1) ? g_a1l : g_a1h;                \
        const __nv_bfloat16* bsrc = (seg == 2) ? g_b1l : g_b1h;                \
        uint32_t ab = abase + (S) * STAGE1_BYTES;                              \
        uint32_t bb = ab + 16384;                                              \
        _Pragma("unroll")                                                      \
        for (int j = 0; j < 4; j++) {                                          \
            int idx = tid + j * 256;                                           \
            int m = idx >> 3, kp = idx & 7;                                    \
            cp16u(ab + m * 128 + ((kp ^ (m & 7)) << 4),                        \
                  asrc + arow0 + (size_t)m * K1 + kin + kp * 8);               \
        }                                                                      \
        _Pragma("unroll")                                                      \
        for (int j = 0; j < 8; j++) {                                          \
            int idx = tid + j * 256;                                           \
            int oc = idx >> 3, kp = idx & 7;                                   \
            cp16u(bb + oc * 128 + ((kp ^ (oc & 7)) << 4),                      \
                  bsrc + boff + (size_t)oc * K1 + kin + kp * 8);               \
        }                                                                      \
    }

    STAGE_LOAD1(0, 0);
    asm volatile("cp.async.commit_group;");
    STAGE_LOAD1(1, 1);
    asm volatile("cp.async.commit_group;");

    int sc = 0;   // buffer index of chunk c
    for (int c = 0; c < NCHUNK1; c++) {
        if (c + 1 < NCHUNK1) asm volatile("cp.async.wait_group 1;");
        else                 asm volatile("cp.async.wait_group 0;");
        __syncthreads();
        if (c + 2 < NCHUNK1) {
            int sn = sc + 2; if (sn >= 3) sn -= 3;
            STAGE_LOAD1(c + 2, sn);
            asm volatile("cp.async.commit_group;");
        }

        const uint32_t abuf = abase + sc * STAGE1_BYTES;
        const uint32_t aB = abuf + aRow * 128;
        const uint32_t bB = abuf + 16384 + bRow * 128;

#pragma unroll
        for (int ks = 0; ks < 4; ks++) {
            uint32_t a[4][4];
#pragma unroll
            for (int mi = 0; mi < 4; mi++) {
                uint32_t ad = aB + mi * 2048 + (((2 * ks + kA) ^ sA) << 4);
                asm volatile(
                    "ldmatrix.sync.aligned.m8n8.x4.shared.b16 {%0,%1,%2,%3}, [%4];"
                    : "=r"(a[mi][0]), "=r"(a[mi][1]), "=r"(a[mi][2]), "=r"(a[mi][3])
                    : "r"(ad));
            }
            uint32_t bg[8][2];
#pragma unroll
            for (int p = 0; p < 4; p++) {
                uint32_t bd = bB + p * 2048 + (((2 * ks + kB) ^ sB) << 4);
                asm volatile(
                    "ldmatrix.sync.aligned.m8n8.x4.shared.b16 {%0,%1,%2,%3}, [%4];"
                    : "=r"(bg[2 * p][0]), "=r"(bg[2 * p][1]),
                      "=r"(bg[2 * p + 1][0]), "=r"(bg[2 * p + 1][1])
                    : "r"(bd));
            }
#pragma unroll
            for (int mi = 0; mi < 4; mi++)
#pragma unroll
                for (int ni = 0; ni < 8; ni++)
                    asm volatile(
                        "mma.sync.aligned.m16n8k16.row.col.f32.bf16.bf16.f32 "
                        "{%0,%1,%2,%3}, {%4,%5,%6,%7}, {%8,%9}, {%0,%1,%2,%3};"
                        : "+f"(acc[mi][ni][0]), "+f"(acc[mi][ni][1]),
                          "+f"(acc[mi][ni][2]), "+f"(acc[mi][ni][3])
                        : "r"(a[mi][0]), "r"(a[mi][1]), "r"(a[mi][2]), "r"(a[mi][3]),
                          "r"(bg[ni][0]), "r"(bg[ni][1]));
        }
        __syncthreads();
        if (++sc == 3) sc = 0;
    }
#undef STAGE_LOAD1

    const int mrow = mh * 128 + wm * 64 + (lane >> 2);
    const int ncb  = nq * 256 + wn * 64 + 2 * (lane & 3);
#pragma unroll
    for (int ni = 0; ni < 8; ni++) {
        int n0 = ncb + ni * 8;
        float b0 = bias[n0], b1 = bias[n0 + 1];
        float* p0 = g_x1 + ((size_t)n0 * TT + t) * 256;
        float* p1 = g_x1 + ((size_t)(n0 + 1) * TT + t) * 256;
#pragma unroll
        for (int mi = 0; mi < 4; mi++) {
            int m0 = mrow + mi * 16;
            int m1 = m0 + 8;
            p0[m0] = acc[mi][ni][0] + b0;
            p1[m0] = acc[mi][ni][1] + b1;
            p0[m1] = acc[mi][ni][2] + b0;
            p1[m1] = acc[mi][ni][3] + b1;
        }
    }
}

// ============================================================================
// Conv2 via mma.sync bf16x3 GEMM + fused maxpool, 3-stage pipeline.
// Grid (t=64, nq=2). 256 thr = 8 warps (1m x 8n), warp tile 64x32.
// ============================================================================
__global__ void __launch_bounds__(256)
conv2_mma(const float* __restrict__ bias) {
    extern __shared__ __align__(128) char dsmem[];

    const int t    = blockIdx.x;
    const int nq   = blockIdx.y;
    const int tid  = threadIdx.x;
    const int warp = tid >> 5;
    const int lane = tid & 31;
    const int wn   = warp;

    const uint32_t abase = smem_u32(dsmem);

    const int aRow = ((lane >> 3) & 1) * 8 + (lane & 7);
    const int kA   = lane >> 4;
    const int sA   = aRow & 7;
    const int bRow = wn * 32 + ((lane >> 4) << 3) + (lane & 7);
    const int kB   = (lane >> 3) & 1;
    const int sB   = bRow & 7;

    float acc[4][4][4];
#pragma unroll
    for (int mi = 0; mi < 4; mi++)
#pragma unroll
        for (int ni = 0; ni < 4; ni++)
#pragma unroll
            for (int r = 0; r < 4; r++) acc[mi][ni][r] = 0.f;

    const size_t arow0 = (size_t)t * 64 * K2;
    const size_t boff  = (size_t)(nq * 256) * K2;

#define STAGE_LOAD2(CH, S)                                                     \
    {                                                                          \
        int seg = (CH) >> 8;                                                   \
        int kin = ((CH) & 255) * 64;                                           \
        const __nv_bfloat16* asrc = (seg == 1) ? g_a2l : g_a2h;                \
        const __nv_bfloat16* bsrc = (seg == 2) ? g_b2l : g_b2h;                \
        uint32_t ab = abase + (S) * STAGE2_BYTES;                              \
        uint32_t bb = ab + 8192;                                               \
        _Pragma("unroll")                                                      \
        for (int j = 0; j < 2; j++) {                                          \
            int idx = tid + j * 256;                                           \
            int m = idx >> 3, kp = idx & 7;                                    \
            cp16u(ab + m * 128 + ((kp ^ (m & 7)) << 4),                        \
                  asrc + arow0 + (size_t)m * K2 + kin + kp * 8);               \
        }                                                                      \
        _Pragma("unroll")                                                      \
        for (int j = 0; j < 8; j++) {                                          \
            int idx = tid + j * 256;                                           \
            int oc = idx >> 3, kp = idx & 7;                                   \
            cp16u(bb + oc * 128 + ((kp ^ (oc & 7)) << 4),                      \
                  bsrc + boff + (size_t)oc * K2 + kin + kp * 8);               \
        }                                                                      \
    }

    STAGE_LOAD2(0, 0);
    asm volatile("cp.async.commit_group;");
    STAGE_LOAD2(1, 1);
    asm volatile("cp.async.commit_group;");

    int sc = 0;
    for (int c = 0; c < NCHUNK2; c++) {
        if (c + 1 < NCHUNK2) asm volatile("cp.async.wait_group 1;");
        else                 asm volatile("cp.async.wait_group 0;");
        __syncthreads();
        if (c + 2 < NCHUNK2) {
            int sn = sc + 2; if (sn >= 3) sn -= 3;
            STAGE_LOAD2(c + 2, sn);
            asm volatile("cp.async.commit_group;");
        }

        const uint32_t abuf = abase + sc * STAGE2_BYTES;
        const uint32_t aB = abuf + aRow * 128;
        const uint32_t bB = abuf + 8192 + bRow * 128;

#pragma unroll
        for (int ks = 0; ks < 4; ks++) {
            uint32_t a[4][4];
#pragma unroll
            for (int mi = 0; mi < 4; mi++) {
                uint32_t ad = aB + mi * 2048 + (((2 * ks + kA) ^ sA) << 4);
                asm volatile(
                    "ldmatrix.sync.aligned.m8n8.x4.shared.b16 {%0,%1,%2,%3}, [%4];"
                    : "=r"(a[mi][0]), "=r"(a[mi][1]), "=r"(a[mi][2]), "=r"(a[mi][3])
                    : "r"(ad));
            }
            uint32_t bg[4][2];
#pragma unroll
            for (int p = 0; p < 2; p++) {
                uint32_t bd = bB + p * 2048 + (((2 * ks + kB) ^ sB) << 4);
                asm volatile(
                    "ldmatrix.sync.aligned.m8n8.x4.shared.b16 {%0,%1,%2,%3}, [%4];"
                    : "=r"(bg[2 * p][0]), "=r"(bg[2 * p][1]),
                      "=r"(bg[2 * p + 1][0]), "=r"(bg[2 * p + 1][1])
                    : "r"(bd));
            }
#pragma unroll
            for (int mi = 0; mi < 4; mi++)
#pragma unroll
                for (int ni = 0; ni < 4; ni++)
                    asm volatile(
                        "mma.sync.aligned.m16n8k16.row.col.f32.bf16.bf16.f32 "
                        "{%0,%1,%2,%3}, {%4,%5,%6,%7}, {%8,%9}, {%0,%1,%2,%3};"
                        : "+f"(acc[mi][ni][0]), "+f"(acc[mi][ni][1]),
                          "+f"(acc[mi][ni][2]), "+f"(acc[mi][ni][3])
                        : "r"(a[mi][0]), "r"(a[mi][1]), "r"(a[mi][2]), "r"(a[mi][3]),
                          "r"(bg[ni][0]), "r"(bg[ni][1]));
        }
        __syncthreads();
        if (++sc == 3) sc = 0;
    }
#undef STAGE_LOAD2

#pragma unroll
    for (int ni = 0; ni < 4; ni++) {
        float me = -3.4e38f, mo = -3.4e38f;
#pragma unroll
        for (int mi = 0; mi < 4; mi++) {
            me = fmaxf(me, fmaxf(acc[mi][ni][0], acc[mi][ni][2]));
            mo = fmaxf(mo, fmaxf(acc[mi][ni][1], acc[mi][ni][3]));
        }
#pragma unroll
        for (int off = 4; off < 32; off <<= 1) {
            me = fmaxf(me, __shfl_xor_sync(0xffffffffu, me, off));
            mo = fmaxf(mo, __shfl_xor_sync(0xffffffffu, mo, off));
        }
        if (lane < 4) {
            int oc = nq * 256 + wn * 32 + ni * 8 + 2 * lane;
            g_feat[oc * TT + t]       = me + bias[oc];
            g_feat[(oc + 1) * TT + t] = mo + bias[oc + 1];
        }
    }
}

// ============================================================================
// Head (unchanged, passing since R1)
// ============================================================================
__device__ __forceinline__ float iou1d(float s1, float e1, float s2, float e2) {
    float inter = fmaxf(fminf(e1, e2) - fmaxf(s1, s2), 0.f);
    float uni   = (e1 - s1) + (e2 - s2) - inter;
    return inter / fmaxf(uni, 1e-6f);
}

__global__ void __launch_bounds__(512, 1)
head_kernel(const float* __restrict__ sw, const float* __restrict__ sb,
            const float* __restrict__ dw, const float* __restrict__ db,
            const float* __restrict__ gt, const int* __restrict__ vlen,
            float* __restrict__ out) {
    __shared__ float s_sl[16 * 64], s_dl[16 * 64];
    __shared__ float s_bs[NANCH], s_be[NANCH], s_sc[NANCH];
    __shared__ float s_as[NANCH], s_ae[NANCH];
    __shared__ float s_lp0[NANCH], s_lp1[NANCH], s_dc[NANCH], s_dt[NANCH];
    __shared__ float s_gt[16];
    __shared__ int   s_best[8];
    __shared__ float r0[512], r1[512], r2[512], r3[512];

    const int tid  = threadIdx.x;
    const int wid  = tid >> 5;
    const int lane = tid & 31;
    if (tid < 16) s_gt[tid] = gt[tid];

    const int o = tid >> 6;
    const int t = tid & 63;
    {
        float a0 = sb[o], a1 = sb[o + 8], d0 = db[o], d1 = db[o + 8];
        for (int c = 0; c < C2; c++) {
            float f = g_feat[c * 64 + t];
            a0 = fmaf(sw[o * 512 + c],       f, a0);
            a1 = fmaf(sw[(o + 8) * 512 + c], f, a1);
            d0 = fmaf(dw[o * 512 + c],       f, d0);
            d1 = fmaf(dw[(o + 8) * 512 + c], f, d1);
        }
        s_sl[o * 64 + t] = a0;  s_sl[(o + 8) * 64 + t] = a1;
        s_dl[o * 64 + t] = d0;  s_dl[(o + 8) * 64 + t] = d1;
    }
    __syncthreads();

    {
        const int a = o;
        float l0 = s_sl[a * 64 + t], l1 = s_sl[(a + 8) * 64 + t];
        float mx = fmaxf(l0, l1);
        float lse = mx + logf(expf(l0 - mx) + expf(l1 - mx));
        float p1  = expf(l1 - lse);
        float dc  = s_dl[a * 64 + t], dl = s_dl[(a + 8) * 64 + t];
        float alen = (float)(8 << a);
        float ctr  = (t + 0.5f) * 8.f;
        float pc = ctr + dc * alen;
        float pl = alen * expf(fminf(fmaxf(dl, -10.f), 10.f));
        float ps = fminf(fmaxf(pc - 0.5f * pl, 0.f), 512.f);
        float pe = fminf(fmaxf(pc + 0.5f * pl, 0.f), 512.f);
        s_bs[tid] = ps;  s_be[tid] = pe;
        s_sc[tid] = (pe - ps >= 4.f) ? p1 : -1.0e9f;
        s_as[tid] = ctr - 0.5f * alen;
        s_ae[tid] = ctr + 0.5f * alen;
        s_lp0[tid] = l0 - lse;  s_lp1[tid] = l1 - lse;
        s_dc[tid] = dc;  s_dt[tid] = dl;
    }
    __syncthreads();

    if (wid < 8) {
        float gs = s_gt[wid * 2], ge = s_gt[wid * 2 + 1];
        float bv = -3.4e38f; int bi = 0x7fffffff;
        for (int k = 0; k < 16; k++) {
            int n = lane + 32 * k;
            float v = iou1d(s_as[n], s_ae[n], gs, ge);
            if (v > bv) { bv = v; bi = n; }
        }
        for (int off = 16; off; off >>= 1) {
            float ov = __shfl_xor_sync(0xffffffffu, bv, off);
            int   oi = __shfl_xor_sync(0xffffffffu, bi, off);
            if (ov > bv || (ov == bv && oi < bi)) { bv = ov; bi = oi; }
        }
        if (lane == 0) s_best[wid] = bi;
    }
    __syncthreads();

    {
        float myas = s_as[tid], myae = s_ae[tid];
        float miou = -1.f; int ag = 0;
#pragma unroll
        for (int g = 0; g < 8; g++) {
            float v = iou1d(myas, myae, s_gt[2 * g], s_gt[2 * g + 1]);
            if (v > miou) { miou = v; ag = g; }
        }
        int lab = (miou < 0.3f) ? 0 : -1;
        if (miou >= 0.7f) lab = 1;
#pragma unroll
        for (int g = 0; g < 8; g++)
            if (s_best[g] == tid) lab = 1;
        float vl = (float)vlen[0];
        if (!(myas >= 0.f && myae <= vl)) lab = -1;

        float gs = s_gt[2 * ag], ge = s_gt[2 * ag + 1];
        float gc = 0.5f * (gs + ge);
        float gl = fmaxf(ge - gs, 1e-6f);
        float ac = 0.5f * (myas + myae);
        float al = myae - myas;
        float rl0 = (gc - ac) / al;
        float rl1 = logf(gl / al);
        float d0 = s_dc[tid] - rl0, d1 = s_dt[tid] - rl1;
        float sl1 = (fabsf(d0) < 1.f ? 0.5f * d0 * d0 : fabsf(d0) - 0.5f)
                  + (fabsf(d1) < 1.f ? 0.5f * d1 * d1 : fabsf(d1) - 0.5f);
        float maskv = (lab >= 0) ? 1.f : 0.f;
        float posv  = (lab == 1) ? 1.f : 0.f;
        float nll   = -((lab == 1) ? s_lp1[tid] : s_lp0[tid]);
        r0[tid] = nll * maskv;  r1[tid] = maskv;
        r2[tid] = sl1 * posv;   r3[tid] = posv;
    }
    __syncthreads();
    for (int s = 256; s > 0; s >>= 1) {
        if (tid < s) {
            r0[tid] += r0[tid + s];  r1[tid] += r1[tid + s];
            r2[tid] += r2[tid + s];  r3[tid] += r3[tid + s];
        }
        __syncthreads();
    }
    if (tid == 0) {
        out[300] = r0[0] / fmaxf(r1[0], 1.f);
        out[301] = r2[0] / fmaxf(r3[0], 1.f);
    }
    __syncthreads();

    if (wid == 0) {
        for (int it = 0; it < 100; it++) {
            float bv = -3.4e38f; int bi = 0x7fffffff;
#pragma unroll
            for (int k = 0; k < 16; k++) {
                int n = lane + 32 * k;
                float v = s_sc[n];
                if (v > bv) { bv = v; bi = n; }
            }
            for (int off = 16; off; off >>= 1) {
                float ov = __shfl_xor_sync(0xffffffffu, bv, off);
                int   oi = __shfl_xor_sync(0xffffffffu, bi, off);
                if (ov > bv || (ov == bv && oi < bi)) { bv = ov; bi = oi; }
            }
            float kb0 = s_bs[bi], kb1 = s_be[bi];
            bool keep = bv > -5.0e8f;
            if (lane == 0) {
                out[2 * it]     = keep ? kb0 : 0.f;
                out[2 * it + 1] = keep ? kb1 : 0.f;
                out[200 + it]   = keep ? bv  : 0.f;
            }
#pragma unroll
            for (int k = 0; k < 16; k++) {
                int n = lane + 32 * k;
                float v = iou1d(kb0, kb1, s_bs[n], s_be[n]);
                if (v > 0.7f || n == bi) s_sc[n] = -1.0e9f;
            }
            __syncwarp();
        }
    }
}

// ============================================================================
extern "C" void kernel_launch(void* const* d_in, const int* in_sizes, int n_in,
                              void* d_out, int out_size) {
    const float* base = (const float*)d_in[0];
    const float* gt   = (const float*)d_in[1];
    const int*   vl   = (const int*)d_in[2];
    const float* c1w  = (const float*)d_in[3];
    const float* c1b  = (const float*)d_in[4];
    const float* c2w  = (const float*)d_in[5];
    const float* c2b  = (const float*)d_in[6];
    const float* sw   = (const float*)d_in[7];
    const float* sb   = (const float*)d_in[8];
    const float* dw   = (const float*)d_in[9];
    const float* db   = (const float*)d_in[10];
    float* out = (float*)d_out;

    static int attr_set = 0;
    if (!attr_set) {
        cudaFuncSetAttribute(conv1_mma,
                             cudaFuncAttributeMaxDynamicSharedMemorySize, C1MMA_SMEM);
        cudaFuncSetAttribute(conv2_mma,
                             cudaFuncAttributeMaxDynamicSharedMemorySize, C2MMA_SMEM);
        attr_set = 1;
    }

    split_w1<<<512, 256>>>(c1w);
    split_w2<<<512, 256>>>(c2w);
    im2col1<<<dim3(64, 256), 256>>>(base);
    conv1_mma<<<dim3(64, 2, 2), 256, C1MMA_SMEM>>>(c1b);
    im2col2<<<dim3(64, 8), 256>>>();
    conv2_mma<<<dim3(64, 2), 256, C2MMA_SMEM>>>(c2b);
    head_kernel<<<1, 512>>>(sw, sb, dw, db, gt, vl, out);
}

// round 9
// speedup vs baseline: 5.4113x; 1.1909x over previous
#include <cuda_runtime.h>
#include <cuda_bf16.h>
#include <cstdint>

typedef unsigned long long ull;

// ---------------- problem constants ----------------
#define CIN   256
#define TT    64
#define HIN   32
#define WIN   32
#define C1    512
#define C2    512
#define NANCH 512

// conv1 GEMM: K1 = 256 ic * 27 taps
#define K1      6912
#define NCHUNK1 324            // 3 segments * 108 chunks of 64
#define STAGE1_BYTES 40960     // A 8KB + B 32KB
#define C1MMA_SMEM  (2 * STAGE1_BYTES)   // 80KB, 2 CTAs/SM

// conv2 GEMM: K2 = 512 ic * 32 padded taps (27 real + 5 zero)
#define K2      16384
#define NCHUNK2 768            // 3 segments * 256 chunks of 64
#define STAGE2_BYTES 24576     // A 8KB + B 16KB
#define C2MMA_SMEM  (3 * STAGE2_BYTES)   // 72KB, 2 CTAs/SM

// ---------------- device scratch ----------------
__device__ __align__(16) __nv_bfloat16 g_a1h[(size_t)64 * 256 * K1];  // 226 MB
__device__ __align__(16) __nv_bfloat16 g_a1l[(size_t)64 * 256 * K1];  // 226 MB
__device__ __align__(16) __nv_bfloat16 g_b1h[(size_t)C1 * K1];        //   7 MB
__device__ __align__(16) __nv_bfloat16 g_b1l[(size_t)C1 * K1];        //   7 MB
__device__ float g_x1[(size_t)C1 * TT * 256];                          //  33 MB
__device__ __align__(16) __nv_bfloat16 g_a2h[(size_t)64 * 64 * K2];   // 134 MB
__device__ __align__(16) __nv_bfloat16 g_a2l[(size_t)64 * 64 * K2];   // 134 MB
__device__ __align__(16) __nv_bfloat16 g_b2h[(size_t)C2 * K2];        //  17 MB
__device__ __align__(16) __nv_bfloat16 g_b2l[(size_t)C2 * K2];        //  17 MB
__device__ float g_feat[C2 * TT];

// ---------------- helpers ----------------
__device__ __forceinline__ void cp16u(unsigned dst, const void* src) {
    asm volatile("cp.async.cg.shared.global [%0], [%1], 16;" :: "r"(dst), "l"(src));
}
__device__ __forceinline__ uint32_t smem_u32(const void* p) {
    return (uint32_t)__cvta_generic_to_shared(p);
}
__device__ __forceinline__ unsigned pack_bf2(float a, float b) {
    __nv_bfloat162 p = __floats2bfloat162_rn(a, b);
    return *reinterpret_cast<unsigned*>(&p);
}

// ============================================================================
// Prepass: split conv1 weights into bf16 hi/lo  (k = ic*27+tap natural order)
// ============================================================================
__global__ void split_w1(const float* __restrict__ w) {
    int oc = blockIdx.x;
    const float* src = w + (size_t)oc * K1;
    __nv_bfloat16* dh = g_b1h + (size_t)oc * K1;
    __nv_bfloat16* dl = g_b1l + (size_t)oc * K1;
    for (int k = threadIdx.x; k < K1; k += 256) {
        float v = src[k];
        __nv_bfloat16 hi = __float2bfloat16(v);
        dh[k] = hi;
        dl[k] = __float2bfloat16(v - __bfloat162float(hi));
    }
}

// ============================================================================
// Prepass: split conv2 weights -> [oc][ic*32+tap] padded order, hi/lo
// ============================================================================
__global__ void split_w2(const float* __restrict__ w) {
    int oc = blockIdx.x;
    const float* src = w + (size_t)oc * (512 * 27);
    __nv_bfloat16* dh = g_b2h + (size_t)oc * K2;
    __nv_bfloat16* dl = g_b2l + (size_t)oc * K2;
#pragma unroll 4
    for (int j = 0; j < 64; j++) {
        int k = threadIdx.x + j * 256;
        int ic = k >> 5, tap = k & 31;
        float v = (tap < 27) ? src[ic * 27 + tap] : 0.f;
        __nv_bfloat16 hi = __float2bfloat16(v);
        dh[k] = hi;
        dl[k] = __float2bfloat16(v - __bfloat162float(hi));
    }
}

// ============================================================================
// Prepass: im2col + split of input -> A1 [t][m(256)][k(6912)] hi/lo bf16
// ============================================================================
__global__ void im2col1(const float* __restrict__ in) {
    const int t = blockIdx.x;
    const int m = blockIdx.y;
    const int h = m >> 4, w = m & 15;
    __nv_bfloat16* dh = g_a1h + ((size_t)t * 256 + m) * K1;
    __nv_bfloat16* dl = g_a1l + ((size_t)t * 256 + m) * K1;
#pragma unroll
    for (int j = 0; j < 27; j++) {
        int k   = threadIdx.x + j * 256;
        int ic  = k / 27;
        int tap = k - ic * 27;
        int kd = tap / 9, r = tap - kd * 9, kh = r / 3, kw = r - kh * 3;
        int ti = t + kd - 1, hh = 2 * h + kh - 1, ww = 2 * w + kw - 1;
        float v = 0.f;
        if (ti >= 0 && ti < TT && hh >= 0 && hh < HIN && ww >= 0 && ww < WIN)
            v = in[((size_t)(ic * TT + ti) * HIN + hh) * WIN + ww];
        __nv_bfloat16 hi = __float2bfloat16(v);
        dh[k] = hi;
        dl[k] = __float2bfloat16(v - __bfloat162float(hi));
    }
}

// ============================================================================
// im2col2: g_x1 fp32 -> A2 [t*64+m][ic*32+tap] hi/lo bf16 (padded taps zero)
// ============================================================================
__global__ void __launch_bounds__(256)
im2col2() {
    __shared__ float sm[4][3][256];
    const int t   = blockIdx.x;
    const int ic0 = blockIdx.y * 64;
    const int tid = threadIdx.x;
    const int icq = tid >> 6;
    const int m   = tid & 63;
    const int h   = m >> 3, w = m & 7;

    for (int it = 0; it < 16; it++) {
        const int icb = ic0 + it * 4;
        __syncthreads();
#pragma unroll
        for (int icq2 = 0; icq2 < 4; icq2++)
#pragma unroll
            for (int kd = 0; kd < 3; kd++) {
                int ti = t + kd - 1;
                sm[icq2][kd][tid & 255] = 0.f;
                if (ti >= 0 && ti < TT && tid < 256)
                    sm[icq2][kd][tid] =
                        g_x1[((size_t)(icb + icq2) * TT + ti) * 256 + tid];
            }
        __syncthreads();

        float v[32];
#pragma unroll
        for (int tap = 0; tap < 27; tap++) {
            const int kd = tap / 9, rr = tap - kd * 9;
            const int kh = rr / 3, kw = rr - kh * 3;
            int hh = 2 * h + kh - 1, ww = 2 * w + kw - 1;
            v[tap] = (hh >= 0 && ww >= 0) ? sm[icq][kd][hh * 16 + ww] : 0.f;
        }
#pragma unroll
        for (int tap = 27; tap < 32; tap++) v[tap] = 0.f;

        unsigned uh[16], ul[16];
#pragma unroll
        for (int p = 0; p < 16; p++) {
            float a = v[2 * p], b = v[2 * p + 1];
            uh[p] = pack_bf2(a, b);
            float ah = __bfloat162float(__float2bfloat16(a));
            float bh = __bfloat162float(__float2bfloat16(b));
            ul[p] = pack_bf2(a - ah, b - bh);
        }
        const size_t row = ((size_t)t * 64 + m) * K2 + (size_t)(icb + icq) * 32;
        uint4* dh = (uint4*)(g_a2h + row);
        uint4* dl = (uint4*)(g_a2l + row);
        dh[0] = make_uint4(uh[0], uh[1], uh[2], uh[3]);
        dh[1] = make_uint4(uh[4], uh[5], uh[6], uh[7]);
        dh[2] = make_uint4(uh[8], uh[9], uh[10], uh[11]);
        dh[3] = make_uint4(uh[12], uh[13], uh[14], uh[15]);
        dl[0] = make_uint4(ul[0], ul[1], ul[2], ul[3]);
        dl[1] = make_uint4(ul[4], ul[5], ul[6], ul[7]);
        dl[2] = make_uint4(ul[8], ul[9], ul[10], ul[11]);
        dl[3] = make_uint4(ul[12], ul[13], ul[14], ul[15]);
    }
}

// ============================================================================
// Conv1 via mma.sync bf16x3 GEMM, 2-stage pipeline, 2 CTAs/SM.
// Grid (t=64, mq=4, nq=2). 128 thr = 4 warps (1m x 4n), warp tile 64x64.
// CTA tile: M=64, N=256.
// ============================================================================
__global__ void __launch_bounds__(128, 2)
conv1_mma(const float* __restrict__ bias) {
    extern __shared__ __align__(128) char dsmem[];

    const int t    = blockIdx.x;
    const int mq   = blockIdx.y;
    const int nq   = blockIdx.z;
    const int tid  = threadIdx.x;
    const int warp = tid >> 5;
    const int lane = tid & 31;
    const int wn   = warp;               // 0..3 -> N offset (64 each)

    const uint32_t abase = smem_u32(dsmem);

    const int aRow = ((lane >> 3) & 1) * 8 + (lane & 7);   // 0..15
    const int kA   = lane >> 4;
    const int sA   = aRow & 7;
    const int bRow = wn * 64 + ((lane >> 4) << 3) + (lane & 7);
    const int kB   = (lane >> 3) & 1;
    const int sB   = bRow & 7;

    float acc[4][8][4];
#pragma unroll
    for (int mi = 0; mi < 4; mi++)
#pragma unroll
        for (int ni = 0; ni < 8; ni++)
#pragma unroll
            for (int r = 0; r < 4; r++) acc[mi][ni][r] = 0.f;

    const size_t arow0 = ((size_t)t * 256 + mq * 64) * K1;
    const size_t boff  = (size_t)(nq * 256) * K1;

#define STAGE_LOAD1(CH, S)                                                     \
    {                                                                          \
        int seg = (CH) / 108;                                                  \
        int kin = ((CH) - seg * 108) * 64;                                     \
        const __nv_bfloat16* asrc = (seg == 1) ? g_a1l : g_a1h;                \
        const __nv_bfloat16* bsrc = (seg == 2) ? g_b1l : g_b1h;                \
        uint32_t ab = abase + (S) * STAGE1_BYTES;                              \
        uint32_t bb = ab + 8192;                                               \
        _Pragma("unroll")                                                      \
        for (int j = 0; j < 4; j++) {                                          \
            int idx = tid + j * 128;                                           \
            int m = idx >> 3, kp = idx & 7;                                    \
            cp16u(ab + m * 128 + ((kp ^ (m & 7)) << 4),                        \
                  asrc + arow0 + (size_t)m * K1 + kin + kp * 8);               \
        }                                                                      \
        _Pragma("unroll")                                                      \
        for (int j = 0; j < 16; j++) {                                         \
            int idx = tid + j * 128;                                           \
            int oc = idx >> 3, kp = idx & 7;                                   \
            cp16u(bb + oc * 128 + ((kp ^ (oc & 7)) << 4),                      \
                  bsrc + boff + (size_t)oc * K1 + kin + kp * 8);               \
        }                                                                      \
    }

    STAGE_LOAD1(0, 0);
    asm volatile("cp.async.commit_group;");

    for (int c = 0; c < NCHUNK1; c++) {
        if (c + 1 < NCHUNK1) {
            STAGE_LOAD1(c + 1, (c + 1) & 1);
            asm volatile("cp.async.commit_group;");
            asm volatile("cp.async.wait_group 1;");
        } else {
            asm volatile("cp.async.wait_group 0;");
        }
        __syncthreads();

        const uint32_t abuf = abase + (c & 1) * STAGE1_BYTES;
        const uint32_t aB = abuf + aRow * 128;
        const uint32_t bB = abuf + 8192 + bRow * 128;

#pragma unroll
        for (int ks = 0; ks < 4; ks++) {
            uint32_t a[4][4];
#pragma unroll
            for (int mi = 0; mi < 4; mi++) {
                uint32_t ad = aB + mi * 2048 + (((2 * ks + kA) ^ sA) << 4);
                asm volatile(
                    "ldmatrix.sync.aligned.m8n8.x4.shared.b16 {%0,%1,%2,%3}, [%4];"
                    : "=r"(a[mi][0]), "=r"(a[mi][1]), "=r"(a[mi][2]), "=r"(a[mi][3])
                    : "r"(ad));
            }
            uint32_t bg[8][2];
#pragma unroll
            for (int p = 0; p < 4; p++) {
                uint32_t bd = bB + p * 2048 + (((2 * ks + kB) ^ sB) << 4);
                asm volatile(
                    "ldmatrix.sync.aligned.m8n8.x4.shared.b16 {%0,%1,%2,%3}, [%4];"
                    : "=r"(bg[2 * p][0]), "=r"(bg[2 * p][1]),
                      "=r"(bg[2 * p + 1][0]), "=r"(bg[2 * p + 1][1])
                    : "r"(bd));
            }
#pragma unroll
            for (int mi = 0; mi < 4; mi++)
#pragma unroll
                for (int ni = 0; ni < 8; ni++)
                    asm volatile(
                        "mma.sync.aligned.m16n8k16.row.col.f32.bf16.bf16.f32 "
                        "{%0,%1,%2,%3}, {%4,%5,%6,%7}, {%8,%9}, {%0,%1,%2,%3};"
                        : "+f"(acc[mi][ni][0]), "+f"(acc[mi][ni][1]),
                          "+f"(acc[mi][ni][2]), "+f"(acc[mi][ni][3])
                        : "r"(a[mi][0]), "r"(a[mi][1]), "r"(a[mi][2]), "r"(a[mi][3]),
                          "r"(bg[ni][0]), "r"(bg[ni][1]));
        }
        __syncthreads();
    }
#undef STAGE_LOAD1

    // epilogue: bias + plain fp32 store into g_x1[oc][t][m]
    const int mbase = mq * 64 + (lane >> 2);
    const int ncb   = nq * 256 + wn * 64 + 2 * (lane & 3);
#pragma unroll
    for (int ni = 0; ni < 8; ni++) {
        int n0 = ncb + ni * 8;
        float b0 = bias[n0], b1 = bias[n0 + 1];
        float* p0 = g_x1 + ((size_t)n0 * TT + t) * 256;
        float* p1 = g_x1 + ((size_t)(n0 + 1) * TT + t) * 256;
#pragma unroll
        for (int mi = 0; mi < 4; mi++) {
            int m0 = mbase + mi * 16;
            int m1 = m0 + 8;
            p0[m0] = acc[mi][ni][0] + b0;
            p1[m0] = acc[mi][ni][1] + b1;
            p0[m1] = acc[mi][ni][2] + b0;
            p1[m1] = acc[mi][ni][3] + b1;
        }
    }
}

// ============================================================================
// Conv2 via mma.sync bf16x3 GEMM + fused maxpool, 3-stage, 2 CTAs/SM.
// Grid (t=64, nq=4). 128 thr = 4 warps (1m x 4n), warp tile 64x32.
// CTA tile: M=64, N=128.
// ============================================================================
__global__ void __launch_bounds__(128, 2)
conv2_mma(const float* __restrict__ bias) {
    extern __shared__ __align__(128) char dsmem[];

    const int t    = blockIdx.x;
    const int nq   = blockIdx.y;
    const int tid  = threadIdx.x;
    const int warp = tid >> 5;
    const int lane = tid & 31;
    const int wn   = warp;               // 0..3 -> N offset (32 each)

    const uint32_t abase = smem_u32(dsmem);

    const int aRow = ((lane >> 3) & 1) * 8 + (lane & 7);
    const int kA   = lane >> 4;
    const int sA   = aRow & 7;
    const int bRow = wn * 32 + ((lane >> 4) << 3) + (lane & 7);
    const int kB   = (lane >> 3) & 1;
    const int sB   = bRow & 7;

    float acc[4][4][4];
#pragma unroll
    for (int mi = 0; mi < 4; mi++)
#pragma unroll
        for (int ni = 0; ni < 4; ni++)
#pragma unroll
            for (int r = 0; r < 4; r++) acc[mi][ni][r] = 0.f;

    const size_t arow0 = (size_t)t * 64 * K2;
    const size_t boff  = (size_t)(nq * 128) * K2;

#define STAGE_LOAD2(CH, S)                                                     \
    {                                                                          \
        int seg = (CH) >> 8;                                                   \
        int kin = ((CH) & 255) * 64;                                           \
        const __nv_bfloat16* asrc = (seg == 1) ? g_a2l : g_a2h;                \
        const __nv_bfloat16* bsrc = (seg == 2) ? g_b2l : g_b2h;                \
        uint32_t ab = abase + (S) * STAGE2_BYTES;                              \
        uint32_t bb = ab + 8192;                                               \
        _Pragma("unroll")                                                      \
        for (int j = 0; j < 4; j++) {                                          \
            int idx = tid + j * 128;                                           \
            int m = idx >> 3, kp = idx & 7;                                    \
            cp16u(ab + m * 128 + ((kp ^ (m & 7)) << 4),                        \
                  asrc + arow0 + (size_t)m * K2 + kin + kp * 8);               \
        }                                                                      \
        _Pragma("unroll")                                                      \
        for (int j = 0; j < 8; j++) {                                          \
            int idx = tid + j * 128;                                           \
            int oc = idx >> 3, kp = idx & 7;                                   \
            cp16u(bb + oc * 128 + ((kp ^ (oc & 7)) << 4),                      \
                  bsrc + boff + (size_t)oc * K2 + kin + kp * 8);               \
        }                                                                      \
    }

    STAGE_LOAD2(0, 0);
    asm volatile("cp.async.commit_group;");
    STAGE_LOAD2(1, 1);
    asm volatile("cp.async.commit_group;");

    int sc = 0;
    for (int c = 0; c < NCHUNK2; c++) {
        if (c + 1 < NCHUNK2) asm volatile("cp.async.wait_group 1;");
        else                 asm volatile("cp.async.wait_group 0;");
        __syncthreads();
        if (c + 2 < NCHUNK2) {
            int sn = sc + 2; if (sn >= 3) sn -= 3;
            STAGE_LOAD2(c + 2, sn);
            asm volatile("cp.async.commit_group;");
        }

        const uint32_t abuf = abase + sc * STAGE2_BYTES;
        const uint32_t aB = abuf + aRow * 128;
        const uint32_t bB = abuf + 8192 + bRow * 128;

#pragma unroll
        for (int ks = 0; ks < 4; ks++) {
            uint32_t a[4][4];
#pragma unroll
            for (int mi = 0; mi < 4; mi++) {
                uint32_t ad = aB + mi * 2048 + (((2 * ks + kA) ^ sA) << 4);
                asm volatile(
                    "ldmatrix.sync.aligned.m8n8.x4.shared.b16 {%0,%1,%2,%3}, [%4];"
                    : "=r"(a[mi][0]), "=r"(a[mi][1]), "=r"(a[mi][2]), "=r"(a[mi][3])
                    : "r"(ad));
            }
            uint32_t bg[4][2];
#pragma unroll
            for (int p = 0; p < 2; p++) {
                uint32_t bd = bB + p * 2048 + (((2 * ks + kB) ^ sB) << 4);
                asm volatile(
                    "ldmatrix.sync.aligned.m8n8.x4.shared.b16 {%0,%1,%2,%3}, [%4];"
                    : "=r"(bg[2 * p][0]), "=r"(bg[2 * p][1]),
                      "=r"(bg[2 * p + 1][0]), "=r"(bg[2 * p + 1][1])
                    : "r"(bd));
            }
#pragma unroll
            for (int mi = 0; mi < 4; mi++)
#pragma unroll
                for (int ni = 0; ni < 4; ni++)
                    asm volatile(
                        "mma.sync.aligned.m16n8k16.row.col.f32.bf16.bf16.f32 "
                        "{%0,%1,%2,%3}, {%4,%5,%6,%7}, {%8,%9}, {%0,%1,%2,%3};"
                        : "+f"(acc[mi][ni][0]), "+f"(acc[mi][ni][1]),
                          "+f"(acc[mi][ni][2]), "+f"(acc[mi][ni][3])
                        : "r"(a[mi][0]), "r"(a[mi][1]), "r"(a[mi][2]), "r"(a[mi][3]),
                          "r"(bg[ni][0]), "r"(bg[ni][1]));
        }
        __syncthreads();
        if (++sc == 3) sc = 0;
    }
#undef STAGE_LOAD2

    // fused maxpool epilogue: max over all 64 positions, + bias -> g_feat
#pragma unroll
    for (int ni = 0; ni < 4; ni++) {
        float me = -3.4e38f, mo = -3.4e38f;
#pragma unroll
        for (int mi = 0; mi < 4; mi++) {
            me = fmaxf(me, fmaxf(acc[mi][ni][0], acc[mi][ni][2]));
            mo = fmaxf(mo, fmaxf(acc[mi][ni][1], acc[mi][ni][3]));
        }
#pragma unroll
        for (int off = 4; off < 32; off <<= 1) {
            me = fmaxf(me, __shfl_xor_sync(0xffffffffu, me, off));
            mo = fmaxf(mo, __shfl_xor_sync(0xffffffffu, mo, off));
        }
        if (lane < 4) {
            int oc = nq * 128 + wn * 32 + ni * 8 + 2 * lane;
            g_feat[oc * TT + t]       = me + bias[oc];
            g_feat[(oc + 1) * TT + t] = mo + bias[oc + 1];
        }
    }
}

// ============================================================================
// Head (unchanged, passing since R1)
// ============================================================================
__device__ __forceinline__ float iou1d(float s1, float e1, float s2, float e2) {
    float inter = fmaxf(fminf(e1, e2) - fmaxf(s1, s2), 0.f);
    float uni   = (e1 - s1) + (e2 - s2) - inter;
    return inter / fmaxf(uni, 1e-6f);
}

__global__ void __launch_bounds__(512, 1)
head_kernel(const float* __restrict__ sw, const float* __restrict__ sb,
            const float* __restrict__ dw, const float* __restrict__ db,
            const float* __restrict__ gt, const int* __restrict__ vlen,
            float* __restrict__ out) {
    __shared__ float s_sl[16 * 64], s_dl[16 * 64];
    __shared__ float s_bs[NANCH], s_be[NANCH], s_sc[NANCH];
    __shared__ float s_as[NANCH], s_ae[NANCH];
    __shared__ float s_lp0[NANCH], s_lp1[NANCH], s_dc[NANCH], s_dt[NANCH];
    __shared__ float s_gt[16];
    __shared__ int   s_best[8];
    __shared__ float r0[512], r1[512], r2[512], r3[512];

    const int tid  = threadIdx.x;
    const int wid  = tid >> 5;
    const int lane = tid & 31;
    if (tid < 16) s_gt[tid] = gt[tid];

    const int o = tid >> 6;
    const int t = tid & 63;
    {
        float a0 = sb[o], a1 = sb[o + 8], d0 = db[o], d1 = db[o + 8];
        for (int c = 0; c < C2; c++) {
            float f = g_feat[c * 64 + t];
            a0 = fmaf(sw[o * 512 + c],       f, a0);
            a1 = fmaf(sw[(o + 8) * 512 + c], f, a1);
            d0 = fmaf(dw[o * 512 + c],       f, d0);
            d1 = fmaf(dw[(o + 8) * 512 + c], f, d1);
        }
        s_sl[o * 64 + t] = a0;  s_sl[(o + 8) * 64 + t] = a1;
        s_dl[o * 64 + t] = d0;  s_dl[(o + 8) * 64 + t] = d1;
    }
    __syncthreads();

    {
        const int a = o;
        float l0 = s_sl[a * 64 + t], l1 = s_sl[(a + 8) * 64 + t];
        float mx = fmaxf(l0, l1);
        float lse = mx + logf(expf(l0 - mx) + expf(l1 - mx));
        float p1  = expf(l1 - lse);
        float dc  = s_dl[a * 64 + t], dl = s_dl[(a + 8) * 64 + t];
        float alen = (float)(8 << a);
        float ctr  = (t + 0.5f) * 8.f;
        float pc = ctr + dc * alen;
        float pl = alen * expf(fminf(fmaxf(dl, -10.f), 10.f));
        float ps = fminf(fmaxf(pc - 0.5f * pl, 0.f), 512.f);
        float pe = fminf(fmaxf(pc + 0.5f * pl, 0.f), 512.f);
        s_bs[tid] = ps;  s_be[tid] = pe;
        s_sc[tid] = (pe - ps >= 4.f) ? p1 : -1.0e9f;
        s_as[tid] = ctr - 0.5f * alen;
        s_ae[tid] = ctr + 0.5f * alen;
        s_lp0[tid] = l0 - lse;  s_lp1[tid] = l1 - lse;
        s_dc[tid] = dc;  s_dt[tid] = dl;
    }
    __syncthreads();

    if (wid < 8) {
        float gs = s_gt[wid * 2], ge = s_gt[wid * 2 + 1];
        float bv = -3.4e38f; int bi = 0x7fffffff;
        for (int k = 0; k < 16; k++) {
            int n = lane + 32 * k;
            float v = iou1d(s_as[n], s_ae[n], gs, ge);
            if (v > bv) { bv = v; bi = n; }
        }
        for (int off = 16; off; off >>= 1) {
            float ov = __shfl_xor_sync(0xffffffffu, bv, off);
            int   oi = __shfl_xor_sync(0xffffffffu, bi, off);
            if (ov > bv || (ov == bv && oi < bi)) { bv = ov; bi = oi; }
        }
        if (lane == 0) s_best[wid] = bi;
    }
    __syncthreads();

    {
        float myas = s_as[tid], myae = s_ae[tid];
        float miou = -1.f; int ag = 0;
#pragma unroll
        for (int g = 0; g < 8; g++) {
            float v = iou1d(myas, myae, s_gt[2 * g], s_gt[2 * g + 1]);
            if (v > miou) { miou = v; ag = g; }
        }
        int lab = (miou < 0.3f) ? 0 : -1;
        if (miou >= 0.7f) lab = 1;
#pragma unroll
        for (int g = 0; g < 8; g++)
            if (s_best[g] == tid) lab = 1;
        float vl = (float)vlen[0];
        if (!(myas >= 0.f && myae <= vl)) lab = -1;

        float gs = s_gt[2 * ag], ge = s_gt[2 * ag + 1];
        float gc = 0.5f * (gs + ge);
        float gl = fmaxf(ge - gs, 1e-6f);
        float ac = 0.5f * (myas + myae);
        float al = myae - myas;
        float rl0 = (gc - ac) / al;
        float rl1 = logf(gl / al);
        float d0 = s_dc[tid] - rl0, d1 = s_dt[tid] - rl1;
        float sl1 = (fabsf(d0) < 1.f ? 0.5f * d0 * d0 : fabsf(d0) - 0.5f)
                  + (fabsf(d1) < 1.f ? 0.5f * d1 * d1 : fabsf(d1) - 0.5f);
        float maskv = (lab >= 0) ? 1.f : 0.f;
        float posv  = (lab == 1) ? 1.f : 0.f;
        float nll   = -((lab == 1) ? s_lp1[tid] : s_lp0[tid]);
        r0[tid] = nll * maskv;  r1[tid] = maskv;
        r2[tid] = sl1 * posv;   r3[tid] = posv;
    }
    __syncthreads();
    for (int s = 256; s > 0; s >>= 1) {
        if (tid < s) {
            r0[tid] += r0[tid + s];  r1[tid] += r1[tid + s];
            r2[tid] += r2[tid + s];  r3[tid] += r3[tid + s];
        }
        __syncthreads();
    }
    if (tid == 0) {
        out[300] = r0[0] / fmaxf(r1[0], 1.f);
        out[301] = r2[0] / fmaxf(r3[0], 1.f);
    }
    __syncthreads();

    if (wid == 0) {
        for (int it = 0; it < 100; it++) {
            float bv = -3.4e38f; int bi = 0x7fffffff;
#pragma unroll
            for (int k = 0; k < 16; k++) {
                int n = lane + 32 * k;
                float v = s_sc[n];
                if (v > bv) { bv = v; bi = n; }
            }
            for (int off = 16; off; off >>= 1) {
                float ov = __shfl_xor_sync(0xffffffffu, bv, off);
                int   oi = __shfl_xor_sync(0xffffffffu, bi, off);
                if (ov > bv || (ov == bv && oi < bi)) { bv = ov; bi = oi; }
            }
            float kb0 = s_bs[bi], kb1 = s_be[bi];
            bool keep = bv > -5.0e8f;
            if (lane == 0) {
                out[2 * it]     = keep ? kb0 : 0.f;
                out[2 * it + 1] = keep ? kb1 : 0.f;
                out[200 + it]   = keep ? bv  : 0.f;
            }
#pragma unroll
            for (int k = 0; k < 16; k++) {
                int n = lane + 32 * k;
                float v = iou1d(kb0, kb1, s_bs[n], s_be[n]);
                if (v > 0.7f || n == bi) s_sc[n] = -1.0e9f;
            }
            __syncwarp();
        }
    }
}

// ============================================================================
extern "C" void kernel_launch(void* const* d_in, const int* in_sizes, int n_in,
                              void* d_out, int out_size) {
    const float* base = (const float*)d_in[0];
    const float* gt   = (const float*)d_in[1];
    const int*   vl   = (const int*)d_in[2];
    const float* c1w  = (const float*)d_in[3];
    const float* c1b  = (const float*)d_in[4];
    const float* c2w  = (const float*)d_in[5];
    const float* c2b  = (const float*)d_in[6];
    const float* sw   = (const float*)d_in[7];
    const float* sb   = (const float*)d_in[8];
    const float* dw   = (const float*)d_in[9];
    const float* db   = (const float*)d_in[10];
    float* out = (float*)d_out;

    static int attr_set = 0;
    if (!attr_set) {
        cudaFuncSetAttribute(conv1_mma,
                             cudaFuncAttributeMaxDynamicSharedMemorySize, C1MMA_SMEM);
        cudaFuncSetAttribute(conv2_mma,
                             cudaFuncAttributeMaxDynamicSharedMemorySize, C2MMA_SMEM);
        attr_set = 1;
    }

    split_w1<<<512, 256>>>(c1w);
    split_w2<<<512, 256>>>(c2w);
    im2col1<<<dim3(64, 256), 256>>>(base);
    conv1_mma<<<dim3(64, 4, 2), 128, C1MMA_SMEM>>>(c1b);
    im2col2<<<dim3(64, 8), 256>>>();
    conv2_mma<<<dim3(64, 4), 128, C2MMA_SMEM>>>(c2b);
    head_kernel<<<1, 512>>>(sw, sb, dw, db, gt, vl, out);
}

// round 10
// speedup vs baseline: 6.2293x; 1.1512x over previous
#include <cuda_runtime.h>
#include <cuda_bf16.h>
#include <cstdint>

typedef unsigned long long ull;

// ---------------- problem constants ----------------
#define CIN   256
#define TT    64
#define HIN   32
#define WIN   32
#define C1    512
#define C2    512
#define NANCH 512

// conv1 GEMM: K1 = 27 taps * 256 ic (tap-major: k = tap*256 + ic)
#define K1      6912
#define NCHUNK1 324            // 3 segments * 108 (27 tap * 4 icc)
#define STAGE1_BYTES 40960     // A 8KB + B 32KB
#define C1MMA_SMEM  (2 * STAGE1_BYTES)   // 80KB, 2 CTAs/SM

// conv2 GEMM: K2 = 27 taps * 512 ic (tap-major)
#define K2      13824
#define NCHUNK2 648            // 3 segments * 216 (27 tap * 8 icc)
#define STAGE2_BYTES 24576     // A 8KB + B 16KB
#define C2MMA_SMEM  (3 * STAGE2_BYTES)   // 72KB, 2 CTAs/SM

// padded activation tensors (ic innermost)
// P1: [tp 66][hp 34][wp 34][ic 256]   P2: [tp 66][hp 18][wp 18][ic 512]
#define P1_ELEMS ((size_t)66 * 34 * 34 * 256)   // 19,531,776
#define P2_ELEMS ((size_t)66 * 18 * 18 * 512)   // 10,948,608

// ---------------- device scratch ----------------
__device__ __align__(16) __nv_bfloat16 g_p1h[P1_ELEMS];          // 39 MB
__device__ __align__(16) __nv_bfloat16 g_p1l[P1_ELEMS];          // 39 MB
__device__ __align__(16) __nv_bfloat16 g_p2h[P2_ELEMS];          // 22 MB
__device__ __align__(16) __nv_bfloat16 g_p2l[P2_ELEMS];          // 22 MB
__device__ __align__(16) __nv_bfloat16 g_b1h[(size_t)C1 * K1];   //  7 MB
__device__ __align__(16) __nv_bfloat16 g_b1l[(size_t)C1 * K1];   //  7 MB
__device__ __align__(16) __nv_bfloat16 g_b2h[(size_t)C2 * K2];   // 14 MB
__device__ __align__(16) __nv_bfloat16 g_b2l[(size_t)C2 * K2];   // 14 MB
__device__ float g_feat[C2 * TT];

// ---------------- helpers ----------------
__device__ __forceinline__ void cp16u(unsigned dst, const void* src) {
    asm volatile("cp.async.cg.shared.global [%0], [%1], 16;" :: "r"(dst), "l"(src));
}
__device__ __forceinline__ uint32_t smem_u32(const void* p) {
    return (uint32_t)__cvta_generic_to_shared(p);
}
__device__ __forceinline__ unsigned pack_bf2(float a, float b) {
    __nv_bfloat162 p = __floats2bfloat162_rn(a, b);
    return *reinterpret_cast<unsigned*>(&p);
}

// ============================================================================
// memzero (halo init for P1/P2)
// ============================================================================
__global__ void memzero(uint4* p, size_t n) {
    size_t i = (size_t)blockIdx.x * blockDim.x + threadIdx.x;
    size_t stride = (size_t)gridDim.x * blockDim.x;
    uint4 z = make_uint4(0u, 0u, 0u, 0u);
    for (; i < n; i += stride) p[i] = z;
}

// ============================================================================
// split_w1: w1[oc][ic*27+tap] -> b1 [oc][tap*256+ic] hi/lo
// ============================================================================
__global__ void split_w1(const float* __restrict__ w) {
    int oc = blockIdx.x;
    const float* src = w + (size_t)oc * K1;
    __nv_bfloat16* dh = g_b1h + (size_t)oc * K1;
    __nv_bfloat16* dl = g_b1l + (size_t)oc * K1;
#pragma unroll 3
    for (int j = 0; j < 27; j++) {
        int k = threadIdx.x + j * 256;
        int tap = k >> 8, ic = k & 255;
        float v = src[ic * 27 + tap];
        __nv_bfloat16 hi = __float2bfloat16(v);
        dh[k] = hi;
        dl[k] = __float2bfloat16(v - __bfloat162float(hi));
    }
}

// ============================================================================
// split_w2: w2[oc][ic*27+tap] -> b2 [oc][tap*512+ic] hi/lo
// ============================================================================
__global__ void split_w2(const float* __restrict__ w) {
    int oc = blockIdx.x;
    const float* src = w + (size_t)oc * (512 * 27);
    __nv_bfloat16* dh = g_b2h + (size_t)oc * K2;
    __nv_bfloat16* dl = g_b2l + (size_t)oc * K2;
#pragma unroll 6
    for (int j = 0; j < 54; j++) {
        int k = threadIdx.x + j * 256;
        int tap = k >> 9, ic = k & 511;
        float v = src[ic * 27 + tap];
        __nv_bfloat16 hi = __float2bfloat16(v);
        dh[k] = hi;
        dl[k] = __float2bfloat16(v - __bfloat162float(hi));
    }
}

// ============================================================================
// pad_split1: input [ic][t][h][w] fp32 -> P1 [t+1][h+1][w+1][ic] hi/lo bf16.
// Grid (t=64, h=32), 256 threads, smem transpose.
// ============================================================================
__global__ void __launch_bounds__(256)
pad_split1(const float* __restrict__ in) {
    __shared__ float sm[256 * 33];      // [ic][w] padded stride 33
    const int t = blockIdx.x;
    const int h = blockIdx.y;
    const int tid = threadIdx.x;

    // load: coalesced over w
#pragma unroll 8
    for (int j = 0; j < 32; j++) {
        int k = tid + j * 256;
        int ic = k >> 5, w = k & 31;
        sm[ic * 33 + w] = in[((size_t)(ic * TT + t) * HIN + h) * WIN + w];
    }
    __syncthreads();

    // write: thread (w = tid>>3, icg = tid&7) handles 32 ics, XOR-permuted LDS
    const int w   = tid >> 3;
    const int icg = tid & 7;
    float v[32];
#pragma unroll
    for (int i = 0; i < 32; i++) {
        int jj = i ^ (icg << 2);
        v[jj] = sm[(icg * 32 + jj) * 33 + w];
    }
    unsigned uh[16], ul[16];
#pragma unroll
    for (int p = 0; p < 16; p++) {
        float a = v[2 * p], b = v[2 * p + 1];
        uh[p] = pack_bf2(a, b);
        float ah = __bfloat162float(__float2bfloat16(a));
        float bh = __bfloat162float(__float2bfloat16(b));
        ul[p] = pack_bf2(a - ah, b - bh);
    }
    const size_t row = (((size_t)(t + 1) * 34) + (h + 1)) * 34 + (w + 1);
    uint4* dh = (uint4*)(g_p1h + row * 256 + icg * 32);
    uint4* dl = (uint4*)(g_p1l + row * 256 + icg * 32);
    dh[0] = make_uint4(uh[0], uh[1], uh[2], uh[3]);
    dh[1] = make_uint4(uh[4], uh[5], uh[6], uh[7]);
    dh[2] = make_uint4(uh[8], uh[9], uh[10], uh[11]);
    dh[3] = make_uint4(uh[12], uh[13], uh[14], uh[15]);
    dl[0] = make_uint4(ul[0], ul[1], ul[2], ul[3]);
    dl[1] = make_uint4(ul[4], ul[5], ul[6], ul[7]);
    dl[2] = make_uint4(ul[8], ul[9], ul[10], ul[11]);
    dl[3] = make_uint4(ul[12], ul[13], ul[14], ul[15]);
}

// ============================================================================
// Conv1 via mma.sync bf16x3 GEMM, A gathered from P1 (no im2col).
// Grid (t=64, mq=4, nq=2). 128 thr = 4 warps (1m x 4n), warp tile 64x64.
// Epilogue: bias + hi/lo bf16 write straight into P2 padded layout.
// ============================================================================
__global__ void __launch_bounds__(128, 2)
conv1_mma(const float* __restrict__ bias) {
    extern __shared__ __align__(128) char dsmem[];

    const int t    = blockIdx.x;
    const int mq   = blockIdx.y;
    const int nq   = blockIdx.z;
    const int tid  = threadIdx.x;
    const int warp = tid >> 5;
    const int lane = tid & 31;
    const int wn   = warp;

    const uint32_t abase = smem_u32(dsmem);

    const int aRow = ((lane >> 3) & 1) * 8 + (lane & 7);
    const int kA   = lane >> 4;
    const int sA   = aRow & 7;
    const int bRow = wn * 64 + ((lane >> 4) << 3) + (lane & 7);
    const int kB   = (lane >> 3) & 1;
    const int sB   = bRow & 7;

    float acc[4][8][4];
#pragma unroll
    for (int mi = 0; mi < 4; mi++)
#pragma unroll
        for (int ni = 0; ni < 8; ni++)
#pragma unroll
            for (int r = 0; r < 4; r++) acc[mi][ni][r] = 0.f;

    const size_t boff = (size_t)(nq * 256) * K1;

#define STAGE_LOAD1(CH, S)                                                     \
    {                                                                          \
        int seg = (CH) / 108;                                                  \
        int r   = (CH) - seg * 108;                                            \
        int tap = r >> 2, icc = r & 3;                                         \
        int kd = tap / 9, rr = tap - kd * 9, kh = rr / 3, kw = rr - kh * 3;    \
        const __nv_bfloat16* asrc = (seg == 1) ? g_p1l : g_p1h;                \
        const __nv_bfloat16* bsrc = (seg == 2) ? g_b1l : g_b1h;                \
        const size_t tb = (size_t)(t + kd) * (34 * 34 * 256) + icc * 64;       \
        uint32_t ab = abase + (S) * STAGE1_BYTES;                              \
        uint32_t bb = ab + 8192;                                               \
        _Pragma("unroll")                                                      \
        for (int j = 0; j < 4; j++) {                                          \
            int idx = tid + j * 128;                                           \
            int m = idx >> 3, kp = idx & 7;                                    \
            int mg = mq * 64 + m;                                              \
            int hp = 2 * (mg >> 4) + kh, wp = 2 * (mg & 15) + kw;              \
            cp16u(ab + m * 128 + ((kp ^ (m & 7)) << 4),                        \
                  asrc + tb + ((size_t)hp * 34 + wp) * 256 + kp * 8);          \
        }                                                                      \
        _Pragma("unroll")                                                      \
        for (int j = 0; j < 16; j++) {                                         \
            int idx = tid + j * 128;                                           \
            int oc = idx >> 3, kp = idx & 7;                                   \
            cp16u(bb + oc * 128 + ((kp ^ (oc & 7)) << 4),                      \
                  bsrc + boff + (size_t)oc * K1 + r * 64 + kp * 8);            \
        }                                                                      \
    }

    STAGE_LOAD1(0, 0);
    asm volatile("cp.async.commit_group;");

    for (int c = 0; c < NCHUNK1; c++) {
        if (c + 1 < NCHUNK1) {
            STAGE_LOAD1(c + 1, (c + 1) & 1);
            asm volatile("cp.async.commit_group;");
            asm volatile("cp.async.wait_group 1;");
        } else {
            asm volatile("cp.async.wait_group 0;");
        }
        __syncthreads();

        const uint32_t abuf = abase + (c & 1) * STAGE1_BYTES;
        const uint32_t aB = abuf + aRow * 128;
        const uint32_t bB = abuf + 8192 + bRow * 128;

#pragma unroll
        for (int ks = 0; ks < 4; ks++) {
            uint32_t a[4][4];
#pragma unroll
            for (int mi = 0; mi < 4; mi++) {
                uint32_t ad = aB + mi * 2048 + (((2 * ks + kA) ^ sA) << 4);
                asm volatile(
                    "ldmatrix.sync.aligned.m8n8.x4.shared.b16 {%0,%1,%2,%3}, [%4];"
                    : "=r"(a[mi][0]), "=r"(a[mi][1]), "=r"(a[mi][2]), "=r"(a[mi][3])
                    : "r"(ad));
            }
            uint32_t bg[8][2];
#pragma unroll
            for (int p = 0; p < 4; p++) {
                uint32_t bd = bB + p * 2048 + (((2 * ks + kB) ^ sB) << 4);
                asm volatile(
                    "ldmatrix.sync.aligned.m8n8.x4.shared.b16 {%0,%1,%2,%3}, [%4];"
                    : "=r"(bg[2 * p][0]), "=r"(bg[2 * p][1]),
                      "=r"(bg[2 * p + 1][0]), "=r"(bg[2 * p + 1][1])
                    : "r"(bd));
            }
#pragma unroll
            for (int mi = 0; mi < 4; mi++)
#pragma unroll
                for (int ni = 0; ni < 8; ni++)
                    asm volatile(
                        "mma.sync.aligned.m16n8k16.row.col.f32.bf16.bf16.f32 "
                        "{%0,%1,%2,%3}, {%4,%5,%6,%7}, {%8,%9}, {%0,%1,%2,%3};"
                        : "+f"(acc[mi][ni][0]), "+f"(acc[mi][ni][1]),
                          "+f"(acc[mi][ni][2]), "+f"(acc[mi][ni][3])
                        : "r"(a[mi][0]), "r"(a[mi][1]), "r"(a[mi][2]), "r"(a[mi][3]),
                          "r"(bg[ni][0]), "r"(bg[ni][1]));
        }
        __syncthreads();
    }
#undef STAGE_LOAD1

    // epilogue: bias + hi/lo bf16 -> P2 [t+1][h1+1][w1+1][oc]
    const int mbase = mq * 64 + (lane >> 2);
    const int ncb   = nq * 256 + wn * 64 + 2 * (lane & 3);
#pragma unroll
    for (int mi = 0; mi < 4; mi++) {
        int m0 = mbase + mi * 16;
        int m1 = m0 + 8;
        size_t row0 = (((size_t)(t + 1) * 18) + ((m0 >> 4) + 1)) * 18 + ((m0 & 15) + 1);
        size_t row1 = (((size_t)(t + 1) * 18) + ((m1 >> 4) + 1)) * 18 + ((m1 & 15) + 1);
#pragma unroll
        for (int ni = 0; ni < 8; ni++) {
            int n0 = ncb + ni * 8;
            float b0 = bias[n0], b1 = bias[n0 + 1];
            float v00 = acc[mi][ni][0] + b0, v01 = acc[mi][ni][1] + b1;
            float v10 = acc[mi][ni][2] + b0, v11 = acc[mi][ni][3] + b1;
            unsigned h0 = pack_bf2(v00, v01), h1 = pack_bf2(v10, v11);
            float r00 = v00 - __bfloat162float(__float2bfloat16(v00));
            float r01 = v01 - __bfloat162float(__float2bfloat16(v01));
            float r10 = v10 - __bfloat162float(__float2bfloat16(v10));
            float r11 = v11 - __bfloat162float(__float2bfloat16(v11));
            *(unsigned*)(g_p2h + row0 * 512 + n0) = h0;
            *(unsigned*)(g_p2h + row1 * 512 + n0) = h1;
            *(unsigned*)(g_p2l + row0 * 512 + n0) = pack_bf2(r00, r01);
            *(unsigned*)(g_p2l + row1 * 512 + n0) = pack_bf2(r10, r11);
        }
    }
}

// ============================================================================
// Conv2 via mma.sync bf16x3 GEMM + fused maxpool, A gathered from P2.
// Grid (t=64, nq=4). 128 thr = 4 warps (1m x 4n), warp tile 64x32. 3-stage.
// ============================================================================
__global__ void __launch_bounds__(128, 2)
conv2_mma(const float* __restrict__ bias) {
    extern __shared__ __align__(128) char dsmem[];

    const int t    = blockIdx.x;
    const int nq   = blockIdx.y;
    const int tid  = threadIdx.x;
    const int warp = tid >> 5;
    const int lane = tid & 31;
    const int wn   = warp;

    const uint32_t abase = smem_u32(dsmem);

    const int aRow = ((lane >> 3) & 1) * 8 + (lane & 7);
    const int kA   = lane >> 4;
    const int sA   = aRow & 7;
    const int bRow = wn * 32 + ((lane >> 4) << 3) + (lane & 7);
    const int kB   = (lane >> 3) & 1;
    const int sB   = bRow & 7;

    float acc[4][4][4];
#pragma unroll
    for (int mi = 0; mi < 4; mi++)
#pragma unroll
        for (int ni = 0; ni < 4; ni++)
#pragma unroll
            for (int r = 0; r < 4; r++) acc[mi][ni][r] = 0.f;

    const size_t boff = (size_t)(nq * 128) * K2;

#define STAGE_LOAD2(CH, S)                                                     \
    {                                                                          \
        int seg = (CH) / 216;                                                  \
        int r   = (CH) - seg * 216;                                            \
        int tap = r >> 3, icc = r & 7;                                         \
        int kd = tap / 9, rr = tap - kd * 9, kh = rr / 3, kw = rr - kh * 3;    \
        const __nv_bfloat16* asrc = (seg == 1) ? g_p2l : g_p2h;                \
        const __nv_bfloat16* bsrc = (seg == 2) ? g_b2l : g_b2h;                \
        const size_t tb = (size_t)(t + kd) * (18 * 18 * 512) + icc * 64;       \
        uint32_t ab = abase + (S) * STAGE2_BYTES;                              \
        uint32_t bb = ab + 8192;                                               \
        _Pragma("unroll")                                                      \
        for (int j = 0; j < 4; j++) {                                          \
            int idx = tid + j * 128;                                           \
            int m = idx >> 3, kp = idx & 7;                                    \
            int hp = 2 * (m >> 3) + kh, wp = 2 * (m & 7) + kw;                 \
            cp16u(ab + m * 128 + ((kp ^ (m & 7)) << 4),                        \
                  asrc + tb + ((size_t)hp * 18 + wp) * 512 + kp * 8);          \
        }                                                                      \
        _Pragma("unroll")                                                      \
        for (int j = 0; j < 8; j++) {                                          \
            int idx = tid + j * 128;                                           \
            int oc = idx >> 3, kp = idx & 7;                                   \
            cp16u(bb + oc * 128 + ((kp ^ (oc & 7)) << 4),                      \
                  bsrc + boff + (size_t)oc * K2 + r * 64 + kp * 8);            \
        }                                                                      \
    }

    STAGE_LOAD2(0, 0);
    asm volatile("cp.async.commit_group;");
    STAGE_LOAD2(1, 1);
    asm volatile("cp.async.commit_group;");

    int sc = 0;
    for (int c = 0; c < NCHUNK2; c++) {
        if (c + 1 < NCHUNK2) asm volatile("cp.async.wait_group 1;");
        else                 asm volatile("cp.async.wait_group 0;");
        __syncthreads();
        if (c + 2 < NCHUNK2) {
            int sn = sc + 2; if (sn >= 3) sn -= 3;
            STAGE_LOAD2(c + 2, sn);
            asm volatile("cp.async.commit_group;");
        }

        const uint32_t abuf = abase + sc * STAGE2_BYTES;
        const uint32_t aB = abuf + aRow * 128;
        const uint32_t bB = abuf + 8192 + bRow * 128;

#pragma unroll
        for (int ks = 0; ks < 4; ks++) {
            uint32_t a[4][4];
#pragma unroll
            for (int mi = 0; mi < 4; mi++) {
                uint32_t ad = aB + mi * 2048 + (((2 * ks + kA) ^ sA) << 4);
                asm volatile(
                    "ldmatrix.sync.aligned.m8n8.x4.shared.b16 {%0,%1,%2,%3}, [%4];"
                    : "=r"(a[mi][0]), "=r"(a[mi][1]), "=r"(a[mi][2]), "=r"(a[mi][3])
                    : "r"(ad));
            }
            uint32_t bg[4][2];
#pragma unroll
            for (int p = 0; p < 2; p++) {
                uint32_t bd = bB + p * 2048 + (((2 * ks + kB) ^ sB) << 4);
                asm volatile(
                    "ldmatrix.sync.aligned.m8n8.x4.shared.b16 {%0,%1,%2,%3}, [%4];"
                    : "=r"(bg[2 * p][0]), "=r"(bg[2 * p][1]),
                      "=r"(bg[2 * p + 1][0]), "=r"(bg[2 * p + 1][1])
                    : "r"(bd));
            }
#pragma unroll
            for (int mi = 0; mi < 4; mi++)
#pragma unroll
                for (int ni = 0; ni < 4; ni++)
                    asm volatile(
                        "mma.sync.aligned.m16n8k16.row.col.f32.bf16.bf16.f32 "
                        "{%0,%1,%2,%3}, {%4,%5,%6,%7}, {%8,%9}, {%0,%1,%2,%3};"
                        : "+f"(acc[mi][ni][0]), "+f"(acc[mi][ni][1]),
                          "+f"(acc[mi][ni][2]), "+f"(acc[mi][ni][3])
                        : "r"(a[mi][0]), "r"(a[mi][1]), "r"(a[mi][2]), "r"(a[mi][3]),
                          "r"(bg[ni][0]), "r"(bg[ni][1]));
        }
        __syncthreads();
        if (++sc == 3) sc = 0;
    }
#undef STAGE_LOAD2

    // fused maxpool epilogue
#pragma unroll
    for (int ni = 0; ni < 4; ni++) {
        float me = -3.4e38f, mo = -3.4e38f;
#pragma unroll
        for (int mi = 0; mi < 4; mi++) {
            me = fmaxf(me, fmaxf(acc[mi][ni][0], acc[mi][ni][2]));
            mo = fmaxf(mo, fmaxf(acc[mi][ni][1], acc[mi][ni][3]));
        }
#pragma unroll
        for (int off = 4; off < 32; off <<= 1) {
            me = fmaxf(me, __shfl_xor_sync(0xffffffffu, me, off));
            mo = fmaxf(mo, __shfl_xor_sync(0xffffffffu, mo, off));
        }
        if (lane < 4) {
            int oc = nq * 128 + wn * 32 + ni * 8 + 2 * lane;
            g_feat[oc * TT + t]       = me + bias[oc];
            g_feat[(oc + 1) * TT + t] = mo + bias[oc + 1];
        }
    }
}

// ============================================================================
// Head (unchanged, passing since R1)
// ============================================================================
__device__ __forceinline__ float iou1d(float s1, float e1, float s2, float e2) {
    float inter = fmaxf(fminf(e1, e2) - fmaxf(s1, s2), 0.f);
    float uni   = (e1 - s1) + (e2 - s2) - inter;
    return inter / fmaxf(uni, 1e-6f);
}

__global__ void __launch_bounds__(512, 1)
head_kernel(const float* __restrict__ sw, const float* __restrict__ sb,
            const float* __restrict__ dw, const float* __restrict__ db,
            const float* __restrict__ gt, const int* __restrict__ vlen,
            float* __restrict__ out) {
    __shared__ float s_sl[16 * 64], s_dl[16 * 64];
    __shared__ float s_bs[NANCH], s_be[NANCH], s_sc[NANCH];
    __shared__ float s_as[NANCH], s_ae[NANCH];
    __shared__ float s_lp0[NANCH], s_lp1[NANCH], s_dc[NANCH], s_dt[NANCH];
    __shared__ float s_gt[16];
    __shared__ int   s_best[8];
    __shared__ float r0[512], r1[512], r2[512], r3[512];

    const int tid  = threadIdx.x;
    const int wid  = tid >> 5;
    const int lane = tid & 31;
    if (tid < 16) s_gt[tid] = gt[tid];

    const int o = tid >> 6;
    const int t = tid & 63;
    {
        float a0 = sb[o], a1 = sb[o + 8], d0 = db[o], d1 = db[o + 8];
        for (int c = 0; c < C2; c++) {
            float f = g_feat[c * 64 + t];
            a0 = fmaf(sw[o * 512 + c],       f, a0);
            a1 = fmaf(sw[(o + 8) * 512 + c], f, a1);
            d0 = fmaf(dw[o * 512 + c],       f, d0);
            d1 = fmaf(dw[(o + 8) * 512 + c], f, d1);
        }
        s_sl[o * 64 + t] = a0;  s_sl[(o + 8) * 64 + t] = a1;
        s_dl[o * 64 + t] = d0;  s_dl[(o + 8) * 64 + t] = d1;
    }
    __syncthreads();

    {
        const int a = o;
        float l0 = s_sl[a * 64 + t], l1 = s_sl[(a + 8) * 64 + t];
        float mx = fmaxf(l0, l1);
        float lse = mx + logf(expf(l0 - mx) + expf(l1 - mx));
        float p1  = expf(l1 - lse);
        float dc  = s_dl[a * 64 + t], dl = s_dl[(a + 8) * 64 + t];
        float alen = (float)(8 << a);
        float ctr  = (t + 0.5f) * 8.f;
        float pc = ctr + dc * alen;
        float pl = alen * expf(fminf(fmaxf(dl, -10.f), 10.f));
        float ps = fminf(fmaxf(pc - 0.5f * pl, 0.f), 512.f);
        float pe = fminf(fmaxf(pc + 0.5f * pl, 0.f), 512.f);
        s_bs[tid] = ps;  s_be[tid] = pe;
        s_sc[tid] = (pe - ps >= 4.f) ? p1 : -1.0e9f;
        s_as[tid] = ctr - 0.5f * alen;
        s_ae[tid] = ctr + 0.5f * alen;
        s_lp0[tid] = l0 - lse;  s_lp1[tid] = l1 - lse;
        s_dc[tid] = dc;  s_dt[tid] = dl;
    }
    __syncthreads();

    if (wid < 8) {
        float gs = s_gt[wid * 2], ge = s_gt[wid * 2 + 1];
        float bv = -3.4e38f; int bi = 0x7fffffff;
        for (int k = 0; k < 16; k++) {
            int n = lane + 32 * k;
            float v = iou1d(s_as[n], s_ae[n], gs, ge);
            if (v > bv) { bv = v; bi = n; }
        }
        for (int off = 16; off; off >>= 1) {
            float ov = __shfl_xor_sync(0xffffffffu, bv, off);
            int   oi = __shfl_xor_sync(0xffffffffu, bi, off);
            if (ov > bv || (ov == bv && oi < bi)) { bv = ov; bi = oi; }
        }
        if (lane == 0) s_best[wid] = bi;
    }
    __syncthreads();

    {
        float myas = s_as[tid], myae = s_ae[tid];
        float miou = -1.f; int ag = 0;
#pragma unroll
        for (int g = 0; g < 8; g++) {
            float v = iou1d(myas, myae, s_gt[2 * g], s_gt[2 * g + 1]);
            if (v > miou) { miou = v; ag = g; }
        }
        int lab = (miou < 0.3f) ? 0 : -1;
        if (miou >= 0.7f) lab = 1;
#pragma unroll
        for (int g = 0; g < 8; g++)
            if (s_best[g] == tid) lab = 1;
        float vl = (float)vlen[0];
        if (!(myas >= 0.f && myae <= vl)) lab = -1;

        float gs = s_gt[2 * ag], ge = s_gt[2 * ag + 1];
        float gc = 0.5f * (gs + ge);
        float gl = fmaxf(ge - gs, 1e-6f);
        float ac = 0.5f * (myas + myae);
        float al = myae - myas;
        float rl0 = (gc - ac) / al;
        float rl1 = logf(gl / al);
        float d0 = s_dc[tid] - rl0, d1 = s_dt[tid] - rl1;
        float sl1 = (fabsf(d0) < 1.f ? 0.5f * d0 * d0 : fabsf(d0) - 0.5f)
                  + (fabsf(d1) < 1.f ? 0.5f * d1 * d1 : fabsf(d1) - 0.5f);
        float maskv = (lab >= 0) ? 1.f : 0.f;
        float posv  = (lab == 1) ? 1.f : 0.f;
        float nll   = -((lab == 1) ? s_lp1[tid] : s_lp0[tid]);
        r0[tid] = nll * maskv;  r1[tid] = maskv;
        r2[tid] = sl1 * posv;   r3[tid] = posv;
    }
    __syncthreads();
    for (int s = 256; s > 0; s >>= 1) {
        if (tid < s) {
            r0[tid] += r0[tid + s];  r1[tid] += r1[tid + s];
            r2[tid] += r2[tid + s];  r3[tid] += r3[tid + s];
        }
        __syncthreads();
    }
    if (tid == 0) {
        out[300] = r0[0] / fmaxf(r1[0], 1.f);
        out[301] = r2[0] / fmaxf(r3[0], 1.f);
    }
    __syncthreads();

    if (wid == 0) {
        for (int it = 0; it < 100; it++) {
            float bv = -3.4e38f; int bi = 0x7fffffff;
#pragma unroll
            for (int k = 0; k < 16; k++) {
                int n = lane + 32 * k;
                float v = s_sc[n];
                if (v > bv) { bv = v; bi = n; }
            }
            for (int off = 16; off; off >>= 1) {
                float ov = __shfl_xor_sync(0xffffffffu, bv, off);
                int   oi = __shfl_xor_sync(0xffffffffu, bi, off);
                if (ov > bv || (ov == bv && oi < bi)) { bv = ov; bi = oi; }
            }
            float kb0 = s_bs[bi], kb1 = s_be[bi];
            bool keep = bv > -5.0e8f;
            if (lane == 0) {
                out[2 * it]     = keep ? kb0 : 0.f;
                out[2 * it + 1] = keep ? kb1 : 0.f;
                out[200 + it]   = keep ? bv  : 0.f;
            }
#pragma unroll
            for (int k = 0; k < 16; k++) {
                int n = lane + 32 * k;
                float v = iou1d(kb0, kb1, s_bs[n], s_be[n]);
                if (v > 0.7f || n == bi) s_sc[n] = -1.0e9f;
            }
            __syncwarp();
        }
    }
}

// ============================================================================
extern "C" void kernel_launch(void* const* d_in, const int* in_sizes, int n_in,
                              void* d_out, int out_size) {
    const float* base = (const float*)d_in[0];
    const float* gt   = (const float*)d_in[1];
    const int*   vl   = (const int*)d_in[2];
    const float* c1w  = (const float*)d_in[3];
    const float* c1b  = (const float*)d_in[4];
    const float* c2w  = (const float*)d_in[5];
    const float* c2b  = (const float*)d_in[6];
    const float* sw   = (const float*)d_in[7];
    const float* sb   = (const float*)d_in[8];
    const float* dw   = (const float*)d_in[9];
    const float* db   = (const float*)d_in[10];
    float* out = (float*)d_out;

    static int attr_set = 0;
    if (!attr_set) {
        cudaFuncSetAttribute(conv1_mma,
                             cudaFuncAttributeMaxDynamicSharedMemorySize, C1MMA_SMEM);
        cudaFuncSetAttribute(conv2_mma,
                             cudaFuncAttributeMaxDynamicSharedMemorySize, C2MMA_SMEM);
        attr_set = 1;
    }

    void *p1h, *p1l, *p2h, *p2l;
    cudaGetSymbolAddress(&p1h, g_p1h);
    cudaGetSymbolAddress(&p1l, g_p1l);
    cudaGetSymbolAddress(&p2h, g_p2h);
    cudaGetSymbolAddress(&p2l, g_p2l);

    memzero<<<1024, 256>>>((uint4*)p1h, P1_ELEMS * 2 / 16);
    memzero<<<1024, 256>>>((uint4*)p1l, P1_ELEMS * 2 / 16);
    memzero<<<1024, 256>>>((uint4*)p2h, P2_ELEMS * 2 / 16);
    memzero<<<1024, 256>>>((uint4*)p2l, P2_ELEMS * 2 / 16);
    split_w1<<<512, 256>>>(c1w);
    split_w2<<<512, 256>>>(c2w);
    pad_split1<<<dim3(64, 32), 256>>>(base);
    conv1_mma<<<dim3(64, 4, 2), 128, C1MMA_SMEM>>>(c1b);
    conv2_mma<<<dim3(64, 4), 128, C2MMA_SMEM>>>(c2b);
    head_kernel<<<1, 512>>>(sw, sb, dw, db, gt, vl, out);
}